// round 4
// baseline (speedup 1.0000x reference)
#include <cuda_runtime.h>
#include <cuda_fp16.h>
#include <math.h>
#include <stddef.h>

#define BB 1024
#define SS 256
#define DD 300
#define HH 150
#define G4 600     // 4*H
#define N2 1200    // both directions

// ---------------- scratch (device globals; total ~1.27 GB, under 2GB code-model cap)
__device__ float  g_bufA [(size_t)BB * SS * DD];   // xe (layer0 in) -> reused as h2 (layer1 out)
__device__ float  g_bufB [(size_t)BB * SS * DD];   // h1 (layer0 out / layer1 in)
__device__ __half g_gates[(size_t)BB * SS * N2];   // precomputed input gates (fp16)
__device__ float  g_wcat0[N2 * DD];                // packed Wih layer0 [1200][300]
__device__ float  g_wcat1[N2 * DD];
__device__ float  g_whht0[2 * HH * G4];            // [dir][k][n] transposed Whh layer0
__device__ float  g_whht1[2 * HH * G4];
__device__ float  g_w1t  [DD * DD];
__device__ float  g_w2t  [DD * DD];
__device__ float  g_tmp  [BB * DD];
__device__ int    g_len  [BB];

// ---------------- lengths from mask (robust to int32 or int64 mask) -----------
__global__ void k_len32(const int* __restrict__ mask) {
    int b = blockIdx.x * blockDim.x + threadIdx.x;
    if (b < BB) {
        const int* m = mask + (size_t)b * SS;
        int c = 0;
        for (int t = 0; t < SS; ++t) c += (m[t] != 0);
        g_len[b] = c;
    }
}
__global__ void k_len64(const int* __restrict__ mask) {
    int b = blockIdx.x * blockDim.x + threadIdx.x;
    if (b < BB) {
        const int* m = mask + (size_t)b * SS * 2;   // int64 little-endian pairs
        int c = 0;
        for (int t = 0; t < SS; ++t) c += ((m[2 * t] | m[2 * t + 1]) != 0);
        g_len[b] = c;
    }
}

// ---------------- weight packing / transposes ----------------------------------
__global__ void k_pack_wcat0(const float* __restrict__ Wf, const float* __restrict__ Wb) {
    int idx = blockIdx.x * blockDim.x + threadIdx.x;
    if (idx < N2 * DD) {
        int n = idx / DD, k = idx - n * DD;
        g_wcat0[idx] = (n < G4) ? Wf[n * DD + k] : Wb[(n - G4) * DD + k];
    }
}
__global__ void k_pack_wcat1(const float* __restrict__ Wf, const float* __restrict__ Wb) {
    int idx = blockIdx.x * blockDim.x + threadIdx.x;
    if (idx < N2 * DD) {
        int n = idx / DD, k = idx - n * DD;
        g_wcat1[idx] = (n < G4) ? Wf[n * DD + k] : Wb[(n - G4) * DD + k];
    }
}
__global__ void k_tr_whh0(const float* __restrict__ Wf, const float* __restrict__ Wb) {
    int idx = blockIdx.x * blockDim.x + threadIdx.x;
    if (idx < G4 * HH) {
        int r = idx / HH, c = idx - r * HH;
        g_whht0[c * G4 + r]           = Wf[idx];
        g_whht0[HH * G4 + c * G4 + r] = Wb[idx];
    }
}
__global__ void k_tr_whh1(const float* __restrict__ Wf, const float* __restrict__ Wb) {
    int idx = blockIdx.x * blockDim.x + threadIdx.x;
    if (idx < G4 * HH) {
        int r = idx / HH, c = idx - r * HH;
        g_whht1[c * G4 + r]           = Wf[idx];
        g_whht1[HH * G4 + c * G4 + r] = Wb[idx];
    }
}
__global__ void k_tr_fc(const float* __restrict__ W1, const float* __restrict__ W2) {
    int idx = blockIdx.x * blockDim.x + threadIdx.x;
    if (idx < DD * DD) {
        int r = idx / DD, c = idx - r * DD;
        g_w1t[c * DD + r] = W1[idx];
        g_w2t[c * DD + r] = W2[idx];
    }
}

// ---------------- embedding gather (float4) ------------------------------------
__global__ void k_embed(const int* __restrict__ x, const float* __restrict__ emb) {
    int idx = blockIdx.x * blockDim.x + threadIdx.x;   // B*S*75 float4s
    int bt = idx / 75;
    int r  = idx - bt * 75;
    int tok = x[bt];
    float4 v = make_float4(0.f, 0.f, 0.f, 0.f);
    if (tok != 0) v = reinterpret_cast<const float4*>(emb)[(size_t)tok * 75 + r];
    reinterpret_cast<float4*>(g_bufA)[idx] = v;
}

// ---------------- big input GEMM: C[M,N](fp16) = A[M,K] * Bw[N,K]^T -------------
// BM=128, BN=64, BK=8, TM=8, TN=4, 256 threads
__device__ __forceinline__ void gemm_body(const float* __restrict__ A,
                                          const float* __restrict__ Bw,
                                          __half* __restrict__ C,
                                          int M, int K, int N) {
    __shared__ float As[8 * 128];
    __shared__ float Bs[8 * 64];
    int tid = threadIdx.x;
    int m0 = blockIdx.x * 128, n0 = blockIdx.y * 64;
    int tx = tid & 15, ty = tid >> 4;

    float acc[8][4];
#pragma unroll
    for (int i = 0; i < 8; ++i)
#pragma unroll
        for (int j = 0; j < 4; ++j) acc[i][j] = 0.f;

    int arow = tid >> 1, ak = (tid & 1) * 4;
    int brow = tid >> 1, bk = (tid & 1) * 4;
    int KT = (K + 7) / 8;

    for (int kt = 0; kt < KT; ++kt) {
        int k0 = kt * 8;
        float4 av = make_float4(0.f, 0.f, 0.f, 0.f);
        if (k0 + ak < K)  // K % 4 == 0 => whole float4 valid when base in range
            av = *reinterpret_cast<const float4*>(A + (size_t)(m0 + arow) * K + k0 + ak);
        As[(ak + 0) * 128 + arow] = av.x;
        As[(ak + 1) * 128 + arow] = av.y;
        As[(ak + 2) * 128 + arow] = av.z;
        As[(ak + 3) * 128 + arow] = av.w;
        if (tid < 128) {
            float4 bv = make_float4(0.f, 0.f, 0.f, 0.f);
            if ((n0 + brow < N) && (k0 + bk < K))
                bv = *reinterpret_cast<const float4*>(Bw + (size_t)(n0 + brow) * K + k0 + bk);
            Bs[(bk + 0) * 64 + brow] = bv.x;
            Bs[(bk + 1) * 64 + brow] = bv.y;
            Bs[(bk + 2) * 64 + brow] = bv.z;
            Bs[(bk + 3) * 64 + brow] = bv.w;
        }
        __syncthreads();
#pragma unroll
        for (int kk = 0; kk < 8; ++kk) {
            float a[8], bq[4];
            *reinterpret_cast<float4*>(&a[0]) = *reinterpret_cast<const float4*>(&As[kk * 128 + ty * 8]);
            *reinterpret_cast<float4*>(&a[4]) = *reinterpret_cast<const float4*>(&As[kk * 128 + ty * 8 + 4]);
            *reinterpret_cast<float4*>(&bq[0]) = *reinterpret_cast<const float4*>(&Bs[kk * 64 + tx * 4]);
#pragma unroll
            for (int i = 0; i < 8; ++i)
#pragma unroll
                for (int j = 0; j < 4; ++j) acc[i][j] += a[i] * bq[j];
        }
        __syncthreads();
    }
#pragma unroll
    for (int i = 0; i < 8; ++i) {
        int m = m0 + ty * 8 + i;
        int n = n0 + tx * 4;
        if (n < N) {
            __half2* cp = reinterpret_cast<__half2*>(C + (size_t)m * N + n);
            cp[0] = __floats2half2_rn(acc[i][0], acc[i][1]);
            cp[1] = __floats2half2_rn(acc[i][2], acc[i][3]);
        }
    }
}

__global__ void __launch_bounds__(256) k_gemm_l0() {
    gemm_body(g_bufA, g_wcat0, g_gates, BB * SS, DD, N2);
}
__global__ void __launch_bounds__(256) k_gemm_l1() {
    gemm_body(g_bufB, g_wcat1, g_gates, BB * SS, DD, N2);
}

// ---------------- persistent recurrent LSTM kernel ------------------------------
// grid = 256 blocks: dir = blockIdx.x & 1, batch group = blockIdx.x >> 1 (8 rows)
__device__ __forceinline__ float sigm(float x) { return 1.f / (1.f + expf(-x)); }

__device__ __forceinline__ void lstm_body(const __half* __restrict__ Gt,
                                          const float* __restrict__ WhhT,
                                          const float* __restrict__ bias_f,
                                          const float* __restrict__ bias_b,
                                          float* __restrict__ Hout) {
    __shared__ float h_s[HH * 8];     // [j][r]
    __shared__ float g_s[G4 * 9];     // gate staging [n][r], stride 9 (bank-safe)

    int tid = threadIdx.x;
    int dir = blockIdx.x & 1;
    int b0  = (blockIdx.x >> 1) * 8;
    const float* Wd   = WhhT + dir * (HH * G4);
    const float* bias = dir ? bias_b : bias_f;

    float bn = 0.f;
    if (tid < G4) bn = bias[tid];

    int Lr0 = g_len[b0 + 0], Lr1 = g_len[b0 + 1], Lr2 = g_len[b0 + 2], Lr3 = g_len[b0 + 3];
    int Lr4 = g_len[b0 + 4], Lr5 = g_len[b0 + 5], Lr6 = g_len[b0 + 6], Lr7 = g_len[b0 + 7];

    for (int i = tid; i < HH * 8; i += blockDim.x) h_s[i] = 0.f;

    int r0 = tid / HH;            // 0..3 for tid<600
    int j0 = tid - r0 * HH;
    int Le0 = 0, Le1 = 0;
    if (tid < G4) {
        Le0 = g_len[b0 + r0];
        Le1 = g_len[b0 + r0 + 4];
    }
    float c0 = 0.f, c1 = 0.f;
    __syncthreads();

    for (int s = 0; s < SS; ++s) {
        if (tid < G4) {
            float acc0 = 0.f, acc1 = 0.f, acc2 = 0.f, acc3 = 0.f;
            float acc4 = 0.f, acc5 = 0.f, acc6 = 0.f, acc7 = 0.f;
#pragma unroll 5
            for (int k = 0; k < HH; ++k) {
                float w = Wd[k * G4 + tid];
                float4 ha = *reinterpret_cast<const float4*>(&h_s[k * 8]);
                float4 hb = *reinterpret_cast<const float4*>(&h_s[k * 8 + 4]);
                acc0 += w * ha.x; acc1 += w * ha.y; acc2 += w * ha.z; acc3 += w * ha.w;
                acc4 += w * hb.x; acc5 += w * hb.y; acc6 += w * hb.z; acc7 += w * hb.w;
            }
            float accs[8] = {acc0, acc1, acc2, acc3, acc4, acc5, acc6, acc7};
            int   Ls[8]   = {Lr0, Lr1, Lr2, Lr3, Lr4, Lr5, Lr6, Lr7};
#pragma unroll
            for (int r = 0; r < 8; ++r) {
                int L = Ls[r];
                int t = (s < L) ? (dir ? (L - 1 - s) : s) : s;
                float gin = __half2float(Gt[((size_t)(b0 + r) * SS + t) * N2 + dir * G4 + tid]);
                g_s[tid * 9 + r] = accs[r] + gin + bn;
            }
        }
        __syncthreads();
        if (tid < G4) {
            {   // pair 0: row r0
                int rr = r0;
                float gi = g_s[(0 * HH + j0) * 9 + rr];
                float gf = g_s[(1 * HH + j0) * 9 + rr];
                float gg = g_s[(2 * HH + j0) * 9 + rr];
                float go = g_s[(3 * HH + j0) * 9 + rr];
                float iv = sigm(gi), fv = sigm(gf), gv = tanhf(gg), ov = sigm(go);
                float cn = fv * c0 + iv * gv;
                float hn = ov * tanhf(cn);
                int L = Le0;
                bool valid = (s < L);
                int t = valid ? (dir ? (L - 1 - s) : s) : s;
                float hw = valid ? hn : 0.f;
                if (valid) { c0 = cn; h_s[j0 * 8 + rr] = hn; }
                Hout[((size_t)(b0 + rr) * SS + t) * DD + dir * HH + j0] = hw;
            }
            {   // pair 1: row r0+4
                int rr = r0 + 4;
                float gi = g_s[(0 * HH + j0) * 9 + rr];
                float gf = g_s[(1 * HH + j0) * 9 + rr];
                float gg = g_s[(2 * HH + j0) * 9 + rr];
                float go = g_s[(3 * HH + j0) * 9 + rr];
                float iv = sigm(gi), fv = sigm(gf), gv = tanhf(gg), ov = sigm(go);
                float cn = fv * c1 + iv * gv;
                float hn = ov * tanhf(cn);
                int L = Le1;
                bool valid = (s < L);
                int t = valid ? (dir ? (L - 1 - s) : s) : s;
                float hw = valid ? hn : 0.f;
                if (valid) { c1 = cn; h_s[j0 * 8 + rr] = hn; }
                Hout[((size_t)(b0 + rr) * SS + t) * DD + dir * HH + j0] = hw;
            }
        }
        __syncthreads();
    }
}

__global__ void __launch_bounds__(640) k_lstm_l0(const float* __restrict__ bf,
                                                 const float* __restrict__ bb) {
    lstm_body(g_gates, g_whht0, bf, bb, g_bufB);
}
__global__ void __launch_bounds__(640) k_lstm_l1(const float* __restrict__ bf,
                                                 const float* __restrict__ bb) {
    lstm_body(g_gates, g_whht1, bf, bb, g_bufA);
}

// ---------------- final FC layers ----------------------------------------------
__global__ void __launch_bounds__(320) k_fc1(const float* __restrict__ bias) {
    __shared__ float v[DD];
    int b = blockIdx.x, tid = threadIdx.x;
    int L = g_len[b];
    const float* src = g_bufA + ((size_t)b * SS + (L - 1)) * DD;
    if (tid < DD) v[tid] = src[tid];
    __syncthreads();
    if (tid < DD) {
        float acc = bias[tid];
        for (int k = 0; k < DD; ++k) acc += v[k] * g_w1t[k * DD + tid];
        g_tmp[b * DD + tid] = tanhf(acc);
    }
}

__global__ void __launch_bounds__(320) k_fc2(const float* __restrict__ bias,
                                             float* __restrict__ out) {
    __shared__ float v[DD];
    int b = blockIdx.x, tid = threadIdx.x;
    if (tid < DD) v[tid] = g_tmp[b * DD + tid];
    __syncthreads();
    if (tid < DD) {
        float acc = bias[tid];
        for (int k = 0; k < DD; ++k) acc += v[k] * g_w2t[k * DD + tid];
        out[b * DD + tid] = acc;
    }
}

// ---------------- host -----------------------------------------------------------
extern "C" void kernel_launch(void* const* d_in, const int* in_sizes, int n_in,
                              void* d_out, int out_size) {
    const int*   x        = (const int*)  d_in[0];
    const int*   mask     = (const int*)  d_in[1];
    const float* emb      = (const float*)d_in[2];
    const float* Wih_l0f  = (const float*)d_in[3];
    const float* Whh_l0f  = (const float*)d_in[4];
    const float* b_l0f    = (const float*)d_in[5];
    const float* Wih_l0b  = (const float*)d_in[6];
    const float* Whh_l0b  = (const float*)d_in[7];
    const float* b_l0b    = (const float*)d_in[8];
    const float* Wih_l1f  = (const float*)d_in[9];
    const float* Whh_l1f  = (const float*)d_in[10];
    const float* b_l1f    = (const float*)d_in[11];
    const float* Wih_l1b  = (const float*)d_in[12];
    const float* Whh_l1b  = (const float*)d_in[13];
    const float* b_l1b    = (const float*)d_in[14];
    const float* W1       = (const float*)d_in[15];
    const float* b1       = (const float*)d_in[16];
    const float* W2       = (const float*)d_in[17];
    const float* b2       = (const float*)d_in[18];
    float* out = (float*)d_out;

    // lengths (mask may be int32 or int64 depending on harness dtype mapping)
    if (in_sizes[1] == BB * SS) k_len32<<<4, 256>>>(mask);
    else                        k_len64<<<4, 256>>>(mask);

    // weight packing / transposes
    int nWcat = (N2 * DD + 255) / 256;
    k_pack_wcat0<<<nWcat, 256>>>(Wih_l0f, Wih_l0b);
    k_pack_wcat1<<<nWcat, 256>>>(Wih_l1f, Wih_l1b);
    int nWhh = (G4 * HH + 255) / 256;
    k_tr_whh0<<<nWhh, 256>>>(Whh_l0f, Whh_l0b);
    k_tr_whh1<<<nWhh, 256>>>(Whh_l1f, Whh_l1b);
    int nW = (DD * DD + 255) / 256;
    k_tr_fc<<<nW, 256>>>(W1, W2);

    // embedding -> bufA
    k_embed<<<(BB * SS * 75) / 256, 256>>>(x, emb);

    dim3 ggrid((BB * SS) / 128, (N2 + 63) / 64);

    // layer 0: bufA -> gates -> bufB
    k_gemm_l0<<<ggrid, 256>>>();
    k_lstm_l0<<<256, 640>>>(b_l0f, b_l0b);

    // layer 1: bufB -> gates -> bufA
    k_gemm_l1<<<ggrid, 256>>>();
    k_lstm_l1<<<256, 640>>>(b_l1f, b_l1b);

    // head
    k_fc1<<<BB, 320>>>(b1);
    k_fc2<<<BB, 320>>>(b2, out);
}

// round 5
// speedup vs baseline: 1.4363x; 1.4363x over previous
#include <cuda_runtime.h>
#include <cuda_fp16.h>
#include <math.h>
#include <stddef.h>

#define BB 1024
#define SS 256
#define DD 300
#define HH 150
#define G4 600     // 4*H
#define N2 1200    // both directions
#define KP 304     // K padded to multiple of 16
#define KT16 (KP / 16)   // 19 k-steps

// ---------------- scratch (device globals; total ~1.1 GB) ----------------------
__device__ __half g_a16  [(size_t)BB * SS * KP];   // fp16 GEMM A: xe (L0), then h1 (L1)
__device__ float  g_h2   [(size_t)BB * SS * DD];   // layer1 output (fp32, for head)
__device__ __half g_gates[(size_t)BB * SS * N2];   // input-projection gates (fp16)
__device__ __half g_w16_0[N2 * KP];                // packed fp16 Wih layer0 (padded)
__device__ __half g_w16_1[N2 * KP];
__device__ float  g_whht0[2 * HH * G4];            // [dir][k][n] transposed Whh
__device__ float  g_whht1[2 * HH * G4];
__device__ float  g_w1t  [DD * DD];
__device__ float  g_w2t  [DD * DD];
__device__ float  g_tmp  [BB * DD];
__device__ int    g_len  [BB];

// ---------------- lengths from mask --------------------------------------------
__global__ void k_len32(const int* __restrict__ mask) {
    int b = blockIdx.x * blockDim.x + threadIdx.x;
    if (b < BB) {
        const int* m = mask + (size_t)b * SS;
        int c = 0;
        for (int t = 0; t < SS; ++t) c += (m[t] != 0);
        g_len[b] = c;
    }
}
__global__ void k_len64(const int* __restrict__ mask) {
    int b = blockIdx.x * blockDim.x + threadIdx.x;
    if (b < BB) {
        const int* m = mask + (size_t)b * SS * 2;
        int c = 0;
        for (int t = 0; t < SS; ++t) c += ((m[2 * t] | m[2 * t + 1]) != 0);
        g_len[b] = c;
    }
}

// ---------------- weight packing ------------------------------------------------
__global__ void k_pack_w16_0(const float* __restrict__ Wf, const float* __restrict__ Wb) {
    int idx = blockIdx.x * blockDim.x + threadIdx.x;
    if (idx < N2 * KP) {
        int n = idx / KP, k = idx - n * KP;
        float v = 0.f;
        if (k < DD) v = (n < G4) ? Wf[n * DD + k] : Wb[(n - G4) * DD + k];
        g_w16_0[idx] = __float2half(v);
    }
}
__global__ void k_pack_w16_1(const float* __restrict__ Wf, const float* __restrict__ Wb) {
    int idx = blockIdx.x * blockDim.x + threadIdx.x;
    if (idx < N2 * KP) {
        int n = idx / KP, k = idx - n * KP;
        float v = 0.f;
        if (k < DD) v = (n < G4) ? Wf[n * DD + k] : Wb[(n - G4) * DD + k];
        g_w16_1[idx] = __float2half(v);
    }
}
__global__ void k_tr_whh0(const float* __restrict__ Wf, const float* __restrict__ Wb) {
    int idx = blockIdx.x * blockDim.x + threadIdx.x;
    if (idx < G4 * HH) {
        int r = idx / HH, c = idx - r * HH;
        g_whht0[c * G4 + r]           = Wf[idx];
        g_whht0[HH * G4 + c * G4 + r] = Wb[idx];
    }
}
__global__ void k_tr_whh1(const float* __restrict__ Wf, const float* __restrict__ Wb) {
    int idx = blockIdx.x * blockDim.x + threadIdx.x;
    if (idx < G4 * HH) {
        int r = idx / HH, c = idx - r * HH;
        g_whht1[c * G4 + r]           = Wf[idx];
        g_whht1[HH * G4 + c * G4 + r] = Wb[idx];
    }
}
__global__ void k_tr_fc(const float* __restrict__ W1, const float* __restrict__ W2) {
    int idx = blockIdx.x * blockDim.x + threadIdx.x;
    if (idx < DD * DD) {
        int r = idx / DD, c = idx - r * DD;
        g_w1t[c * DD + r] = W1[idx];
        g_w2t[c * DD + r] = W2[idx];
    }
}

// ---------------- embedding gather -> fp16 A (zeroes K pad) ---------------------
// one thread per half2: M * (KP/2) = M * 152 units
__global__ void k_embed16(const int* __restrict__ x, const float* __restrict__ emb) {
    int idx = blockIdx.x * blockDim.x + threadIdx.x;
    int bt = idx / 152;
    int c  = idx - bt * 152;          // half2 index within row
    int tok = x[bt];
    __half2 v = __floats2half2_rn(0.f, 0.f);
    if (c < 150 && tok != 0) {
        float2 f = reinterpret_cast<const float2*>(emb)[(size_t)tok * 150 + c];
        v = __floats2half2_rn(f.x, f.y);
    }
    reinterpret_cast<__half2*>(g_a16)[idx] = v;
}

// ---------------- HMMA GEMM: C[M,N](fp16) = A[M,KP](fp16) * Bw[N,KP]^T ----------
// CTA 128x64, 8 warps (4x2), each warp 32x32; mma m16n8k16 f32 accum.
__device__ __forceinline__ void gemm16_body(const __half* __restrict__ A,
                                            const __half* __restrict__ Bw,
                                            __half* __restrict__ C) {
    __shared__ __half As[128][24];   // row stride 48B (16B-aligned, conflict-safe)
    __shared__ __half Bs[64][24];

    const int N = N2;
    int tid  = threadIdx.x;
    int m0   = blockIdx.x * 128;
    int n0   = blockIdx.y * 64;
    int warp = tid >> 5, lane = tid & 31;
    int wm = warp & 3, wn = warp >> 2;       // warp tile: rows wm*32, cols wn*32
    int l4 = lane >> 2, c2 = (lane & 3) * 2;

    float acc[2][4][4];
#pragma unroll
    for (int i = 0; i < 2; ++i)
#pragma unroll
        for (int j = 0; j < 4; ++j)
#pragma unroll
            for (int q = 0; q < 4; ++q) acc[i][j][q] = 0.f;

    int arow = tid >> 1, achk = (tid & 1) * 8;   // 16B chunk (8 halves)
    int brow = tid >> 1, bchk = (tid & 1) * 8;
    bool bvalid = (tid < 128) && (n0 + brow < N);

    // stage k-tile 0
    {
        uint4 va = *reinterpret_cast<const uint4*>(A + (size_t)(m0 + arow) * KP + achk);
        *reinterpret_cast<uint4*>(&As[arow][achk]) = va;
        if (tid < 128) {
            uint4 vb = make_uint4(0, 0, 0, 0);
            if (bvalid) vb = *reinterpret_cast<const uint4*>(Bw + (size_t)(n0 + brow) * KP + bchk);
            *reinterpret_cast<uint4*>(&Bs[brow][bchk]) = vb;
        }
    }
    __syncthreads();

    for (int kt = 0; kt < KT16; ++kt) {
        uint4 va, vb;
        bool nxt = (kt + 1 < KT16);
        if (nxt) {
            int k0 = (kt + 1) * 16;
            va = *reinterpret_cast<const uint4*>(A + (size_t)(m0 + arow) * KP + k0 + achk);
            vb = make_uint4(0, 0, 0, 0);
            if (bvalid) vb = *reinterpret_cast<const uint4*>(Bw + (size_t)(n0 + brow) * KP + k0 + bchk);
        }

        // fragments
        unsigned af[2][4];
#pragma unroll
        for (int mi = 0; mi < 2; ++mi) {
            int rb = wm * 32 + mi * 16;
            af[mi][0] = *reinterpret_cast<const unsigned*>(&As[rb + l4][c2]);
            af[mi][1] = *reinterpret_cast<const unsigned*>(&As[rb + l4 + 8][c2]);
            af[mi][2] = *reinterpret_cast<const unsigned*>(&As[rb + l4][c2 + 8]);
            af[mi][3] = *reinterpret_cast<const unsigned*>(&As[rb + l4 + 8][c2 + 8]);
        }
        unsigned bf[4][2];
#pragma unroll
        for (int ni = 0; ni < 4; ++ni) {
            int nr = wn * 32 + ni * 8 + l4;
            bf[ni][0] = *reinterpret_cast<const unsigned*>(&Bs[nr][c2]);
            bf[ni][1] = *reinterpret_cast<const unsigned*>(&Bs[nr][c2 + 8]);
        }
#pragma unroll
        for (int mi = 0; mi < 2; ++mi)
#pragma unroll
            for (int ni = 0; ni < 4; ++ni) {
                asm volatile(
                    "mma.sync.aligned.m16n8k16.row.col.f32.f16.f16.f32 "
                    "{%0,%1,%2,%3},{%4,%5,%6,%7},{%8,%9},{%0,%1,%2,%3};"
                    : "+f"(acc[mi][ni][0]), "+f"(acc[mi][ni][1]),
                      "+f"(acc[mi][ni][2]), "+f"(acc[mi][ni][3])
                    : "r"(af[mi][0]), "r"(af[mi][1]), "r"(af[mi][2]), "r"(af[mi][3]),
                      "r"(bf[ni][0]), "r"(bf[ni][1]));
            }

        __syncthreads();
        if (nxt) {
            *reinterpret_cast<uint4*>(&As[arow][achk]) = va;
            if (tid < 128) *reinterpret_cast<uint4*>(&Bs[brow][bchk]) = vb;
        }
        __syncthreads();
    }

    // store fp16
#pragma unroll
    for (int mi = 0; mi < 2; ++mi)
#pragma unroll
        for (int ni = 0; ni < 4; ++ni) {
            int m = m0 + wm * 32 + mi * 16 + l4;
            int n = n0 + wn * 32 + ni * 8 + c2;
            if (n < N) {
                __half2 h01 = __floats2half2_rn(acc[mi][ni][0], acc[mi][ni][1]);
                __half2 h23 = __floats2half2_rn(acc[mi][ni][2], acc[mi][ni][3]);
                *reinterpret_cast<__half2*>(C + (size_t)m * N + n)       = h01;
                *reinterpret_cast<__half2*>(C + (size_t)(m + 8) * N + n) = h23;
            }
        }
}

__global__ void __launch_bounds__(256) k_gemm16_l0() { gemm16_body(g_a16, g_w16_0, g_gates); }
__global__ void __launch_bounds__(256) k_gemm16_l1() { gemm16_body(g_a16, g_w16_1, g_gates); }

// ---------------- persistent recurrent LSTM kernel ------------------------------
__device__ __forceinline__ float sigm(float x) { return 1.f / (1.f + expf(-x)); }
__device__ __forceinline__ void store_h(float*  p, float v) { *p = v; }
__device__ __forceinline__ void store_h(__half* p, float v) { *p = __float2half(v); }

template <typename OutT>
__device__ __forceinline__ void lstm_body(const __half* __restrict__ Gt,
                                          const float* __restrict__ WhhT,
                                          const float* __restrict__ bias_f,
                                          const float* __restrict__ bias_b,
                                          OutT* __restrict__ Hout, int ostride) {
    __shared__ float h_s[HH * 8];     // [j][r]
    __shared__ float g_s[G4 * 9];     // gate staging [n][r], stride 9

    int tid = threadIdx.x;
    int dir = blockIdx.x & 1;
    int b0  = (blockIdx.x >> 1) * 8;
    const float* Wd   = WhhT + dir * (HH * G4);
    const float* bias = dir ? bias_b : bias_f;

    float bn = 0.f;
    if (tid < G4) bn = bias[tid];

    int Lr0 = g_len[b0 + 0], Lr1 = g_len[b0 + 1], Lr2 = g_len[b0 + 2], Lr3 = g_len[b0 + 3];
    int Lr4 = g_len[b0 + 4], Lr5 = g_len[b0 + 5], Lr6 = g_len[b0 + 6], Lr7 = g_len[b0 + 7];

    for (int i = tid; i < HH * 8; i += blockDim.x) h_s[i] = 0.f;

    int r0 = tid / HH;            // 0..3 for tid<600
    int j0 = tid - r0 * HH;
    int Le0 = 0, Le1 = 0;
    if (tid < G4) {
        Le0 = g_len[b0 + r0];
        Le1 = g_len[b0 + r0 + 4];
    }
    float c0 = 0.f, c1 = 0.f;
    __syncthreads();

    for (int s = 0; s < SS; ++s) {
        if (tid < G4) {
            float acc0 = 0.f, acc1 = 0.f, acc2 = 0.f, acc3 = 0.f;
            float acc4 = 0.f, acc5 = 0.f, acc6 = 0.f, acc7 = 0.f;
#pragma unroll 5
            for (int k = 0; k < HH; ++k) {
                float w = Wd[k * G4 + tid];
                float4 ha = *reinterpret_cast<const float4*>(&h_s[k * 8]);
                float4 hb = *reinterpret_cast<const float4*>(&h_s[k * 8 + 4]);
                acc0 += w * ha.x; acc1 += w * ha.y; acc2 += w * ha.z; acc3 += w * ha.w;
                acc4 += w * hb.x; acc5 += w * hb.y; acc6 += w * hb.z; acc7 += w * hb.w;
            }
            float accs[8] = {acc0, acc1, acc2, acc3, acc4, acc5, acc6, acc7};
            int   Ls[8]   = {Lr0, Lr1, Lr2, Lr3, Lr4, Lr5, Lr6, Lr7};
#pragma unroll
            for (int r = 0; r < 8; ++r) {
                int L = Ls[r];
                int t = (s < L) ? (dir ? (L - 1 - s) : s) : s;
                float gin = __half2float(Gt[((size_t)(b0 + r) * SS + t) * N2 + dir * G4 + tid]);
                g_s[tid * 9 + r] = accs[r] + gin + bn;
            }
        }
        __syncthreads();
        if (tid < G4) {
            {   // row r0
                int rr = r0;
                float gi = g_s[(0 * HH + j0) * 9 + rr];
                float gf = g_s[(1 * HH + j0) * 9 + rr];
                float gg = g_s[(2 * HH + j0) * 9 + rr];
                float go = g_s[(3 * HH + j0) * 9 + rr];
                float iv = sigm(gi), fv = sigm(gf), gv = tanhf(gg), ov = sigm(go);
                float cn = fv * c0 + iv * gv;
                float hn = ov * tanhf(cn);
                int L = Le0;
                bool valid = (s < L);
                int t = valid ? (dir ? (L - 1 - s) : s) : s;
                float hw = valid ? hn : 0.f;
                if (valid) { c0 = cn; h_s[j0 * 8 + rr] = hn; }
                store_h(Hout + ((size_t)(b0 + rr) * SS + t) * ostride + dir * HH + j0, hw);
            }
            {   // row r0+4
                int rr = r0 + 4;
                float gi = g_s[(0 * HH + j0) * 9 + rr];
                float gf = g_s[(1 * HH + j0) * 9 + rr];
                float gg = g_s[(2 * HH + j0) * 9 + rr];
                float go = g_s[(3 * HH + j0) * 9 + rr];
                float iv = sigm(gi), fv = sigm(gf), gv = tanhf(gg), ov = sigm(go);
                float cn = fv * c1 + iv * gv;
                float hn = ov * tanhf(cn);
                int L = Le1;
                bool valid = (s < L);
                int t = valid ? (dir ? (L - 1 - s) : s) : s;
                float hw = valid ? hn : 0.f;
                if (valid) { c1 = cn; h_s[j0 * 8 + rr] = hn; }
                store_h(Hout + ((size_t)(b0 + rr) * SS + t) * ostride + dir * HH + j0, hw);
            }
        }
        __syncthreads();
    }
}

__global__ void __launch_bounds__(640) k_lstm_l0(const float* __restrict__ bf,
                                                 const float* __restrict__ bb) {
    lstm_body<__half>(g_gates, g_whht0, bf, bb, g_a16, KP);  // h1 -> fp16 A buffer
}
__global__ void __launch_bounds__(640) k_lstm_l1(const float* __restrict__ bf,
                                                 const float* __restrict__ bb) {
    lstm_body<float>(g_gates, g_whht1, bf, bb, g_h2, DD);    // h2 -> fp32 for head
}

// ---------------- final FC layers -----------------------------------------------
__global__ void __launch_bounds__(320) k_fc1(const float* __restrict__ bias) {
    __shared__ float v[DD];
    int b = blockIdx.x, tid = threadIdx.x;
    int L = g_len[b];
    const float* src = g_h2 + ((size_t)b * SS + (L - 1)) * DD;
    if (tid < DD) v[tid] = src[tid];
    __syncthreads();
    if (tid < DD) {
        float acc = bias[tid];
        for (int k = 0; k < DD; ++k) acc += v[k] * g_w1t[k * DD + tid];
        g_tmp[b * DD + tid] = tanhf(acc);
    }
}
__global__ void __launch_bounds__(320) k_fc2(const float* __restrict__ bias,
                                             float* __restrict__ out) {
    __shared__ float v[DD];
    int b = blockIdx.x, tid = threadIdx.x;
    if (tid < DD) v[tid] = g_tmp[b * DD + tid];
    __syncthreads();
    if (tid < DD) {
        float acc = bias[tid];
        for (int k = 0; k < DD; ++k) acc += v[k] * g_w2t[k * DD + tid];
        out[b * DD + tid] = acc;
    }
}

// ---------------- host ------------------------------------------------------------
extern "C" void kernel_launch(void* const* d_in, const int* in_sizes, int n_in,
                              void* d_out, int out_size) {
    const int*   x        = (const int*)  d_in[0];
    const int*   mask     = (const int*)  d_in[1];
    const float* emb      = (const float*)d_in[2];
    const float* Wih_l0f  = (const float*)d_in[3];
    const float* Whh_l0f  = (const float*)d_in[4];
    const float* b_l0f    = (const float*)d_in[5];
    const float* Wih_l0b  = (const float*)d_in[6];
    const float* Whh_l0b  = (const float*)d_in[7];
    const float* b_l0b    = (const float*)d_in[8];
    const float* Wih_l1f  = (const float*)d_in[9];
    const float* Whh_l1f  = (const float*)d_in[10];
    const float* b_l1f    = (const float*)d_in[11];
    const float* Wih_l1b  = (const float*)d_in[12];
    const float* Whh_l1b  = (const float*)d_in[13];
    const float* b_l1b    = (const float*)d_in[14];
    const float* W1       = (const float*)d_in[15];
    const float* b1       = (const float*)d_in[16];
    const float* W2       = (const float*)d_in[17];
    const float* b2       = (const float*)d_in[18];
    float* out = (float*)d_out;

    if (in_sizes[1] == BB * SS) k_len32<<<4, 256>>>(mask);
    else                        k_len64<<<4, 256>>>(mask);

    int nW16 = (N2 * KP + 255) / 256;
    k_pack_w16_0<<<nW16, 256>>>(Wih_l0f, Wih_l0b);
    k_pack_w16_1<<<nW16, 256>>>(Wih_l1f, Wih_l1b);
    int nWhh = (G4 * HH + 255) / 256;
    k_tr_whh0<<<nWhh, 256>>>(Whh_l0f, Whh_l0b);
    k_tr_whh1<<<nWhh, 256>>>(Whh_l1f, Whh_l1b);
    int nW = (DD * DD + 255) / 256;
    k_tr_fc<<<nW, 256>>>(W1, W2);

    // embedding -> fp16 A (zero-pads K tail)
    k_embed16<<<(BB * SS * 152 + 255) / 256, 256>>>(x, emb);

    dim3 g16((BB * SS) / 128, (N2 + 63) / 64);   // 2048 x 19

    // layer 0: a16 -> gates -> a16(h1, fp16)
    k_gemm16_l0<<<g16, 256>>>();
    k_lstm_l0<<<256, 640>>>(b_l0f, b_l0b);

    // layer 1: a16 -> gates -> h2(fp32)
    k_gemm16_l1<<<g16, 256>>>();
    k_lstm_l1<<<256, 640>>>(b_l1f, b_l1b);

    // head
    k_fc1<<<BB, 320>>>(b1);
    k_fc2<<<BB, 320>>>(b2, out);
}

// round 6
// speedup vs baseline: 3.6715x; 2.5562x over previous
#include <cuda_runtime.h>
#include <cuda_fp16.h>
#include <math.h>
#include <stddef.h>

#define BB 1024
#define SS 256
#define DD 300
#define HH 150
#define G4 600     // 4*H
#define N2 1200    // both directions
#define KP 304     // input-GEMM K padded to 16
#define KT16 (KP / 16)

// recurrence tiling
#define RK 160          // HH padded to 16 (10 k-tiles)
#define RKT 10
#define RNW 19          // warps per LSTM block (608 cols / 32)
#define HSTR 168        // h16 row stride (halves)
#define GSTR 616        // gate-stage row stride (halves)
#define PERM_PER_DIR (RNW * 32 * 160)   // halves per dir (= 97,280)

// ---------------- device scratch ------------------------------------------------
__device__ __half g_a16  [(size_t)BB * SS * KP];   // fp16 A: xe (L0) then h1 (L1)
__device__ float  g_h2   [(size_t)BB * SS * DD];   // layer1 output fp32
__device__ __half g_gates[(size_t)BB * SS * N2];   // input-projection gates fp16
__device__ __half g_w16_0[N2 * KP];                // packed Wih L0
__device__ __half g_w16_1[N2 * KP];
__device__ __half g_whhp0[2 * PERM_PER_DIR];       // fragment-permuted Whh L0
__device__ __half g_whhp1[2 * PERM_PER_DIR];
__device__ float  g_w1t  [DD * DD];
__device__ float  g_w2t  [DD * DD];
__device__ float  g_tmp  [BB * DD];
__device__ int    g_len  [BB];

// ---------------- fused setup kernel --------------------------------------------
__device__ __forceinline__ void perm_pack(const float* Wf, const float* Wb,
                                          __half* dst, int idx) {
    // layout: [dir][w][l][kt(10)][p(2)][ridx(4)][h(2)]
    int dir = idx / PERM_PER_DIR;
    int rem = idx - dir * PERM_PER_DIR;
    int wl  = rem / 160;
    int r2  = rem - wl * 160;
    int w   = wl >> 5, l = wl & 31;
    int kt  = r2 >> 4;
    int r3  = r2 & 15;
    int p   = r3 >> 3;
    int r4  = r3 & 7;
    int ridx = r4 >> 1, h = r4 & 1;
    int n = w * 32 + (p * 2 + (ridx >> 1)) * 8 + (l >> 2);
    int k = kt * 16 + (l & 3) * 2 + (ridx & 1) * 8 + h;
    float v = 0.f;
    if (n < G4 && k < HH) v = dir ? Wb[n * HH + k] : Wf[n * HH + k];
    dst[idx] = __float2half(v);
}

__global__ void k_setup(const int* __restrict__ mask, int mask64,
                        const float* __restrict__ Wih_l0f, const float* __restrict__ Wih_l0b,
                        const float* __restrict__ Wih_l1f, const float* __restrict__ Wih_l1b,
                        const float* __restrict__ Whh_l0f, const float* __restrict__ Whh_l0b,
                        const float* __restrict__ Whh_l1f, const float* __restrict__ Whh_l1b,
                        const float* __restrict__ W1, const float* __restrict__ W2) {
    int idx = blockIdx.x * blockDim.x + threadIdx.x;
    int task = blockIdx.y;
    if (task == 0) {                       // lengths
        if (idx < BB) {
            int c = 0;
            if (mask64) {
                const int* m = mask + (size_t)idx * SS * 2;
                for (int t = 0; t < SS; ++t) c += ((m[2 * t] | m[2 * t + 1]) != 0);
            } else {
                const int* m = mask + (size_t)idx * SS;
                for (int t = 0; t < SS; ++t) c += (m[t] != 0);
            }
            g_len[idx] = c;
        }
    } else if (task == 1 || task == 2) {   // pack Wih (padded fp16)
        if (idx < N2 * KP) {
            int n = idx / KP, k = idx - n * KP;
            const float* Wf = (task == 1) ? Wih_l0f : Wih_l1f;
            const float* Wb = (task == 1) ? Wih_l0b : Wih_l1b;
            float v = 0.f;
            if (k < DD) v = (n < G4) ? Wf[n * DD + k] : Wb[(n - G4) * DD + k];
            ((task == 1) ? g_w16_0 : g_w16_1)[idx] = __float2half(v);
        }
    } else if (task == 3) {                // perm Whh layer0
        if (idx < 2 * PERM_PER_DIR) perm_pack(Whh_l0f, Whh_l0b, g_whhp0, idx);
    } else if (task == 4) {                // perm Whh layer1
        if (idx < 2 * PERM_PER_DIR) perm_pack(Whh_l1f, Whh_l1b, g_whhp1, idx);
    } else {                               // FC transposes
        if (idx < DD * DD) {
            int r = idx / DD, c = idx - r * DD;
            g_w1t[c * DD + r] = W1[idx];
            g_w2t[c * DD + r] = W2[idx];
        }
    }
}

// ---------------- embedding gather -> fp16 A ------------------------------------
__global__ void k_embed16(const int* __restrict__ x, const float* __restrict__ emb) {
    int idx = blockIdx.x * blockDim.x + threadIdx.x;
    int bt = idx / 152;
    int c  = idx - bt * 152;
    int tok = x[bt];
    __half2 v = __floats2half2_rn(0.f, 0.f);
    if (c < 150 && tok != 0) {
        float2 f = reinterpret_cast<const float2*>(emb)[(size_t)tok * 150 + c];
        v = __floats2half2_rn(f.x, f.y);
    }
    reinterpret_cast<__half2*>(g_a16)[idx] = v;
}

// ---------------- input GEMM (HMMA): gates = A[M,KP] * Wih[N2,KP]^T --------------
__device__ __forceinline__ void gemm16_body(const __half* __restrict__ A,
                                            const __half* __restrict__ Bw,
                                            __half* __restrict__ C) {
    __shared__ __half As[128][24];
    __shared__ __half Bs[64][24];
    const int N = N2;
    int tid  = threadIdx.x;
    int m0   = blockIdx.x * 128;
    int n0   = blockIdx.y * 64;
    int warp = tid >> 5, lane = tid & 31;
    int wm = warp & 3, wn = warp >> 2;
    int l4 = lane >> 2, c2 = (lane & 3) * 2;

    float acc[2][4][4];
#pragma unroll
    for (int i = 0; i < 2; ++i)
#pragma unroll
        for (int j = 0; j < 4; ++j)
#pragma unroll
            for (int q = 0; q < 4; ++q) acc[i][j][q] = 0.f;

    int arow = tid >> 1, achk = (tid & 1) * 8;
    int brow = tid >> 1, bchk = (tid & 1) * 8;
    bool bvalid = (tid < 128) && (n0 + brow < N);

    {
        uint4 va = *reinterpret_cast<const uint4*>(A + (size_t)(m0 + arow) * KP + achk);
        *reinterpret_cast<uint4*>(&As[arow][achk]) = va;
        if (tid < 128) {
            uint4 vb = make_uint4(0, 0, 0, 0);
            if (bvalid) vb = *reinterpret_cast<const uint4*>(Bw + (size_t)(n0 + brow) * KP + bchk);
            *reinterpret_cast<uint4*>(&Bs[brow][bchk]) = vb;
        }
    }
    __syncthreads();

    for (int kt = 0; kt < KT16; ++kt) {
        uint4 va, vb;
        bool nxt = (kt + 1 < KT16);
        if (nxt) {
            int k0 = (kt + 1) * 16;
            va = *reinterpret_cast<const uint4*>(A + (size_t)(m0 + arow) * KP + k0 + achk);
            vb = make_uint4(0, 0, 0, 0);
            if (bvalid) vb = *reinterpret_cast<const uint4*>(Bw + (size_t)(n0 + brow) * KP + k0 + bchk);
        }
        unsigned af[2][4];
#pragma unroll
        for (int mi = 0; mi < 2; ++mi) {
            int rb = wm * 32 + mi * 16;
            af[mi][0] = *reinterpret_cast<const unsigned*>(&As[rb + l4][c2]);
            af[mi][1] = *reinterpret_cast<const unsigned*>(&As[rb + l4 + 8][c2]);
            af[mi][2] = *reinterpret_cast<const unsigned*>(&As[rb + l4][c2 + 8]);
            af[mi][3] = *reinterpret_cast<const unsigned*>(&As[rb + l4 + 8][c2 + 8]);
        }
        unsigned bf[4][2];
#pragma unroll
        for (int ni = 0; ni < 4; ++ni) {
            int nr = wn * 32 + ni * 8 + l4;
            bf[ni][0] = *reinterpret_cast<const unsigned*>(&Bs[nr][c2]);
            bf[ni][1] = *reinterpret_cast<const unsigned*>(&Bs[nr][c2 + 8]);
        }
#pragma unroll
        for (int mi = 0; mi < 2; ++mi)
#pragma unroll
            for (int ni = 0; ni < 4; ++ni)
                asm volatile(
                    "mma.sync.aligned.m16n8k16.row.col.f32.f16.f16.f32 "
                    "{%0,%1,%2,%3},{%4,%5,%6,%7},{%8,%9},{%0,%1,%2,%3};"
                    : "+f"(acc[mi][ni][0]), "+f"(acc[mi][ni][1]),
                      "+f"(acc[mi][ni][2]), "+f"(acc[mi][ni][3])
                    : "r"(af[mi][0]), "r"(af[mi][1]), "r"(af[mi][2]), "r"(af[mi][3]),
                      "r"(bf[ni][0]), "r"(bf[ni][1]));
        __syncthreads();
        if (nxt) {
            *reinterpret_cast<uint4*>(&As[arow][achk]) = va;
            if (tid < 128) *reinterpret_cast<uint4*>(&Bs[brow][bchk]) = vb;
        }
        __syncthreads();
    }
#pragma unroll
    for (int mi = 0; mi < 2; ++mi)
#pragma unroll
        for (int ni = 0; ni < 4; ++ni) {
            int m = m0 + wm * 32 + mi * 16 + l4;
            int n = n0 + wn * 32 + ni * 8 + c2;
            if (n < N) {
                __half2 h01 = __floats2half2_rn(acc[mi][ni][0], acc[mi][ni][1]);
                __half2 h23 = __floats2half2_rn(acc[mi][ni][2], acc[mi][ni][3]);
                *reinterpret_cast<__half2*>(C + (size_t)m * N + n)       = h01;
                *reinterpret_cast<__half2*>(C + (size_t)(m + 8) * N + n) = h23;
            }
        }
}

__global__ void __launch_bounds__(256) k_gemm16_l0() { gemm16_body(g_a16, g_w16_0, g_gates); }
__global__ void __launch_bounds__(256) k_gemm16_l1() { gemm16_body(g_a16, g_w16_1, g_gates); }

// ---------------- tensor-core persistent LSTM ------------------------------------
// 128 blocks (dir = bx&1, group = bx>>1 -> 16 batch rows), 608 threads = 19 warps.
__device__ __forceinline__ float sigm(float x) { return 1.f / (1.f + expf(-x)); }
__device__ __forceinline__ void store_h(float*  p, float v) { *p = v; }
__device__ __forceinline__ void store_h(__half* p, float v) { *p = __float2half(v); }

template <typename OutT>
__device__ __forceinline__ void lstm_mma_body(const __half* __restrict__ Gt,
                                              const __half* __restrict__ permAll,
                                              const float* __restrict__ bias_f,
                                              const float* __restrict__ bias_b,
                                              OutT* __restrict__ Hout, int ostride) {
    __shared__ __half h16[16][HSTR];         // fp16 h (matmul input), k padded to 160
    __shared__ __half g16[16 * GSTR];        // staged gate preactivations
    __shared__ int    t_s[16];

    int tid  = threadIdx.x;
    int dir  = blockIdx.x & 1;
    int b0   = (blockIdx.x >> 1) * 16;
    int warp = tid >> 5, lane = tid & 31;
    int l4   = lane >> 2, c2 = (lane & 3) * 2;
    int wbase = warp * 32;
    int goff = dir * G4;
    int hoff = dir * HH;
    const float* bias = dir ? bias_b : bias_f;
    const uint4* permLane =
        reinterpret_cast<const uint4*>(permAll + (size_t)dir * PERM_PER_DIR) +
        (warp * 32 + lane) * 20;

    // bias regs for this lane's 8 columns
    float2 bias2[4];
#pragma unroll
    for (int nt = 0; nt < 4; ++nt) {
        int cA = wbase + nt * 8 + c2;
        bias2[nt] = make_float2(0.f, 0.f);
        if (cA < G4) bias2[nt] = make_float2(bias[cA], bias[cA + 1]);
    }

    // rows for MMA staging (gin loads)
    size_t rowA = (size_t)(b0 + l4) * SS;
    size_t rowB = (size_t)(b0 + l4 + 8) * SS;

    // elementwise mapping: thread t<600 -> q (row group), j (hidden index)
    int q  = tid / 150;
    int j  = tid - q * 150;
    int q4 = q * 4;
    int Lrow[4];
    float cst[4] = {0.f, 0.f, 0.f, 0.f};
    if (tid < G4) {
#pragma unroll
        for (int m = 0; m < 4; ++m) Lrow[m] = g_len[b0 + q4 + m];
    }

    // init h16 = 0, t_s for s=0
    for (int i = tid; i < 16 * HSTR; i += blockDim.x)
        (&h16[0][0])[i] = __float2half(0.f);
    if (tid < 16) {
        int L = g_len[b0 + tid];
        t_s[tid] = (0 < L) ? (dir ? (L - 1) : 0) : 0;
    }
    __syncthreads();

    for (int s = 0; s < SS; ++s) {
        // ---- MMA phase: G[16 x 608] = h16[16 x 160] * Whh^T ----
        float acc[4][4];
#pragma unroll
        for (int nt = 0; nt < 4; ++nt)
#pragma unroll
            for (int r = 0; r < 4; ++r) acc[nt][r] = 0.f;

#pragma unroll
        for (int kt = 0; kt < RKT; ++kt) {
            int k0 = kt * 16;
            unsigned a0 = *reinterpret_cast<const unsigned*>(&h16[l4][k0 + c2]);
            unsigned a1 = *reinterpret_cast<const unsigned*>(&h16[l4 + 8][k0 + c2]);
            unsigned a2 = *reinterpret_cast<const unsigned*>(&h16[l4][k0 + c2 + 8]);
            unsigned a3 = *reinterpret_cast<const unsigned*>(&h16[l4 + 8][k0 + c2 + 8]);
            uint4 q0 = permLane[kt * 2 + 0];
            uint4 q1 = permLane[kt * 2 + 1];
            asm volatile("mma.sync.aligned.m16n8k16.row.col.f32.f16.f16.f32 "
                         "{%0,%1,%2,%3},{%4,%5,%6,%7},{%8,%9},{%0,%1,%2,%3};"
                         : "+f"(acc[0][0]), "+f"(acc[0][1]), "+f"(acc[0][2]), "+f"(acc[0][3])
                         : "r"(a0), "r"(a1), "r"(a2), "r"(a3), "r"(q0.x), "r"(q0.y));
            asm volatile("mma.sync.aligned.m16n8k16.row.col.f32.f16.f16.f32 "
                         "{%0,%1,%2,%3},{%4,%5,%6,%7},{%8,%9},{%0,%1,%2,%3};"
                         : "+f"(acc[1][0]), "+f"(acc[1][1]), "+f"(acc[1][2]), "+f"(acc[1][3])
                         : "r"(a0), "r"(a1), "r"(a2), "r"(a3), "r"(q0.z), "r"(q0.w));
            asm volatile("mma.sync.aligned.m16n8k16.row.col.f32.f16.f16.f32 "
                         "{%0,%1,%2,%3},{%4,%5,%6,%7},{%8,%9},{%0,%1,%2,%3};"
                         : "+f"(acc[2][0]), "+f"(acc[2][1]), "+f"(acc[2][2]), "+f"(acc[2][3])
                         : "r"(a0), "r"(a1), "r"(a2), "r"(a3), "r"(q1.x), "r"(q1.y));
            asm volatile("mma.sync.aligned.m16n8k16.row.col.f32.f16.f16.f32 "
                         "{%0,%1,%2,%3},{%4,%5,%6,%7},{%8,%9},{%0,%1,%2,%3};"
                         : "+f"(acc[3][0]), "+f"(acc[3][1]), "+f"(acc[3][2]), "+f"(acc[3][3])
                         : "r"(a0), "r"(a1), "r"(a2), "r"(a3), "r"(q1.z), "r"(q1.w));
        }

        // stage to smem with input-gates + bias
        int tA = t_s[l4], tB = t_s[l4 + 8];
#pragma unroll
        for (int nt = 0; nt < 4; ++nt) {
            int cA = wbase + nt * 8 + c2;
            if (cA < G4) {
                __half2 ga = *reinterpret_cast<const __half2*>(&Gt[(rowA + tA) * N2 + goff + cA]);
                __half2 gb = *reinterpret_cast<const __half2*>(&Gt[(rowB + tB) * N2 + goff + cA]);
                float2 fa = __half22float2(ga), fb = __half22float2(gb);
                __half2 hA = __floats2half2_rn(acc[nt][0] + bias2[nt].x + fa.x,
                                               acc[nt][1] + bias2[nt].y + fa.y);
                __half2 hB = __floats2half2_rn(acc[nt][2] + bias2[nt].x + fb.x,
                                               acc[nt][3] + bias2[nt].y + fb.y);
                *reinterpret_cast<__half2*>(&g16[l4 * GSTR + cA])       = hA;
                *reinterpret_cast<__half2*>(&g16[(l4 + 8) * GSTR + cA]) = hB;
            }
        }
        __syncthreads();

        // ---- elementwise phase ----
        if (tid < G4) {
#pragma unroll
            for (int m = 0; m < 4; ++m) {
                int rr = q4 + m;
                int L  = Lrow[m];
                float gi = __half2float(g16[rr * GSTR + j]);
                float gf = __half2float(g16[rr * GSTR + 150 + j]);
                float gg = __half2float(g16[rr * GSTR + 300 + j]);
                float go = __half2float(g16[rr * GSTR + 450 + j]);
                float iv = sigm(gi), fv = sigm(gf), gv = tanhf(gg), ov = sigm(go);
                float cn = fv * cst[m] + iv * gv;
                float hn = ov * tanhf(cn);
                bool valid = (s < L);
                int t = valid ? (dir ? (L - 1 - s) : s) : s;
                float hw = valid ? hn : 0.f;
                if (valid) {
                    cst[m] = cn;
                    h16[rr][j] = __float2half(hn);
                }
                store_h(Hout + ((size_t)(b0 + rr) * SS + t) * ostride + hoff + j, hw);
            }
            if (j == 0) {   // next step's t indices for this thread's 4 rows
                int s1 = s + 1;
#pragma unroll
                for (int m = 0; m < 4; ++m) {
                    int rr = q4 + m, L = Lrow[m];
                    t_s[rr] = (s1 < L) ? (dir ? (L - 1 - s1) : s1) : s1;
                }
            }
        }
        __syncthreads();
    }
}

__global__ void __launch_bounds__(608) k_lstm_l0(const float* __restrict__ bf,
                                                 const float* __restrict__ bb) {
    lstm_mma_body<__half>(g_gates, g_whhp0, bf, bb, g_a16, KP);   // h1 -> fp16 A
}
__global__ void __launch_bounds__(608) k_lstm_l1(const float* __restrict__ bf,
                                                 const float* __restrict__ bb) {
    lstm_mma_body<float>(g_gates, g_whhp1, bf, bb, g_h2, DD);     // h2 -> fp32
}

// ---------------- final FC layers -------------------------------------------------
__global__ void __launch_bounds__(320) k_fc1(const float* __restrict__ bias) {
    __shared__ float v[DD];
    int b = blockIdx.x, tid = threadIdx.x;
    int L = g_len[b];
    const float* src = g_h2 + ((size_t)b * SS + (L - 1)) * DD;
    if (tid < DD) v[tid] = src[tid];
    __syncthreads();
    if (tid < DD) {
        float acc = bias[tid];
        for (int k = 0; k < DD; ++k) acc += v[k] * g_w1t[k * DD + tid];
        g_tmp[b * DD + tid] = tanhf(acc);
    }
}
__global__ void __launch_bounds__(320) k_fc2(const float* __restrict__ bias,
                                             float* __restrict__ out) {
    __shared__ float v[DD];
    int b = blockIdx.x, tid = threadIdx.x;
    if (tid < DD) v[tid] = g_tmp[b * DD + tid];
    __syncthreads();
    if (tid < DD) {
        float acc = bias[tid];
        for (int k = 0; k < DD; ++k) acc += v[k] * g_w2t[k * DD + tid];
        out[b * DD + tid] = acc;
    }
}

// ---------------- host --------------------------------------------------------------
extern "C" void kernel_launch(void* const* d_in, const int* in_sizes, int n_in,
                              void* d_out, int out_size) {
    const int*   x        = (const int*)  d_in[0];
    const int*   mask     = (const int*)  d_in[1];
    const float* emb      = (const float*)d_in[2];
    const float* Wih_l0f  = (const float*)d_in[3];
    const float* Whh_l0f  = (const float*)d_in[4];
    const float* b_l0f    = (const float*)d_in[5];
    const float* Wih_l0b  = (const float*)d_in[6];
    const float* Whh_l0b  = (const float*)d_in[7];
    const float* b_l0b    = (const float*)d_in[8];
    const float* Wih_l1f  = (const float*)d_in[9];
    const float* Whh_l1f  = (const float*)d_in[10];
    const float* b_l1f    = (const float*)d_in[11];
    const float* Wih_l1b  = (const float*)d_in[12];
    const float* Whh_l1b  = (const float*)d_in[13];
    const float* b_l1b    = (const float*)d_in[14];
    const float* W1       = (const float*)d_in[15];
    const float* b1       = (const float*)d_in[16];
    const float* W2       = (const float*)d_in[17];
    const float* b2       = (const float*)d_in[18];
    float* out = (float*)d_out;

    int mask64 = (in_sizes[1] != BB * SS) ? 1 : 0;

    // launch 0: fused setup
    dim3 sgrid(1425, 6);
    k_setup<<<sgrid, 256>>>(mask, mask64,
                            Wih_l0f, Wih_l0b, Wih_l1f, Wih_l1b,
                            Whh_l0f, Whh_l0b, Whh_l1f, Whh_l1b, W1, W2);

    // launch 1: embedding
    k_embed16<<<(BB * SS * 152 + 255) / 256, 256>>>(x, emb);

    dim3 g16((BB * SS) / 128, (N2 + 63) / 64);

    // launch 2/3: layer 0
    k_gemm16_l0<<<g16, 256>>>();
    k_lstm_l0<<<128, 608>>>(b_l0f, b_l0b);

    // launch 4/5: layer 1
    k_gemm16_l1<<<g16, 256>>>();
    k_lstm_l1<<<128, 608>>>(b_l1f, b_l1b);

    // head
    k_fc1<<<BB, 320>>>(b1);
    k_fc2<<<BB, 320>>>(b2, out);
}

// round 7
// speedup vs baseline: 4.5050x; 1.2270x over previous
#include <cuda_runtime.h>
#include <cuda_fp16.h>
#include <math.h>
#include <stddef.h>

#define BB 1024
#define SS 256
#define DD 300
#define HH 150
#define G4 600     // 4*H
#define N2 1200    // both directions
#define N2P 1280   // padded weight rows for guard-free GEMM loads
#define KP 304     // input-GEMM K padded to 16
#define KT16 (KP / 16)

// recurrence tiling
#define RKT 10
#define RNW 19
#define HSTR 168
#define GSTR 616
#define PERM_PER_DIR (RNW * 32 * 160)

// ---------------- device scratch ------------------------------------------------
__device__ __half g_a16  [(size_t)BB * SS * KP];
__device__ float  g_h2   [(size_t)BB * SS * DD];
__device__ __half g_gates[(size_t)BB * SS * N2];
__device__ __half g_w16_0[N2P * KP];
__device__ __half g_w16_1[N2P * KP];
__device__ __half g_whhp0[2 * PERM_PER_DIR];
__device__ __half g_whhp1[2 * PERM_PER_DIR];
__device__ float  g_w1t  [DD * DD];
__device__ float  g_w2t  [DD * DD];
__device__ float  g_tmp  [BB * DD];
__device__ int    g_len  [BB];

// ---------------- fused setup ----------------------------------------------------
__device__ __forceinline__ void perm_pack(const float* Wf, const float* Wb,
                                          __half* dst, int idx) {
    int dir = idx / PERM_PER_DIR;
    int rem = idx - dir * PERM_PER_DIR;
    int wl  = rem / 160;
    int r2  = rem - wl * 160;
    int w   = wl >> 5, l = wl & 31;
    int kt  = r2 >> 4;
    int r3  = r2 & 15;
    int p   = r3 >> 3;
    int r4  = r3 & 7;
    int ridx = r4 >> 1, h = r4 & 1;
    int n = w * 32 + (p * 2 + (ridx >> 1)) * 8 + (l >> 2);
    int k = kt * 16 + (l & 3) * 2 + (ridx & 1) * 8 + h;
    float v = 0.f;
    if (n < G4 && k < HH) v = dir ? Wb[n * HH + k] : Wf[n * HH + k];
    dst[idx] = __float2half(v);
}

__global__ void k_setup(const int* __restrict__ mask, int mask64,
                        const float* __restrict__ Wih_l0f, const float* __restrict__ Wih_l0b,
                        const float* __restrict__ Wih_l1f, const float* __restrict__ Wih_l1b,
                        const float* __restrict__ Whh_l0f, const float* __restrict__ Whh_l0b,
                        const float* __restrict__ Whh_l1f, const float* __restrict__ Whh_l1b,
                        const float* __restrict__ W1, const float* __restrict__ W2) {
    int idx = blockIdx.x * blockDim.x + threadIdx.x;
    int task = blockIdx.y;
    if (task == 0) {
        if (idx < BB) {
            int c = 0;
            if (mask64) {
                const int* m = mask + (size_t)idx * SS * 2;
                for (int t = 0; t < SS; ++t) c += ((m[2 * t] | m[2 * t + 1]) != 0);
            } else {
                const int* m = mask + (size_t)idx * SS;
                for (int t = 0; t < SS; ++t) c += (m[t] != 0);
            }
            g_len[idx] = c;
        }
    } else if (task == 1 || task == 2) {       // pack Wih padded fp16 (rows>=N2 zero)
        if (idx < N2P * KP) {
            int n = idx / KP, k = idx - n * KP;
            const float* Wf = (task == 1) ? Wih_l0f : Wih_l1f;
            const float* Wb = (task == 1) ? Wih_l0b : Wih_l1b;
            float v = 0.f;
            if (n < N2 && k < DD) v = (n < G4) ? Wf[n * DD + k] : Wb[(n - G4) * DD + k];
            ((task == 1) ? g_w16_0 : g_w16_1)[idx] = __float2half(v);
        }
    } else if (task == 3) {
        if (idx < 2 * PERM_PER_DIR) perm_pack(Whh_l0f, Whh_l0b, g_whhp0, idx);
    } else if (task == 4) {
        if (idx < 2 * PERM_PER_DIR) perm_pack(Whh_l1f, Whh_l1b, g_whhp1, idx);
    } else {
        if (idx < DD * DD) {
            int r = idx / DD, c = idx - r * DD;
            g_w1t[c * DD + r] = W1[idx];
            g_w2t[c * DD + r] = W2[idx];
        }
    }
}

// ---------------- embedding gather -> fp16 A ------------------------------------
__global__ void k_embed16(const int* __restrict__ x, const float* __restrict__ emb) {
    int idx = blockIdx.x * blockDim.x + threadIdx.x;
    int bt = idx / 152;
    int c  = idx - bt * 152;
    int tok = x[bt];
    __half2 v = __floats2half2_rn(0.f, 0.f);
    if (c < 150 && tok != 0) {
        float2 f = reinterpret_cast<const float2*>(emb)[(size_t)tok * 150 + c];
        v = __floats2half2_rn(f.x, f.y);
    }
    reinterpret_cast<__half2*>(g_a16)[idx] = v;
}

// ---------------- input GEMM: cp.async 3-stage, 128x128x16 ----------------------
__device__ __forceinline__ void cp16(unsigned dst, const void* src) {
    asm volatile("cp.async.cg.shared.global [%0], [%1], 16;\n" :: "r"(dst), "l"(src));
}
__device__ __forceinline__ void cp_commit() { asm volatile("cp.async.commit_group;\n"); }
__device__ __forceinline__ void cp_wait1()  { asm volatile("cp.async.wait_group 1;\n"); }
__device__ __forceinline__ void cp_wait0()  { asm volatile("cp.async.wait_group 0;\n"); }

__device__ __forceinline__ void gemm16_body(const __half* __restrict__ A,
                                            const __half* __restrict__ Bw,
                                            __half* __restrict__ C) {
    __shared__ __half As[3][128][24];
    __shared__ __half Bs[3][128][24];
    int tid  = threadIdx.x;
    int m0   = blockIdx.x * 128;
    int n0   = blockIdx.y * 128;
    int warp = tid >> 5, lane = tid & 31;
    int wm = warp & 3, wn = warp >> 2;          // warp tile: 32 rows x 64 cols
    int l4 = lane >> 2, c2 = (lane & 3) * 2;
    int row = tid >> 1, chk = (tid & 1) * 8;

    const __half* Asrc = A + (size_t)(m0 + row) * KP + chk;
    const __half* Bsrc = Bw + (size_t)(n0 + row) * KP + chk;

    float acc[2][8][4];
#pragma unroll
    for (int i = 0; i < 2; ++i)
#pragma unroll
        for (int j = 0; j < 8; ++j)
#pragma unroll
            for (int q = 0; q < 4; ++q) acc[i][j][q] = 0.f;

    // prefetch stages 0,1
#pragma unroll
    for (int p = 0; p < 2; ++p) {
        unsigned da = (unsigned)__cvta_generic_to_shared(&As[p][row][chk]);
        unsigned db = (unsigned)__cvta_generic_to_shared(&Bs[p][row][chk]);
        cp16(da, Asrc + p * 16);
        cp16(db, Bsrc + p * 16);
        cp_commit();
    }

    for (int kt = 0; kt < KT16; ++kt) {
        if (kt == KT16 - 1) cp_wait0(); else cp_wait1();
        __syncthreads();
        int st = kt % 3;
        if (kt + 2 < KT16) {
            int ns = (kt + 2) % 3;
            unsigned da = (unsigned)__cvta_generic_to_shared(&As[ns][row][chk]);
            unsigned db = (unsigned)__cvta_generic_to_shared(&Bs[ns][row][chk]);
            cp16(da, Asrc + (kt + 2) * 16);
            cp16(db, Bsrc + (kt + 2) * 16);
            cp_commit();
        }

        unsigned af[2][4];
#pragma unroll
        for (int mi = 0; mi < 2; ++mi) {
            int rb = wm * 32 + mi * 16;
            af[mi][0] = *reinterpret_cast<const unsigned*>(&As[st][rb + l4][c2]);
            af[mi][1] = *reinterpret_cast<const unsigned*>(&As[st][rb + l4 + 8][c2]);
            af[mi][2] = *reinterpret_cast<const unsigned*>(&As[st][rb + l4][c2 + 8]);
            af[mi][3] = *reinterpret_cast<const unsigned*>(&As[st][rb + l4 + 8][c2 + 8]);
        }
        unsigned bf[8][2];
#pragma unroll
        for (int ni = 0; ni < 8; ++ni) {
            int nr = wn * 64 + ni * 8 + l4;
            bf[ni][0] = *reinterpret_cast<const unsigned*>(&Bs[st][nr][c2]);
            bf[ni][1] = *reinterpret_cast<const unsigned*>(&Bs[st][nr][c2 + 8]);
        }
#pragma unroll
        for (int mi = 0; mi < 2; ++mi)
#pragma unroll
            for (int ni = 0; ni < 8; ++ni)
                asm volatile(
                    "mma.sync.aligned.m16n8k16.row.col.f32.f16.f16.f32 "
                    "{%0,%1,%2,%3},{%4,%5,%6,%7},{%8,%9},{%0,%1,%2,%3};"
                    : "+f"(acc[mi][ni][0]), "+f"(acc[mi][ni][1]),
                      "+f"(acc[mi][ni][2]), "+f"(acc[mi][ni][3])
                    : "r"(af[mi][0]), "r"(af[mi][1]), "r"(af[mi][2]), "r"(af[mi][3]),
                      "r"(bf[ni][0]), "r"(bf[ni][1]));
        __syncthreads();
    }

#pragma unroll
    for (int mi = 0; mi < 2; ++mi)
#pragma unroll
        for (int ni = 0; ni < 8; ++ni) {
            int m = m0 + wm * 32 + mi * 16 + l4;
            int n = n0 + wn * 64 + ni * 8 + c2;
            if (n < N2) {
                __half2 h01 = __floats2half2_rn(acc[mi][ni][0], acc[mi][ni][1]);
                __half2 h23 = __floats2half2_rn(acc[mi][ni][2], acc[mi][ni][3]);
                *reinterpret_cast<__half2*>(C + (size_t)m * N2 + n)       = h01;
                *reinterpret_cast<__half2*>(C + (size_t)(m + 8) * N2 + n) = h23;
            }
        }
}

__global__ void __launch_bounds__(256) k_gemm16_l0() { gemm16_body(g_a16, g_w16_0, g_gates); }
__global__ void __launch_bounds__(256) k_gemm16_l1() { gemm16_body(g_a16, g_w16_1, g_gates); }

// ---------------- fast activations ----------------------------------------------
__device__ __forceinline__ float tanh_fast(float x) {
    float y; asm("tanh.approx.f32 %0, %1;" : "=f"(y) : "f"(x)); return y;
}
__device__ __forceinline__ float sigm_fast(float x) {
    float e; asm("ex2.approx.f32 %0, %1;" : "=f"(e) : "f"(-1.442695041f * x));
    float r; asm("rcp.approx.f32 %0, %1;" : "=f"(r) : "f"(1.f + e));
    return r;
}
__device__ __forceinline__ void store_h(float*  p, float v) { *p = v; }
__device__ __forceinline__ void store_h(__half* p, float v) { *p = __float2half(v); }

// ---------------- tensor-core persistent LSTM ------------------------------------
template <typename OutT>
__device__ __forceinline__ void lstm_mma_body(const __half* __restrict__ Gt,
                                              const __half* __restrict__ permAll,
                                              const float* __restrict__ bias_f,
                                              const float* __restrict__ bias_b,
                                              OutT* __restrict__ Hout, int ostride) {
    __shared__ __half h16[16][HSTR];
    __shared__ __half g16[16 * GSTR];
    __shared__ int    t_s[16];

    int tid  = threadIdx.x;
    int dir  = blockIdx.x & 1;
    int b0   = (blockIdx.x >> 1) * 16;
    int warp = tid >> 5, lane = tid & 31;
    int l4   = lane >> 2, c2 = (lane & 3) * 2;
    int wbase = warp * 32;
    int goff = dir * G4;
    int hoff = dir * HH;
    const float* bias = dir ? bias_b : bias_f;
    const uint4* permLane =
        reinterpret_cast<const uint4*>(permAll + (size_t)dir * PERM_PER_DIR) +
        (warp * 32 + lane) * 20;

    float2 bias2[4];
#pragma unroll
    for (int nt = 0; nt < 4; ++nt) {
        int cA = wbase + nt * 8 + c2;
        bias2[nt] = make_float2(0.f, 0.f);
        if (cA < G4) bias2[nt] = make_float2(bias[cA], bias[cA + 1]);
    }

    size_t rowA = (size_t)(b0 + l4) * SS;
    size_t rowB = (size_t)(b0 + l4 + 8) * SS;

    int q  = tid / 150;
    int j  = tid - q * 150;
    int q4 = q * 4;
    int Lrow[4];
    float cst[4] = {0.f, 0.f, 0.f, 0.f};
    if (tid < G4) {
#pragma unroll
        for (int m = 0; m < 4; ++m) Lrow[m] = g_len[b0 + q4 + m];
    }

    for (int i = tid; i < 16 * HSTR; i += blockDim.x)
        (&h16[0][0])[i] = __float2half(0.f);
    if (tid < 16) {
        int L = g_len[b0 + tid];
        t_s[tid] = (0 < L) ? (dir ? (L - 1) : 0) : 0;
    }
    __syncthreads();

    for (int s = 0; s < SS; ++s) {
        // ---- prefetch input-projection gates for this step (hide DRAM latency) ----
        int tA = t_s[l4], tB = t_s[l4 + 8];
        __half2 ga[4], gb[4];
#pragma unroll
        for (int nt = 0; nt < 4; ++nt) {
            int cA = wbase + nt * 8 + c2;
            if (cA < G4) {
                ga[nt] = *reinterpret_cast<const __half2*>(&Gt[(rowA + tA) * N2 + goff + cA]);
                gb[nt] = *reinterpret_cast<const __half2*>(&Gt[(rowB + tB) * N2 + goff + cA]);
            }
        }

        // ---- MMA phase ----
        float acc[4][4];
#pragma unroll
        for (int nt = 0; nt < 4; ++nt)
#pragma unroll
            for (int r = 0; r < 4; ++r) acc[nt][r] = 0.f;

#pragma unroll
        for (int kt = 0; kt < RKT; ++kt) {
            int k0 = kt * 16;
            unsigned a0 = *reinterpret_cast<const unsigned*>(&h16[l4][k0 + c2]);
            unsigned a1 = *reinterpret_cast<const unsigned*>(&h16[l4 + 8][k0 + c2]);
            unsigned a2 = *reinterpret_cast<const unsigned*>(&h16[l4][k0 + c2 + 8]);
            unsigned a3 = *reinterpret_cast<const unsigned*>(&h16[l4 + 8][k0 + c2 + 8]);
            uint4 q0 = permLane[kt * 2 + 0];
            uint4 q1 = permLane[kt * 2 + 1];
            asm volatile("mma.sync.aligned.m16n8k16.row.col.f32.f16.f16.f32 "
                         "{%0,%1,%2,%3},{%4,%5,%6,%7},{%8,%9},{%0,%1,%2,%3};"
                         : "+f"(acc[0][0]), "+f"(acc[0][1]), "+f"(acc[0][2]), "+f"(acc[0][3])
                         : "r"(a0), "r"(a1), "r"(a2), "r"(a3), "r"(q0.x), "r"(q0.y));
            asm volatile("mma.sync.aligned.m16n8k16.row.col.f32.f16.f16.f32 "
                         "{%0,%1,%2,%3},{%4,%5,%6,%7},{%8,%9},{%0,%1,%2,%3};"
                         : "+f"(acc[1][0]), "+f"(acc[1][1]), "+f"(acc[1][2]), "+f"(acc[1][3])
                         : "r"(a0), "r"(a1), "r"(a2), "r"(a3), "r"(q0.z), "r"(q0.w));
            asm volatile("mma.sync.aligned.m16n8k16.row.col.f32.f16.f16.f32 "
                         "{%0,%1,%2,%3},{%4,%5,%6,%7},{%8,%9},{%0,%1,%2,%3};"
                         : "+f"(acc[2][0]), "+f"(acc[2][1]), "+f"(acc[2][2]), "+f"(acc[2][3])
                         : "r"(a0), "r"(a1), "r"(a2), "r"(a3), "r"(q1.x), "r"(q1.y));
            asm volatile("mma.sync.aligned.m16n8k16.row.col.f32.f16.f16.f32 "
                         "{%0,%1,%2,%3},{%4,%5,%6,%7},{%8,%9},{%0,%1,%2,%3};"
                         : "+f"(acc[3][0]), "+f"(acc[3][1]), "+f"(acc[3][2]), "+f"(acc[3][3])
                         : "r"(a0), "r"(a1), "r"(a2), "r"(a3), "r"(q1.z), "r"(q1.w));
        }

        // ---- stage gates + bias ----
#pragma unroll
        for (int nt = 0; nt < 4; ++nt) {
            int cA = wbase + nt * 8 + c2;
            if (cA < G4) {
                float2 fa = __half22float2(ga[nt]), fb = __half22float2(gb[nt]);
                __half2 hA = __floats2half2_rn(acc[nt][0] + bias2[nt].x + fa.x,
                                               acc[nt][1] + bias2[nt].y + fa.y);
                __half2 hB = __floats2half2_rn(acc[nt][2] + bias2[nt].x + fb.x,
                                               acc[nt][3] + bias2[nt].y + fb.y);
                *reinterpret_cast<__half2*>(&g16[l4 * GSTR + cA])       = hA;
                *reinterpret_cast<__half2*>(&g16[(l4 + 8) * GSTR + cA]) = hB;
            }
        }
        __syncthreads();

        // ---- elementwise phase ----
        if (tid < G4) {
#pragma unroll
            for (int m = 0; m < 4; ++m) {
                int rr = q4 + m;
                int L  = Lrow[m];
                float gi = __half2float(g16[rr * GSTR + j]);
                float gf = __half2float(g16[rr * GSTR + 150 + j]);
                float gg = __half2float(g16[rr * GSTR + 300 + j]);
                float go = __half2float(g16[rr * GSTR + 450 + j]);
                float iv = sigm_fast(gi), fv = sigm_fast(gf);
                float gv = tanh_fast(gg), ov = sigm_fast(go);
                float cn = fv * cst[m] + iv * gv;
                float hn = ov * tanh_fast(cn);
                bool valid = (s < L);
                int t = valid ? (dir ? (L - 1 - s) : s) : s;
                float hw = valid ? hn : 0.f;
                if (valid) {
                    cst[m] = cn;
                    h16[rr][j] = __float2half(hn);
                }
                store_h(Hout + ((size_t)(b0 + rr) * SS + t) * ostride + hoff + j, hw);
            }
            if (j == 0) {
                int s1 = s + 1;
#pragma unroll
                for (int m = 0; m < 4; ++m) {
                    int rr = q4 + m, L = Lrow[m];
                    t_s[rr] = (s1 < L) ? (dir ? (L - 1 - s1) : s1) : s1;
                }
            }
        }
        __syncthreads();
    }
}

__global__ void __launch_bounds__(608) k_lstm_l0(const float* __restrict__ bf,
                                                 const float* __restrict__ bb) {
    lstm_mma_body<__half>(g_gates, g_whhp0, bf, bb, g_a16, KP);
}
__global__ void __launch_bounds__(608) k_lstm_l1(const float* __restrict__ bf,
                                                 const float* __restrict__ bb) {
    lstm_mma_body<float>(g_gates, g_whhp1, bf, bb, g_h2, DD);
}

// ---------------- final FC layers -------------------------------------------------
__global__ void __launch_bounds__(320) k_fc1(const float* __restrict__ bias) {
    __shared__ float v[DD];
    int b = blockIdx.x, tid = threadIdx.x;
    int L = g_len[b];
    const float* src = g_h2 + ((size_t)b * SS + (L - 1)) * DD;
    if (tid < DD) v[tid] = src[tid];
    __syncthreads();
    if (tid < DD) {
        float acc = bias[tid];
        for (int k = 0; k < DD; ++k) acc += v[k] * g_w1t[k * DD + tid];
        g_tmp[b * DD + tid] = tanhf(acc);
    }
}
__global__ void __launch_bounds__(320) k_fc2(const float* __restrict__ bias,
                                             float* __restrict__ out) {
    __shared__ float v[DD];
    int b = blockIdx.x, tid = threadIdx.x;
    if (tid < DD) v[tid] = g_tmp[b * DD + tid];
    __syncthreads();
    if (tid < DD) {
        float acc = bias[tid];
        for (int k = 0; k < DD; ++k) acc += v[k] * g_w2t[k * DD + tid];
        out[b * DD + tid] = acc;
    }
}

// ---------------- host --------------------------------------------------------------
extern "C" void kernel_launch(void* const* d_in, const int* in_sizes, int n_in,
                              void* d_out, int out_size) {
    const int*   x        = (const int*)  d_in[0];
    const int*   mask     = (const int*)  d_in[1];
    const float* emb      = (const float*)d_in[2];
    const float* Wih_l0f  = (const float*)d_in[3];
    const float* Whh_l0f  = (const float*)d_in[4];
    const float* b_l0f    = (const float*)d_in[5];
    const float* Wih_l0b  = (const float*)d_in[6];
    const float* Whh_l0b  = (const float*)d_in[7];
    const float* b_l0b    = (const float*)d_in[8];
    const float* Wih_l1f  = (const float*)d_in[9];
    const float* Whh_l1f  = (const float*)d_in[10];
    const float* b_l1f    = (const float*)d_in[11];
    const float* Wih_l1b  = (const float*)d_in[12];
    const float* Whh_l1b  = (const float*)d_in[13];
    const float* b_l1b    = (const float*)d_in[14];
    const float* W1       = (const float*)d_in[15];
    const float* b1       = (const float*)d_in[16];
    const float* W2       = (const float*)d_in[17];
    const float* b2       = (const float*)d_in[18];
    float* out = (float*)d_out;

    int mask64 = (in_sizes[1] != BB * SS) ? 1 : 0;

    dim3 sgrid(1520, 6);   // max task: N2P*KP/256 = 1520
    k_setup<<<sgrid, 256>>>(mask, mask64,
                            Wih_l0f, Wih_l0b, Wih_l1f, Wih_l1b,
                            Whh_l0f, Whh_l0b, Whh_l1f, Whh_l1b, W1, W2);

    k_embed16<<<(BB * SS * 152 + 255) / 256, 256>>>(x, emb);

    dim3 g16((BB * SS) / 128, N2P / 128);   // 2048 x 10

    k_gemm16_l0<<<g16, 256>>>();
    k_lstm_l0<<<128, 608>>>(b_l0f, b_l0b);

    k_gemm16_l1<<<g16, 256>>>();
    k_lstm_l1<<<128, 608>>>(b_l1f, b_l1b);

    k_fc1<<<BB, 320>>>(b1);
    k_fc2<<<BB, 320>>>(b2, out);
}

// round 9
// speedup vs baseline: 4.7044x; 1.0443x over previous
#include <cuda_runtime.h>
#include <cuda_fp16.h>
#include <math.h>
#include <stddef.h>

#define BB 1024
#define SS 256
#define DD 300
#define HH 150
#define G4 600     // 4*H
#define N2 1200    // both directions
#define N2P 1280   // padded weight rows (guard-free GEMM loads)
#define KP 304     // input-GEMM K padded to 16
#define KT16 (KP / 16)

// recurrence tiling
#define RKT 10
#define RNW 19
#define HSTR 168
#define PERM_PER_DIR (RNW * 32 * 160)

// ---------------- device scratch ------------------------------------------------
__device__ __half g_a16  [(size_t)BB * SS * KP];
__device__ float  g_h2   [(size_t)BB * SS * DD];
__device__ __half g_gates[(size_t)BB * SS * N2];
__device__ __half g_w16_0[N2P * KP];
__device__ __half g_w16_1[N2P * KP];
__device__ __half g_whhp0[2 * PERM_PER_DIR];
__device__ __half g_whhp1[2 * PERM_PER_DIR];
__device__ float  g_bias0[N2P];                 // interleaved bias layer0 (f|b)
__device__ float  g_bias1[N2P];
__device__ float  g_w1t  [DD * DD];
__device__ float  g_w2t  [DD * DD];
__device__ float  g_tmp  [BB * DD];
__device__ int    g_len  [BB];

// gate-interleaved weight-row map: within-dir column m -> weight row
// m = 4*j + g  ->  row = g*HH + j
__device__ __forceinline__ int ilv_row(int m) { return (m & 3) * HH + (m >> 2); }

// ---------------- fused setup ----------------------------------------------------
__device__ __forceinline__ void perm_pack(const float* Wf, const float* Wb,
                                          __half* dst, int idx) {
    int dir = idx / PERM_PER_DIR;
    int rem = idx - dir * PERM_PER_DIR;
    int wl  = rem / 160;
    int r2  = rem - wl * 160;
    int w   = wl >> 5, l = wl & 31;
    int kt  = r2 >> 4;
    int r3  = r2 & 15;
    int p   = r3 >> 3;
    int r4  = r3 & 7;
    int ridx = r4 >> 1, h = r4 & 1;
    int m = w * 32 + (p * 2 + (ridx >> 1)) * 8 + (l >> 2);    // within-dir col (interleaved)
    int k = kt * 16 + (l & 3) * 2 + (ridx & 1) * 8 + h;
    float v = 0.f;
    if (m < G4 && k < HH) {
        int row = ilv_row(m);
        v = dir ? Wb[row * HH + k] : Wf[row * HH + k];
    }
    dst[idx] = __float2half(v);
}

__global__ void k_setup(const int* __restrict__ mask, int mask64,
                        const float* __restrict__ Wih_l0f, const float* __restrict__ Wih_l0b,
                        const float* __restrict__ Wih_l1f, const float* __restrict__ Wih_l1b,
                        const float* __restrict__ Whh_l0f, const float* __restrict__ Whh_l0b,
                        const float* __restrict__ Whh_l1f, const float* __restrict__ Whh_l1b,
                        const float* __restrict__ b_l0f, const float* __restrict__ b_l0b,
                        const float* __restrict__ b_l1f, const float* __restrict__ b_l1b,
                        const float* __restrict__ W1, const float* __restrict__ W2) {
    int idx = blockIdx.x * blockDim.x + threadIdx.x;
    int task = blockIdx.y;
    if (task == 0) {
        if (idx < BB) {
            int c = 0;
            if (mask64) {
                const int* m = mask + (size_t)idx * SS * 2;
                for (int t = 0; t < SS; ++t) c += ((m[2 * t] | m[2 * t + 1]) != 0);
            } else {
                const int* m = mask + (size_t)idx * SS;
                for (int t = 0; t < SS; ++t) c += (m[t] != 0);
            }
            g_len[idx] = c;
        }
        // bias packs (small; reuse task 0 blocks beyond BB range)
        if (idx < N2P) {
            float v0 = 0.f, v1 = 0.f;
            if (idx < N2) {
                int dir = (idx >= G4);
                int m   = idx - dir * G4;
                int row = ilv_row(m);
                v0 = dir ? b_l0b[row] : b_l0f[row];
                v1 = dir ? b_l1b[row] : b_l1f[row];
            }
            g_bias0[idx] = v0;
            g_bias1[idx] = v1;
        }
    } else if (task == 1 || task == 2) {       // pack Wih interleaved fp16
        if (idx < N2P * KP) {
            int n = idx / KP, k = idx - n * KP;
            const float* Wf = (task == 1) ? Wih_l0f : Wih_l1f;
            const float* Wb = (task == 1) ? Wih_l0b : Wih_l1b;
            float v = 0.f;
            if (n < N2 && k < DD) {
                int dir = (n >= G4);
                int m   = n - dir * G4;
                int row = ilv_row(m);
                v = dir ? Wb[row * DD + k] : Wf[row * DD + k];
            }
            ((task == 1) ? g_w16_0 : g_w16_1)[idx] = __float2half(v);
        }
    } else if (task == 3) {
        if (idx < 2 * PERM_PER_DIR) perm_pack(Whh_l0f, Whh_l0b, g_whhp0, idx);
    } else if (task == 4) {
        if (idx < 2 * PERM_PER_DIR) perm_pack(Whh_l1f, Whh_l1b, g_whhp1, idx);
    } else {
        if (idx < DD * DD) {
            int r = idx / DD, c = idx - r * DD;
            g_w1t[c * DD + r] = W1[idx];
            g_w2t[c * DD + r] = W2[idx];
        }
    }
}

// ---------------- embedding gather -> fp16 A ------------------------------------
__global__ void k_embed16(const int* __restrict__ x, const float* __restrict__ emb) {
    int idx = blockIdx.x * blockDim.x + threadIdx.x;
    int bt = idx / 152;
    int c  = idx - bt * 152;
    int tok = x[bt];
    __half2 v = __floats2half2_rn(0.f, 0.f);
    if (c < 150 && tok != 0) {
        float2 f = reinterpret_cast<const float2*>(emb)[(size_t)tok * 150 + c];
        v = __floats2half2_rn(f.x, f.y);
    }
    reinterpret_cast<__half2*>(g_a16)[idx] = v;
}

// ---------------- input GEMM: cp.async 3-stage, 128x128x16, bias fused ----------
__device__ __forceinline__ void cp16(unsigned dst, const void* src) {
    asm volatile("cp.async.cg.shared.global [%0], [%1], 16;\n" :: "r"(dst), "l"(src));
}
__device__ __forceinline__ void cp_commit() { asm volatile("cp.async.commit_group;\n"); }
__device__ __forceinline__ void cp_wait1()  { asm volatile("cp.async.wait_group 1;\n"); }
__device__ __forceinline__ void cp_wait0()  { asm volatile("cp.async.wait_group 0;\n"); }

__device__ __forceinline__ void gemm16_body(const __half* __restrict__ A,
                                            const __half* __restrict__ Bw,
                                            const float* __restrict__ biasv,
                                            __half* __restrict__ C) {
    __shared__ __half As[3][128][24];
    __shared__ __half Bs[3][128][24];
    int tid  = threadIdx.x;
    int m0   = blockIdx.x * 128;
    int n0   = blockIdx.y * 128;
    int warp = tid >> 5, lane = tid & 31;
    int wm = warp & 3, wn = warp >> 2;
    int l4 = lane >> 2, c2 = (lane & 3) * 2;
    int row = tid >> 1, chk = (tid & 1) * 8;

    const __half* Asrc = A + (size_t)(m0 + row) * KP + chk;
    const __half* Bsrc = Bw + (size_t)(n0 + row) * KP + chk;

    float acc[2][8][4];
#pragma unroll
    for (int i = 0; i < 2; ++i)
#pragma unroll
        for (int j = 0; j < 8; ++j)
#pragma unroll
            for (int q = 0; q < 4; ++q) acc[i][j][q] = 0.f;

#pragma unroll
    for (int p = 0; p < 2; ++p) {
        unsigned da = (unsigned)__cvta_generic_to_shared(&As[p][row][chk]);
        unsigned db = (unsigned)__cvta_generic_to_shared(&Bs[p][row][chk]);
        cp16(da, Asrc + p * 16);
        cp16(db, Bsrc + p * 16);
        cp_commit();
    }

    for (int kt = 0; kt < KT16; ++kt) {
        if (kt == KT16 - 1) cp_wait0(); else cp_wait1();
        __syncthreads();
        int st = kt % 3;
        if (kt + 2 < KT16) {
            int ns = (kt + 2) % 3;
            unsigned da = (unsigned)__cvta_generic_to_shared(&As[ns][row][chk]);
            unsigned db = (unsigned)__cvta_generic_to_shared(&Bs[ns][row][chk]);
            cp16(da, Asrc + (kt + 2) * 16);
            cp16(db, Bsrc + (kt + 2) * 16);
            cp_commit();
        }

        unsigned af[2][4];
#pragma unroll
        for (int mi = 0; mi < 2; ++mi) {
            int rb = wm * 32 + mi * 16;
            af[mi][0] = *reinterpret_cast<const unsigned*>(&As[st][rb + l4][c2]);
            af[mi][1] = *reinterpret_cast<const unsigned*>(&As[st][rb + l4 + 8][c2]);
            af[mi][2] = *reinterpret_cast<const unsigned*>(&As[st][rb + l4][c2 + 8]);
            af[mi][3] = *reinterpret_cast<const unsigned*>(&As[st][rb + l4 + 8][c2 + 8]);
        }
        unsigned bf[8][2];
#pragma unroll
        for (int ni = 0; ni < 8; ++ni) {
            int nr = wn * 64 + ni * 8 + l4;
            bf[ni][0] = *reinterpret_cast<const unsigned*>(&Bs[st][nr][c2]);
            bf[ni][1] = *reinterpret_cast<const unsigned*>(&Bs[st][nr][c2 + 8]);
        }
#pragma unroll
        for (int mi = 0; mi < 2; ++mi)
#pragma unroll
            for (int ni = 0; ni < 8; ++ni)
                asm volatile(
                    "mma.sync.aligned.m16n8k16.row.col.f32.f16.f16.f32 "
                    "{%0,%1,%2,%3},{%4,%5,%6,%7},{%8,%9},{%0,%1,%2,%3};"
                    : "+f"(acc[mi][ni][0]), "+f"(acc[mi][ni][1]),
                      "+f"(acc[mi][ni][2]), "+f"(acc[mi][ni][3])
                    : "r"(af[mi][0]), "r"(af[mi][1]), "r"(af[mi][2]), "r"(af[mi][3]),
                      "r"(bf[ni][0]), "r"(bf[ni][1]));
        __syncthreads();
    }

#pragma unroll
    for (int mi = 0; mi < 2; ++mi)
#pragma unroll
        for (int ni = 0; ni < 8; ++ni) {
            int m = m0 + wm * 32 + mi * 16 + l4;
            int n = n0 + wn * 64 + ni * 8 + c2;
            if (n < N2) {
                float2 bv = *reinterpret_cast<const float2*>(&biasv[n]);
                __half2 h01 = __floats2half2_rn(acc[mi][ni][0] + bv.x, acc[mi][ni][1] + bv.y);
                __half2 h23 = __floats2half2_rn(acc[mi][ni][2] + bv.x, acc[mi][ni][3] + bv.y);
                *reinterpret_cast<__half2*>(C + (size_t)m * N2 + n)       = h01;
                *reinterpret_cast<__half2*>(C + (size_t)(m + 8) * N2 + n) = h23;
            }
        }
}

__global__ void __launch_bounds__(256) k_gemm16_l0() { gemm16_body(g_a16, g_w16_0, g_bias0, g_gates); }
__global__ void __launch_bounds__(256) k_gemm16_l1() { gemm16_body(g_a16, g_w16_1, g_bias1, g_gates); }

// ---------------- fast activations ----------------------------------------------
__device__ __forceinline__ float tanh_fast(float x) {
    float y; asm("tanh.approx.f32 %0, %1;" : "=f"(y) : "f"(x)); return y;
}
__device__ __forceinline__ float sigm_fast(float x) {
    float e; asm("ex2.approx.f32 %0, %1;" : "=f"(e) : "f"(-1.442695041f * x));
    float r; asm("rcp.approx.f32 %0, %1;" : "=f"(r) : "f"(1.f + e));
    return r;
}
__device__ __forceinline__ void store_h(float*  p, float v) { *p = v; }
__device__ __forceinline__ void store_h(__half* p, float v) { *p = __float2half(v); }

// ---------------- tensor-core persistent LSTM (1 sync/step, shuffle epilogue) ----
template <typename OutT>
__device__ __forceinline__ void lstm_mma_body(const __half* __restrict__ Gt,
                                              const __half* __restrict__ permAll,
                                              OutT* __restrict__ Hout, int ostride) {
    __shared__ __half h16[2][16][HSTR];

    int tid  = threadIdx.x;
    int dir  = blockIdx.x & 1;
    int b0   = (blockIdx.x >> 1) * 16;
    int warp = tid >> 5, lane = tid & 31;
    int l4   = lane >> 2, c2 = (lane & 3) * 2;
    int wbase = warp * 32;
    int goff = dir * G4;
    int hoff = dir * HH;
    const uint4* permLane =
        reinterpret_cast<const uint4*>(permAll + (size_t)dir * PERM_PER_DIR) +
        (warp * 32 + lane) * 20;

    // per-lane batch rows
    int LA = g_len[b0 + l4];
    int LB = g_len[b0 + l4 + 8];
    int par = lane & 1;                       // 0: owns row l4, 1: owns row l4+8
    int rowSel = par ? (l4 + 8) : l4;
    int Lsel   = par ? LB : LA;
    int jbase  = (wbase >> 2) + ((lane >> 1) & 1);   // j = jbase + 2*nt

    size_t rowAg = (size_t)(b0 + l4) * SS;
    size_t rowBg = (size_t)(b0 + l4 + 8) * SS;
    OutT* outRow = Hout + (size_t)(b0 + rowSel) * SS * ostride + hoff;

    float cst[4] = {0.f, 0.f, 0.f, 0.f};
    float hst[4] = {0.f, 0.f, 0.f, 0.f};

    for (int i = tid; i < 2 * 16 * HSTR; i += blockDim.x)
        (&h16[0][0][0])[i] = __float2half(0.f);
    __syncthreads();

    for (int s = 0; s < SS; ++s) {
        int pp = s & 1;
        int tA = (s < LA) ? (dir ? (LA - 1 - s) : s) : s;
        int tB = (s < LB) ? (dir ? (LB - 1 - s) : s) : s;

        // prefetch input-projection gates (interleaved layout)
        __half2 ga[4], gb[4];
#pragma unroll
        for (int nt = 0; nt < 4; ++nt) {
            int cA = wbase + nt * 8 + c2;
            ga[nt] = __floats2half2_rn(0.f, 0.f);
            gb[nt] = ga[nt];
            if (cA < G4) {
                ga[nt] = *reinterpret_cast<const __half2*>(&Gt[(rowAg + tA) * N2 + goff + cA]);
                gb[nt] = *reinterpret_cast<const __half2*>(&Gt[(rowBg + tB) * N2 + goff + cA]);
            }
        }

        // MMA: G[16 x 608] = h16 x Whh^T
        float acc[4][4];
#pragma unroll
        for (int nt = 0; nt < 4; ++nt)
#pragma unroll
            for (int r = 0; r < 4; ++r) acc[nt][r] = 0.f;

#pragma unroll
        for (int kt = 0; kt < RKT; ++kt) {
            int k0 = kt * 16;
            unsigned a0 = *reinterpret_cast<const unsigned*>(&h16[pp][l4][k0 + c2]);
            unsigned a1 = *reinterpret_cast<const unsigned*>(&h16[pp][l4 + 8][k0 + c2]);
            unsigned a2 = *reinterpret_cast<const unsigned*>(&h16[pp][l4][k0 + c2 + 8]);
            unsigned a3 = *reinterpret_cast<const unsigned*>(&h16[pp][l4 + 8][k0 + c2 + 8]);
            uint4 q0 = permLane[kt * 2 + 0];
            uint4 q1 = permLane[kt * 2 + 1];
            asm volatile("mma.sync.aligned.m16n8k16.row.col.f32.f16.f16.f32 "
                         "{%0,%1,%2,%3},{%4,%5,%6,%7},{%8,%9},{%0,%1,%2,%3};"
                         : "+f"(acc[0][0]), "+f"(acc[0][1]), "+f"(acc[0][2]), "+f"(acc[0][3])
                         : "r"(a0), "r"(a1), "r"(a2), "r"(a3), "r"(q0.x), "r"(q0.y));
            asm volatile("mma.sync.aligned.m16n8k16.row.col.f32.f16.f16.f32 "
                         "{%0,%1,%2,%3},{%4,%5,%6,%7},{%8,%9},{%0,%1,%2,%3};"
                         : "+f"(acc[1][0]), "+f"(acc[1][1]), "+f"(acc[1][2]), "+f"(acc[1][3])
                         : "r"(a0), "r"(a1), "r"(a2), "r"(a3), "r"(q0.z), "r"(q0.w));
            asm volatile("mma.sync.aligned.m16n8k16.row.col.f32.f16.f16.f32 "
                         "{%0,%1,%2,%3},{%4,%5,%6,%7},{%8,%9},{%0,%1,%2,%3};"
                         : "+f"(acc[2][0]), "+f"(acc[2][1]), "+f"(acc[2][2]), "+f"(acc[2][3])
                         : "r"(a0), "r"(a1), "r"(a2), "r"(a3), "r"(q1.x), "r"(q1.y));
            asm volatile("mma.sync.aligned.m16n8k16.row.col.f32.f16.f16.f32 "
                         "{%0,%1,%2,%3},{%4,%5,%6,%7},{%8,%9},{%0,%1,%2,%3};"
                         : "+f"(acc[3][0]), "+f"(acc[3][1]), "+f"(acc[3][2]), "+f"(acc[3][3])
                         : "r"(a0), "r"(a1), "r"(a2), "r"(a3), "r"(q1.z), "r"(q1.w));
        }

        // elementwise: shuffle-exchange to gather all 4 gates per cell
        int t_out = par ? tB : tA;
        bool valid = (s < Lsel);
#pragma unroll
        for (int nt = 0; nt < 4; ++nt) {
            float2 fa = __half22float2(ga[nt]);
            float2 fb = __half22float2(gb[nt]);
            float v0 = acc[nt][0] + fa.x;   // row l4,   cols c2, c2+1
            float v1 = acc[nt][1] + fa.y;
            float v2 = acc[nt][2] + fb.x;   // row l4+8
            float v3 = acc[nt][3] + fb.y;
            float s1 = par ? v0 : v2;
            float s2 = par ? v1 : v3;
            float r1 = __shfl_xor_sync(0xffffffff, s1, 1);
            float r2 = __shfl_xor_sync(0xffffffff, s2, 1);
            float gi, gf, gg, go;
            if (par) { gg = v2; go = v3; gi = r1; gf = r2; }
            else     { gi = v0; gf = v1; gg = r1; go = r2; }
            float iv = sigm_fast(gi), fv = sigm_fast(gf);
            float gv = tanh_fast(gg), ov = sigm_fast(go);
            float cn = fv * cst[nt] + iv * gv;
            float hn = ov * tanh_fast(cn);
            float hw = valid ? hn : 0.f;
            if (valid) { cst[nt] = cn; hst[nt] = hn; }
            int j = jbase + 2 * nt;
            if (j < HH) {
                h16[pp ^ 1][rowSel][j] = __float2half(hst[nt]);
                store_h(outRow + (size_t)t_out * ostride + j, hw);
            }
        }
        __syncthreads();
    }
}

__global__ void __launch_bounds__(608) k_lstm_l0() {
    lstm_mma_body<__half>(g_gates, g_whhp0, g_a16, KP);
}
__global__ void __launch_bounds__(608) k_lstm_l1() {
    lstm_mma_body<float>(g_gates, g_whhp1, g_h2, DD);
}

// ---------------- final FC layers -------------------------------------------------
__global__ void __launch_bounds__(320) k_fc1(const float* __restrict__ bias) {
    __shared__ float v[DD];
    int b = blockIdx.x, tid = threadIdx.x;
    int L = g_len[b];
    const float* src = g_h2 + ((size_t)b * SS + (L - 1)) * DD;
    if (tid < DD) v[tid] = src[tid];
    __syncthreads();
    if (tid < DD) {
        float acc = bias[tid];
        for (int k = 0; k < DD; ++k) acc += v[k] * g_w1t[k * DD + tid];
        g_tmp[b * DD + tid] = tanhf(acc);
    }
}
__global__ void __launch_bounds__(320) k_fc2(const float* __restrict__ bias,
                                             float* __restrict__ out) {
    __shared__ float v[DD];
    int b = blockIdx.x, tid = threadIdx.x;
    if (tid < DD) v[tid] = g_tmp[b * DD + tid];
    __syncthreads();
    if (tid < DD) {
        float acc = bias[tid];
        for (int k = 0; k < DD; ++k) acc += v[k] * g_w2t[k * DD + tid];
        out[b * DD + tid] = acc;
    }
}

// ---------------- host --------------------------------------------------------------
extern "C" void kernel_launch(void* const* d_in, const int* in_sizes, int n_in,
                              void* d_out, int out_size) {
    const int*   x        = (const int*)  d_in[0];
    const int*   mask     = (const int*)  d_in[1];
    const float* emb      = (const float*)d_in[2];
    const float* Wih_l0f  = (const float*)d_in[3];
    const float* Whh_l0f  = (const float*)d_in[4];
    const float* b_l0f    = (const float*)d_in[5];
    const float* Wih_l0b  = (const float*)d_in[6];
    const float* Whh_l0b  = (const float*)d_in[7];
    const float* b_l0b    = (const float*)d_in[8];
    const float* Wih_l1f  = (const float*)d_in[9];
    const float* Whh_l1f  = (const float*)d_in[10];
    const float* b_l1f    = (const float*)d_in[11];
    const float* Wih_l1b  = (const float*)d_in[12];
    const float* Whh_l1b  = (const float*)d_in[13];
    const float* b_l1b    = (const float*)d_in[14];
    const float* W1       = (const float*)d_in[15];
    const float* b1       = (const float*)d_in[16];
    const float* W2       = (const float*)d_in[17];
    const float* b2       = (const float*)d_in[18];
    float* out = (float*)d_out;

    int mask64 = (in_sizes[1] != BB * SS) ? 1 : 0;

    dim3 sgrid(1520, 6);
    k_setup<<<sgrid, 256>>>(mask, mask64,
                            Wih_l0f, Wih_l0b, Wih_l1f, Wih_l1b,
                            Whh_l0f, Whh_l0b, Whh_l1f, Whh_l1b,
                            b_l0f, b_l0b, b_l1f, b_l1b, W1, W2);

    k_embed16<<<(BB * SS * 152 + 255) / 256, 256>>>(x, emb);

    dim3 g16((BB * SS) / 128, N2P / 128);

    k_gemm16_l0<<<g16, 256>>>();
    k_lstm_l0<<<128, 608>>>();

    k_gemm16_l1<<<g16, 256>>>();
    k_lstm_l1<<<128, 608>>>();

    k_fc1<<<BB, 320>>>(b1);
    k_fc2<<<BB, 320>>>(b2, out);
}

// round 10
// speedup vs baseline: 4.7900x; 1.0182x over previous
#include <cuda_runtime.h>
#include <cuda_fp16.h>
#include <math.h>
#include <stddef.h>

#define BB 1024
#define SS 256
#define DD 300
#define HH 150
#define G4 600     // 4*H
#define N2 1200    // both directions
#define N2P 1280   // padded weight rows (guard-free GEMM loads)
#define KP 304     // input-GEMM K padded to 16
#define KT16 (KP / 16)

// recurrence tiling
#define RKT 10
#define RNW 19
#define HSTR 168
#define PERM_PER_DIR (RNW * 32 * 160)

// ---------------- device scratch ------------------------------------------------
__device__ __half g_a16  [(size_t)BB * SS * KP];
__device__ float  g_h2   [(size_t)BB * SS * DD];
__device__ __half g_gates[(size_t)BB * SS * N2];
__device__ __half g_w16_0[N2P * KP];
__device__ __half g_w16_1[N2P * KP];
__device__ __half g_whhp0[2 * PERM_PER_DIR];
__device__ __half g_whhp1[2 * PERM_PER_DIR];
__device__ float  g_bias0[N2P];                 // interleaved bias layer0 (f|b)
__device__ float  g_bias1[N2P];
__device__ float  g_w1t  [DD * DD];
__device__ float  g_w2t  [DD * DD];
__device__ float  g_tmp  [BB * DD];
__device__ int    g_len  [BB];

// gate-interleaved weight-row map: within-dir column m -> weight row
// m = 4*j + g  ->  row = g*HH + j
__device__ __forceinline__ int ilv_row(int m) { return (m & 3) * HH + (m >> 2); }

// ---------------- fused setup ----------------------------------------------------
__device__ __forceinline__ void perm_pack(const float* Wf, const float* Wb,
                                          __half* dst, int idx) {
    int dir = idx / PERM_PER_DIR;
    int rem = idx - dir * PERM_PER_DIR;
    int wl  = rem / 160;
    int r2  = rem - wl * 160;
    int w   = wl >> 5, l = wl & 31;
    int kt  = r2 >> 4;
    int r3  = r2 & 15;
    int p   = r3 >> 3;
    int r4  = r3 & 7;
    int ridx = r4 >> 1, h = r4 & 1;
    int m = w * 32 + (p * 2 + (ridx >> 1)) * 8 + (l >> 2);    // within-dir col (interleaved)
    int k = kt * 16 + (l & 3) * 2 + (ridx & 1) * 8 + h;
    float v = 0.f;
    if (m < G4 && k < HH) {
        int row = ilv_row(m);
        v = dir ? Wb[row * HH + k] : Wf[row * HH + k];
    }
    dst[idx] = __float2half(v);
}

__global__ void k_setup(const int* __restrict__ mask, int mask64,
                        const float* __restrict__ Wih_l0f, const float* __restrict__ Wih_l0b,
                        const float* __restrict__ Wih_l1f, const float* __restrict__ Wih_l1b,
                        const float* __restrict__ Whh_l0f, const float* __restrict__ Whh_l0b,
                        const float* __restrict__ Whh_l1f, const float* __restrict__ Whh_l1b,
                        const float* __restrict__ b_l0f, const float* __restrict__ b_l0b,
                        const float* __restrict__ b_l1f, const float* __restrict__ b_l1b,
                        const float* __restrict__ W1, const float* __restrict__ W2) {
    int idx = blockIdx.x * blockDim.x + threadIdx.x;
    int task = blockIdx.y;
    if (task == 0) {
        if (idx < BB) {
            int c = 0;
            if (mask64) {
                const int* m = mask + (size_t)idx * SS * 2;
                for (int t = 0; t < SS; ++t) c += ((m[2 * t] | m[2 * t + 1]) != 0);
            } else {
                const int* m = mask + (size_t)idx * SS;
                for (int t = 0; t < SS; ++t) c += (m[t] != 0);
            }
            g_len[idx] = c;
        }
        if (idx < N2P) {
            float v0 = 0.f, v1 = 0.f;
            if (idx < N2) {
                int dir = (idx >= G4);
                int m   = idx - dir * G4;
                int row = ilv_row(m);
                v0 = dir ? b_l0b[row] : b_l0f[row];
                v1 = dir ? b_l1b[row] : b_l1f[row];
            }
            g_bias0[idx] = v0;
            g_bias1[idx] = v1;
        }
    } else if (task == 1 || task == 2) {       // pack Wih interleaved fp16
        if (idx < N2P * KP) {
            int n = idx / KP, k = idx - n * KP;
            const float* Wf = (task == 1) ? Wih_l0f : Wih_l1f;
            const float* Wb = (task == 1) ? Wih_l0b : Wih_l1b;
            float v = 0.f;
            if (n < N2 && k < DD) {
                int dir = (n >= G4);
                int m   = n - dir * G4;
                int row = ilv_row(m);
                v = dir ? Wb[row * DD + k] : Wf[row * DD + k];
            }
            ((task == 1) ? g_w16_0 : g_w16_1)[idx] = __float2half(v);
        }
    } else if (task == 3) {
        if (idx < 2 * PERM_PER_DIR) perm_pack(Whh_l0f, Whh_l0b, g_whhp0, idx);
    } else if (task == 4) {
        if (idx < 2 * PERM_PER_DIR) perm_pack(Whh_l1f, Whh_l1b, g_whhp1, idx);
    } else {
        if (idx < DD * DD) {
            int r = idx / DD, c = idx - r * DD;
            g_w1t[c * DD + r] = W1[idx];
            g_w2t[c * DD + r] = W2[idx];
        }
    }
}

// ---------------- embedding gather -> fp16 A ------------------------------------
__global__ void k_embed16(const int* __restrict__ x, const float* __restrict__ emb) {
    int idx = blockIdx.x * blockDim.x + threadIdx.x;
    int bt = idx / 152;
    int c  = idx - bt * 152;
    int tok = x[bt];
    __half2 v = __floats2half2_rn(0.f, 0.f);
    if (c < 150 && tok != 0) {
        float2 f = reinterpret_cast<const float2*>(emb)[(size_t)tok * 150 + c];
        v = __floats2half2_rn(f.x, f.y);
    }
    reinterpret_cast<__half2*>(g_a16)[idx] = v;
}

// ---------------- input GEMM: cp.async 3-stage, 128x128x16, bias fused ----------
__device__ __forceinline__ void cp16(unsigned dst, const void* src) {
    asm volatile("cp.async.cg.shared.global [%0], [%1], 16;\n" :: "r"(dst), "l"(src));
}
__device__ __forceinline__ void cp_commit() { asm volatile("cp.async.commit_group;\n"); }
__device__ __forceinline__ void cp_wait1()  { asm volatile("cp.async.wait_group 1;\n"); }
__device__ __forceinline__ void cp_wait0()  { asm volatile("cp.async.wait_group 0;\n"); }

__device__ __forceinline__ void gemm16_body(const __half* __restrict__ A,
                                            const __half* __restrict__ Bw,
                                            const float* __restrict__ biasv,
                                            __half* __restrict__ C) {
    __shared__ __half As[3][128][24];
    __shared__ __half Bs[3][128][24];
    int tid  = threadIdx.x;
    int m0   = blockIdx.x * 128;
    int n0   = blockIdx.y * 128;
    int warp = tid >> 5, lane = tid & 31;
    int wm = warp & 3, wn = warp >> 2;
    int l4 = lane >> 2, c2 = (lane & 3) * 2;
    int row = tid >> 1, chk = (tid & 1) * 8;

    const __half* Asrc = A + (size_t)(m0 + row) * KP + chk;
    const __half* Bsrc = Bw + (size_t)(n0 + row) * KP + chk;

    float acc[2][8][4];
#pragma unroll
    for (int i = 0; i < 2; ++i)
#pragma unroll
        for (int j = 0; j < 8; ++j)
#pragma unroll
            for (int q = 0; q < 4; ++q) acc[i][j][q] = 0.f;

#pragma unroll
    for (int p = 0; p < 2; ++p) {
        unsigned da = (unsigned)__cvta_generic_to_shared(&As[p][row][chk]);
        unsigned db = (unsigned)__cvta_generic_to_shared(&Bs[p][row][chk]);
        cp16(da, Asrc + p * 16);
        cp16(db, Bsrc + p * 16);
        cp_commit();
    }

    for (int kt = 0; kt < KT16; ++kt) {
        if (kt == KT16 - 1) cp_wait0(); else cp_wait1();
        __syncthreads();
        int st = kt % 3;
        if (kt + 2 < KT16) {
            int ns = (kt + 2) % 3;
            unsigned da = (unsigned)__cvta_generic_to_shared(&As[ns][row][chk]);
            unsigned db = (unsigned)__cvta_generic_to_shared(&Bs[ns][row][chk]);
            cp16(da, Asrc + (kt + 2) * 16);
            cp16(db, Bsrc + (kt + 2) * 16);
            cp_commit();
        }

        unsigned af[2][4];
#pragma unroll
        for (int mi = 0; mi < 2; ++mi) {
            int rb = wm * 32 + mi * 16;
            af[mi][0] = *reinterpret_cast<const unsigned*>(&As[st][rb + l4][c2]);
            af[mi][1] = *reinterpret_cast<const unsigned*>(&As[st][rb + l4 + 8][c2]);
            af[mi][2] = *reinterpret_cast<const unsigned*>(&As[st][rb + l4][c2 + 8]);
            af[mi][3] = *reinterpret_cast<const unsigned*>(&As[st][rb + l4 + 8][c2 + 8]);
        }
        unsigned bf[8][2];
#pragma unroll
        for (int ni = 0; ni < 8; ++ni) {
            int nr = wn * 64 + ni * 8 + l4;
            bf[ni][0] = *reinterpret_cast<const unsigned*>(&Bs[st][nr][c2]);
            bf[ni][1] = *reinterpret_cast<const unsigned*>(&Bs[st][nr][c2 + 8]);
        }
#pragma unroll
        for (int mi = 0; mi < 2; ++mi)
#pragma unroll
            for (int ni = 0; ni < 8; ++ni)
                asm volatile(
                    "mma.sync.aligned.m16n8k16.row.col.f32.f16.f16.f32 "
                    "{%0,%1,%2,%3},{%4,%5,%6,%7},{%8,%9},{%0,%1,%2,%3};"
                    : "+f"(acc[mi][ni][0]), "+f"(acc[mi][ni][1]),
                      "+f"(acc[mi][ni][2]), "+f"(acc[mi][ni][3])
                    : "r"(af[mi][0]), "r"(af[mi][1]), "r"(af[mi][2]), "r"(af[mi][3]),
                      "r"(bf[ni][0]), "r"(bf[ni][1]));
        __syncthreads();
    }

#pragma unroll
    for (int mi = 0; mi < 2; ++mi)
#pragma unroll
        for (int ni = 0; ni < 8; ++ni) {
            int m = m0 + wm * 32 + mi * 16 + l4;
            int n = n0 + wn * 64 + ni * 8 + c2;
            if (n < N2) {
                float2 bv = *reinterpret_cast<const float2*>(&biasv[n]);
                __half2 h01 = __floats2half2_rn(acc[mi][ni][0] + bv.x, acc[mi][ni][1] + bv.y);
                __half2 h23 = __floats2half2_rn(acc[mi][ni][2] + bv.x, acc[mi][ni][3] + bv.y);
                *reinterpret_cast<__half2*>(C + (size_t)m * N2 + n)       = h01;
                *reinterpret_cast<__half2*>(C + (size_t)(m + 8) * N2 + n) = h23;
            }
        }
}

__global__ void __launch_bounds__(256) k_gemm16_l0() { gemm16_body(g_a16, g_w16_0, g_bias0, g_gates); }
__global__ void __launch_bounds__(256) k_gemm16_l1() { gemm16_body(g_a16, g_w16_1, g_bias1, g_gates); }

// ---------------- fast activations ----------------------------------------------
__device__ __forceinline__ float tanh_fast(float x) {
    float y; asm("tanh.approx.f32 %0, %1;" : "=f"(y) : "f"(x)); return y;
}
__device__ __forceinline__ unsigned tanh2_fast(unsigned x) {
    unsigned y; asm("tanh.approx.f16x2 %0, %1;" : "=r"(y) : "r"(x)); return y;
}
__device__ __forceinline__ void ldsm_x4(unsigned& r0, unsigned& r1,
                                        unsigned& r2, unsigned& r3, unsigned addr) {
    asm volatile("ldmatrix.sync.aligned.m8n8.x4.shared.b16 {%0,%1,%2,%3}, [%4];"
                 : "=r"(r0), "=r"(r1), "=r"(r2), "=r"(r3) : "r"(addr));
}
__device__ __forceinline__ void store_h(float*  p, float v) { *p = v; }
__device__ __forceinline__ void store_h(__half* p, float v) { *p = __float2half(v); }

// ---------------- tensor-core persistent LSTM ------------------------------------
// 128 blocks (dir = bx&1, group -> 16 batch rows), 608 threads = 19 warps.
// 1 sync/step; ldmatrix A-frags; f16x2 tanh activations; gates double-buffered.
template <typename OutT>
__device__ __forceinline__ void lstm_mma_body(const __half* __restrict__ Gt,
                                              const __half* __restrict__ permAll,
                                              OutT* __restrict__ Hout, int ostride) {
    __shared__ __align__(16) __half h16[2][16][HSTR];

    int tid  = threadIdx.x;
    int dir  = blockIdx.x & 1;
    int b0   = (blockIdx.x >> 1) * 16;
    int warp = tid >> 5, lane = tid & 31;
    int l4   = lane >> 2, c2 = (lane & 3) * 2;
    int wbase = warp * 32;
    int goff = dir * G4;
    int hoff = dir * HH;
    const uint4* permLane =
        reinterpret_cast<const uint4*>(permAll + (size_t)dir * PERM_PER_DIR) +
        (warp * 32 + lane) * 20;

    // ldmatrix lane source: mat = lane>>3; row = (mat&1)*8 + (lane&7); col = (mat>>1)*8
    int rowL = ((lane >> 3) & 1) * 8 + (lane & 7);
    int colL = (lane >> 4) * 8;
    unsigned aBase = (unsigned)__cvta_generic_to_shared(&h16[0][rowL][colL]);
    const unsigned ppStride = 16 * HSTR * 2;   // bytes

    // per-lane batch rows
    int LA = g_len[b0 + l4];
    int LB = g_len[b0 + l4 + 8];
    int par = lane & 1;                       // 0: owns row l4, 1: owns row l4+8
    int rowSel = par ? (l4 + 8) : l4;
    int Lsel   = par ? LB : LA;
    int jbase  = (wbase >> 2) + ((lane >> 1) & 1);   // j = jbase + 2*nt

    size_t rowAg = (size_t)(b0 + l4) * SS;
    size_t rowBg = (size_t)(b0 + l4 + 8) * SS;
    OutT* outRow = Hout + (size_t)(b0 + rowSel) * SS * ostride + hoff;

    const __half2 sc_if = __floats2half2_rn(0.5f, 0.5f);
    const __half2 sc_go = __floats2half2_rn(1.0f, 0.5f);

    float cst[4] = {0.f, 0.f, 0.f, 0.f};
    float hst[4] = {0.f, 0.f, 0.f, 0.f};

    for (int i = tid; i < 2 * 16 * HSTR; i += blockDim.x)
        (&h16[0][0][0])[i] = __float2half(0.f);

    // prologue: load gates for step 0
    __half2 gaC[4], gbC[4];
    {
        int tA0 = (0 < LA) ? (dir ? (LA - 1) : 0) : 0;
        int tB0 = (0 < LB) ? (dir ? (LB - 1) : 0) : 0;
#pragma unroll
        for (int nt = 0; nt < 4; ++nt) {
            int cA = wbase + nt * 8 + c2;
            gaC[nt] = __floats2half2_rn(0.f, 0.f);
            gbC[nt] = gaC[nt];
            if (cA < G4) {
                gaC[nt] = *reinterpret_cast<const __half2*>(&Gt[(rowAg + tA0) * N2 + goff + cA]);
                gbC[nt] = *reinterpret_cast<const __half2*>(&Gt[(rowBg + tB0) * N2 + goff + cA]);
            }
        }
    }
    __syncthreads();

    for (int s = 0; s < SS; ++s) {
        int pp = s & 1;

        // prefetch gates for step s+1 (hidden behind the whole step)
        __half2 gaN[4], gbN[4];
        {
            int s1 = s + 1;
            int tA1 = (s1 < LA) ? (dir ? (LA - 1 - s1) : s1) : ((s1 < SS) ? s1 : 0);
            int tB1 = (s1 < LB) ? (dir ? (LB - 1 - s1) : s1) : ((s1 < SS) ? s1 : 0);
#pragma unroll
            for (int nt = 0; nt < 4; ++nt) {
                int cA = wbase + nt * 8 + c2;
                gaN[nt] = __floats2half2_rn(0.f, 0.f);
                gbN[nt] = gaN[nt];
                if (cA < G4) {
                    gaN[nt] = *reinterpret_cast<const __half2*>(&Gt[(rowAg + tA1) * N2 + goff + cA]);
                    gbN[nt] = *reinterpret_cast<const __half2*>(&Gt[(rowBg + tB1) * N2 + goff + cA]);
                }
            }
        }

        // MMA: G[16 x 608] = h16 x Whh^T  (ldmatrix A fragments)
        float acc[4][4];
#pragma unroll
        for (int nt = 0; nt < 4; ++nt)
#pragma unroll
            for (int r = 0; r < 4; ++r) acc[nt][r] = 0.f;

        unsigned aAddr = aBase + (unsigned)pp * ppStride;
#pragma unroll
        for (int kt = 0; kt < RKT; ++kt) {
            unsigned a0, a1, a2, a3;
            ldsm_x4(a0, a1, a2, a3, aAddr + kt * 32);
            uint4 q0 = permLane[kt * 2 + 0];
            uint4 q1 = permLane[kt * 2 + 1];
            asm volatile("mma.sync.aligned.m16n8k16.row.col.f32.f16.f16.f32 "
                         "{%0,%1,%2,%3},{%4,%5,%6,%7},{%8,%9},{%0,%1,%2,%3};"
                         : "+f"(acc[0][0]), "+f"(acc[0][1]), "+f"(acc[0][2]), "+f"(acc[0][3])
                         : "r"(a0), "r"(a1), "r"(a2), "r"(a3), "r"(q0.x), "r"(q0.y));
            asm volatile("mma.sync.aligned.m16n8k16.row.col.f32.f16.f16.f32 "
                         "{%0,%1,%2,%3},{%4,%5,%6,%7},{%8,%9},{%0,%1,%2,%3};"
                         : "+f"(acc[1][0]), "+f"(acc[1][1]), "+f"(acc[1][2]), "+f"(acc[1][3])
                         : "r"(a0), "r"(a1), "r"(a2), "r"(a3), "r"(q0.z), "r"(q0.w));
            asm volatile("mma.sync.aligned.m16n8k16.row.col.f32.f16.f16.f32 "
                         "{%0,%1,%2,%3},{%4,%5,%6,%7},{%8,%9},{%0,%1,%2,%3};"
                         : "+f"(acc[2][0]), "+f"(acc[2][1]), "+f"(acc[2][2]), "+f"(acc[2][3])
                         : "r"(a0), "r"(a1), "r"(a2), "r"(a3), "r"(q1.x), "r"(q1.y));
            asm volatile("mma.sync.aligned.m16n8k16.row.col.f32.f16.f16.f32 "
                         "{%0,%1,%2,%3},{%4,%5,%6,%7},{%8,%9},{%0,%1,%2,%3};"
                         : "+f"(acc[3][0]), "+f"(acc[3][1]), "+f"(acc[3][2]), "+f"(acc[3][3])
                         : "r"(a0), "r"(a1), "r"(a2), "r"(a3), "r"(q1.z), "r"(q1.w));
        }

        // elementwise: packed shuffle exchange + f16x2 tanh activations
        int tA = (s < LA) ? (dir ? (LA - 1 - s) : s) : s;
        int tB = (s < LB) ? (dir ? (LB - 1 - s) : s) : s;
        int t_out = par ? tB : tA;
        bool valid = (s < Lsel);
#pragma unroll
        for (int nt = 0; nt < 4; ++nt) {
            float2 fa = __half22float2(gaC[nt]);
            float2 fb = __half22float2(gbC[nt]);
            float v0 = acc[nt][0] + fa.x;   // row l4,   gates per parity
            float v1 = acc[nt][1] + fa.y;
            float v2 = acc[nt][2] + fb.x;   // row l4+8
            float v3 = acc[nt][3] + fb.y;
            // exchange the half that belongs to the partner's row
            float sx = par ? v0 : v2;
            float sy = par ? v1 : v3;
            __half2 snd = __floats2half2_rn(sx, sy);
            unsigned rcvu = __shfl_xor_sync(0xffffffff, *reinterpret_cast<unsigned*>(&snd), 1);
            __half2 rh = *reinterpret_cast<__half2*>(&rcvu);
            // par0 own = (i,f); par1 own = (g,o)
            float px = par ? v2        : v0 * 0.5f;
            float py = par ? v3 * 0.5f : v1 * 0.5f;
            __half2 own2 = __floats2half2_rn(px, py);
            __half2 rsc  = __hmul2(rh, par ? sc_if : sc_go);
            __half2 hif = par ? rsc  : own2;   // (i/2, f/2)
            __half2 hgo = par ? own2 : rsc;    // (g, o/2)
            unsigned t1 = tanh2_fast(*reinterpret_cast<unsigned*>(&hif));
            unsigned t2 = tanh2_fast(*reinterpret_cast<unsigned*>(&hgo));
            float2 f1 = __half22float2(*reinterpret_cast<__half2*>(&t1));
            float2 f2 = __half22float2(*reinterpret_cast<__half2*>(&t2));
            float iv = 0.5f * f1.x + 0.5f;
            float fv = 0.5f * f1.y + 0.5f;
            float gv = f2.x;
            float ov = 0.5f * f2.y + 0.5f;
            float cn = fv * cst[nt] + iv * gv;
            float hn = ov * tanh_fast(cn);
            float hw = valid ? hn : 0.f;
            if (valid) { cst[nt] = cn; hst[nt] = hn; }
            int j = jbase + 2 * nt;
            if (j < HH) {
                h16[pp ^ 1][rowSel][j] = __float2half(hst[nt]);
                store_h(outRow + (size_t)t_out * ostride + j, hw);
            }
        }
#pragma unroll
        for (int nt = 0; nt < 4; ++nt) { gaC[nt] = gaN[nt]; gbC[nt] = gbN[nt]; }
        __syncthreads();
    }
}

__global__ void __launch_bounds__(608) k_lstm_l0() {
    lstm_mma_body<__half>(g_gates, g_whhp0, g_a16, KP);
}
__global__ void __launch_bounds__(608) k_lstm_l1() {
    lstm_mma_body<float>(g_gates, g_whhp1, g_h2, DD);
}

// ---------------- final FC layers -------------------------------------------------
__global__ void __launch_bounds__(320) k_fc1(const float* __restrict__ bias) {
    __shared__ float v[DD];
    int b = blockIdx.x, tid = threadIdx.x;
    int L = g_len[b];
    const float* src = g_h2 + ((size_t)b * SS + (L - 1)) * DD;
    if (tid < DD) v[tid] = src[tid];
    __syncthreads();
    if (tid < DD) {
        float acc = bias[tid];
        for (int k = 0; k < DD; ++k) acc += v[k] * g_w1t[k * DD + tid];
        g_tmp[b * DD + tid] = tanhf(acc);
    }
}
__global__ void __launch_bounds__(320) k_fc2(const float* __restrict__ bias,
                                             float* __restrict__ out) {
    __shared__ float v[DD];
    int b = blockIdx.x, tid = threadIdx.x;
    if (tid < DD) v[tid] = g_tmp[b * DD + tid];
    __syncthreads();
    if (tid < DD) {
        float acc = bias[tid];
        for (int k = 0; k < DD; ++k) acc += v[k] * g_w2t[k * DD + tid];
        out[b * DD + tid] = acc;
    }
}

// ---------------- host --------------------------------------------------------------
extern "C" void kernel_launch(void* const* d_in, const int* in_sizes, int n_in,
                              void* d_out, int out_size) {
    const int*   x        = (const int*)  d_in[0];
    const int*   mask     = (const int*)  d_in[1];
    const float* emb      = (const float*)d_in[2];
    const float* Wih_l0f  = (const float*)d_in[3];
    const float* Whh_l0f  = (const float*)d_in[4];
    const float* b_l0f    = (const float*)d_in[5];
    const float* Wih_l0b  = (const float*)d_in[6];
    const float* Whh_l0b  = (const float*)d_in[7];
    const float* b_l0b    = (const float*)d_in[8];
    const float* Wih_l1f  = (const float*)d_in[9];
    const float* Whh_l1f  = (const float*)d_in[10];
    const float* b_l1f    = (const float*)d_in[11];
    const float* Wih_l1b  = (const float*)d_in[12];
    const float* Whh_l1b  = (const float*)d_in[13];
    const float* b_l1b    = (const float*)d_in[14];
    const float* W1       = (const float*)d_in[15];
    const float* b1       = (const float*)d_in[16];
    const float* W2       = (const float*)d_in[17];
    const float* b2       = (const float*)d_in[18];
    float* out = (float*)d_out;

    int mask64 = (in_sizes[1] != BB * SS) ? 1 : 0;

    dim3 sgrid(1520, 6);
    k_setup<<<sgrid, 256>>>(mask, mask64,
                            Wih_l0f, Wih_l0b, Wih_l1f, Wih_l1b,
                            Whh_l0f, Whh_l0b, Whh_l1f, Whh_l1b,
                            b_l0f, b_l0b, b_l1f, b_l1b, W1, W2);

    k_embed16<<<(BB * SS * 152 + 255) / 256, 256>>>(x, emb);

    dim3 g16((BB * SS) / 128, N2P / 128);

    k_gemm16_l0<<<g16, 256>>>();
    k_lstm_l0<<<128, 608>>>();

    k_gemm16_l1<<<g16, 256>>>();
    k_lstm_l1<<<128, 608>>>();

    k_fc1<<<BB, 320>>>(b1);
    k_fc2<<<BB, 320>>>(b2, out);
}

// round 11
// speedup vs baseline: 4.9755x; 1.0387x over previous
#include <cuda_runtime.h>
#include <cuda_fp16.h>
#include <math.h>
#include <stddef.h>

#define BB 1024
#define SS 256
#define DD 300
#define HH 150
#define G4 600     // 4*H
#define N2 1200    // both directions
#define N2P 1280   // padded weight rows (guard-free GEMM loads)
#define KP 304     // input-GEMM K padded to 16
#define KT16 (KP / 16)

// recurrence tiling
#define RKT 10
#define RNW 19
#define HSTR 168
#define PERM_PER_DIR (RNW * 32 * 160)

// ---------------- device scratch ------------------------------------------------
__device__ __half g_a16  [(size_t)BB * SS * KP];
__device__ float  g_h2   [(size_t)BB * SS * DD];
__device__ __half g_gates[(size_t)BB * SS * N2];
__device__ __half g_w16_0[N2P * KP];
__device__ __half g_w16_1[N2P * KP];
__device__ __half g_whhp0[2 * PERM_PER_DIR];
__device__ __half g_whhp1[2 * PERM_PER_DIR];
__device__ float  g_bias0[N2P];                 // interleaved bias layer0 (f|b)
__device__ float  g_bias1[N2P];
__device__ float  g_w1t  [DD * DD];
__device__ float  g_w2t  [DD * DD];
__device__ float  g_tmp  [BB * DD];
__device__ int    g_len  [BB];

// gate-interleaved weight-row map: within-dir column m -> weight row
// m = 4*j + g  ->  row = g*HH + j
__device__ __forceinline__ int ilv_row(int m) { return (m & 3) * HH + (m >> 2); }

// ---------------- fused setup ----------------------------------------------------
__device__ __forceinline__ void perm_pack(const float* Wf, const float* Wb,
                                          __half* dst, int idx) {
    int dir = idx / PERM_PER_DIR;
    int rem = idx - dir * PERM_PER_DIR;
    int wl  = rem / 160;
    int r2  = rem - wl * 160;
    int w   = wl >> 5, l = wl & 31;
    int kt  = r2 >> 4;
    int r3  = r2 & 15;
    int p   = r3 >> 3;
    int r4  = r3 & 7;
    int ridx = r4 >> 1, h = r4 & 1;
    int m = w * 32 + (p * 2 + (ridx >> 1)) * 8 + (l >> 2);    // within-dir col (interleaved)
    int k = kt * 16 + (l & 3) * 2 + (ridx & 1) * 8 + h;
    float v = 0.f;
    if (m < G4 && k < HH) {
        int row = ilv_row(m);
        v = dir ? Wb[row * HH + k] : Wf[row * HH + k];
    }
    dst[idx] = __float2half(v);
}

__global__ void k_setup(const int* __restrict__ mask, int mask64,
                        const float* __restrict__ Wih_l0f, const float* __restrict__ Wih_l0b,
                        const float* __restrict__ Wih_l1f, const float* __restrict__ Wih_l1b,
                        const float* __restrict__ Whh_l0f, const float* __restrict__ Whh_l0b,
                        const float* __restrict__ Whh_l1f, const float* __restrict__ Whh_l1b,
                        const float* __restrict__ b_l0f, const float* __restrict__ b_l0b,
                        const float* __restrict__ b_l1f, const float* __restrict__ b_l1b,
                        const float* __restrict__ W1, const float* __restrict__ W2) {
    int idx = blockIdx.x * blockDim.x + threadIdx.x;
    int task = blockIdx.y;
    if (task == 0) {
        if (idx < BB) {
            int c = 0;
            if (mask64) {
                const int* m = mask + (size_t)idx * SS * 2;
                for (int t = 0; t < SS; ++t) c += ((m[2 * t] | m[2 * t + 1]) != 0);
            } else {
                const int* m = mask + (size_t)idx * SS;
                for (int t = 0; t < SS; ++t) c += (m[t] != 0);
            }
            g_len[idx] = c;
        }
        if (idx < N2P) {
            float v0 = 0.f, v1 = 0.f;
            if (idx < N2) {
                int dir = (idx >= G4);
                int m   = idx - dir * G4;
                int row = ilv_row(m);
                v0 = dir ? b_l0b[row] : b_l0f[row];
                v1 = dir ? b_l1b[row] : b_l1f[row];
            }
            g_bias0[idx] = v0;
            g_bias1[idx] = v1;
        }
    } else if (task == 1 || task == 2) {       // pack Wih interleaved fp16
        if (idx < N2P * KP) {
            int n = idx / KP, k = idx - n * KP;
            const float* Wf = (task == 1) ? Wih_l0f : Wih_l1f;
            const float* Wb = (task == 1) ? Wih_l0b : Wih_l1b;
            float v = 0.f;
            if (n < N2 && k < DD) {
                int dir = (n >= G4);
                int m   = n - dir * G4;
                int row = ilv_row(m);
                v = dir ? Wb[row * DD + k] : Wf[row * DD + k];
            }
            ((task == 1) ? g_w16_0 : g_w16_1)[idx] = __float2half(v);
        }
    } else if (task == 3) {
        if (idx < 2 * PERM_PER_DIR) perm_pack(Whh_l0f, Whh_l0b, g_whhp0, idx);
    } else if (task == 4) {
        if (idx < 2 * PERM_PER_DIR) perm_pack(Whh_l1f, Whh_l1b, g_whhp1, idx);
    } else {
        if (idx < DD * DD) {
            int r = idx / DD, c = idx - r * DD;
            g_w1t[c * DD + r] = W1[idx];
            g_w2t[c * DD + r] = W2[idx];
        }
    }
}

// ---------------- embedding gather -> fp16 A ------------------------------------
__global__ void k_embed16(const int* __restrict__ x, const float* __restrict__ emb) {
    int idx = blockIdx.x * blockDim.x + threadIdx.x;
    int bt = idx / 152;
    int c  = idx - bt * 152;
    int tok = x[bt];
    __half2 v = __floats2half2_rn(0.f, 0.f);
    if (c < 150 && tok != 0) {
        float2 f = reinterpret_cast<const float2*>(emb)[(size_t)tok * 150 + c];
        v = __floats2half2_rn(f.x, f.y);
    }
    reinterpret_cast<__half2*>(g_a16)[idx] = v;
}

// ---------------- input GEMM: cp.async 3-stage, 128x128x16, bias fused ----------
__device__ __forceinline__ void cp16(unsigned dst, const void* src) {
    asm volatile("cp.async.cg.shared.global [%0], [%1], 16;\n" :: "r"(dst), "l"(src));
}
__device__ __forceinline__ void cp_commit() { asm volatile("cp.async.commit_group;\n"); }
__device__ __forceinline__ void cp_wait1()  { asm volatile("cp.async.wait_group 1;\n"); }
__device__ __forceinline__ void cp_wait0()  { asm volatile("cp.async.wait_group 0;\n"); }

__device__ __forceinline__ void gemm16_body(const __half* __restrict__ A,
                                            const __half* __restrict__ Bw,
                                            const float* __restrict__ biasv,
                                            __half* __restrict__ C) {
    __shared__ __half As[3][128][24];
    __shared__ __half Bs[3][128][24];
    int tid  = threadIdx.x;
    int m0   = blockIdx.x * 128;
    int n0   = blockIdx.y * 128;
    int warp = tid >> 5, lane = tid & 31;
    int wm = warp & 3, wn = warp >> 2;
    int l4 = lane >> 2, c2 = (lane & 3) * 2;
    int row = tid >> 1, chk = (tid & 1) * 8;

    const __half* Asrc = A + (size_t)(m0 + row) * KP + chk;
    const __half* Bsrc = Bw + (size_t)(n0 + row) * KP + chk;

    float acc[2][8][4];
#pragma unroll
    for (int i = 0; i < 2; ++i)
#pragma unroll
        for (int j = 0; j < 8; ++j)
#pragma unroll
            for (int q = 0; q < 4; ++q) acc[i][j][q] = 0.f;

#pragma unroll
    for (int p = 0; p < 2; ++p) {
        unsigned da = (unsigned)__cvta_generic_to_shared(&As[p][row][chk]);
        unsigned db = (unsigned)__cvta_generic_to_shared(&Bs[p][row][chk]);
        cp16(da, Asrc + p * 16);
        cp16(db, Bsrc + p * 16);
        cp_commit();
    }

    for (int kt = 0; kt < KT16; ++kt) {
        if (kt == KT16 - 1) cp_wait0(); else cp_wait1();
        __syncthreads();
        int st = kt % 3;
        if (kt + 2 < KT16) {
            int ns = (kt + 2) % 3;
            unsigned da = (unsigned)__cvta_generic_to_shared(&As[ns][row][chk]);
            unsigned db = (unsigned)__cvta_generic_to_shared(&Bs[ns][row][chk]);
            cp16(da, Asrc + (kt + 2) * 16);
            cp16(db, Bsrc + (kt + 2) * 16);
            cp_commit();
        }

        unsigned af[2][4];
#pragma unroll
        for (int mi = 0; mi < 2; ++mi) {
            int rb = wm * 32 + mi * 16;
            af[mi][0] = *reinterpret_cast<const unsigned*>(&As[st][rb + l4][c2]);
            af[mi][1] = *reinterpret_cast<const unsigned*>(&As[st][rb + l4 + 8][c2]);
            af[mi][2] = *reinterpret_cast<const unsigned*>(&As[st][rb + l4][c2 + 8]);
            af[mi][3] = *reinterpret_cast<const unsigned*>(&As[st][rb + l4 + 8][c2 + 8]);
        }
        unsigned bf[8][2];
#pragma unroll
        for (int ni = 0; ni < 8; ++ni) {
            int nr = wn * 64 + ni * 8 + l4;
            bf[ni][0] = *reinterpret_cast<const unsigned*>(&Bs[st][nr][c2]);
            bf[ni][1] = *reinterpret_cast<const unsigned*>(&Bs[st][nr][c2 + 8]);
        }
#pragma unroll
        for (int mi = 0; mi < 2; ++mi)
#pragma unroll
            for (int ni = 0; ni < 8; ++ni)
                asm volatile(
                    "mma.sync.aligned.m16n8k16.row.col.f32.f16.f16.f32 "
                    "{%0,%1,%2,%3},{%4,%5,%6,%7},{%8,%9},{%0,%1,%2,%3};"
                    : "+f"(acc[mi][ni][0]), "+f"(acc[mi][ni][1]),
                      "+f"(acc[mi][ni][2]), "+f"(acc[mi][ni][3])
                    : "r"(af[mi][0]), "r"(af[mi][1]), "r"(af[mi][2]), "r"(af[mi][3]),
                      "r"(bf[ni][0]), "r"(bf[ni][1]));
        __syncthreads();
    }

#pragma unroll
    for (int mi = 0; mi < 2; ++mi)
#pragma unroll
        for (int ni = 0; ni < 8; ++ni) {
            int m = m0 + wm * 32 + mi * 16 + l4;
            int n = n0 + wn * 64 + ni * 8 + c2;
            if (n < N2) {
                float2 bv = *reinterpret_cast<const float2*>(&biasv[n]);
                __half2 h01 = __floats2half2_rn(acc[mi][ni][0] + bv.x, acc[mi][ni][1] + bv.y);
                __half2 h23 = __floats2half2_rn(acc[mi][ni][2] + bv.x, acc[mi][ni][3] + bv.y);
                *reinterpret_cast<__half2*>(C + (size_t)m * N2 + n)       = h01;
                *reinterpret_cast<__half2*>(C + (size_t)(m + 8) * N2 + n) = h23;
            }
        }
}

__global__ void __launch_bounds__(256) k_gemm16_l0() { gemm16_body(g_a16, g_w16_0, g_bias0, g_gates); }
__global__ void __launch_bounds__(256) k_gemm16_l1() { gemm16_body(g_a16, g_w16_1, g_bias1, g_gates); }

// ---------------- fast activations ----------------------------------------------
__device__ __forceinline__ float tanh_fast(float x) {
    float y; asm("tanh.approx.f32 %0, %1;" : "=f"(y) : "f"(x)); return y;
}
__device__ __forceinline__ unsigned tanh2_fast(unsigned x) {
    unsigned y; asm("tanh.approx.f16x2 %0, %1;" : "=r"(y) : "r"(x)); return y;
}
__device__ __forceinline__ void ldsm_x4(unsigned& r0, unsigned& r1,
                                        unsigned& r2, unsigned& r3, unsigned addr) {
    asm volatile("ldmatrix.sync.aligned.m8n8.x4.shared.b16 {%0,%1,%2,%3}, [%4];"
                 : "=r"(r0), "=r"(r1), "=r"(r2), "=r"(r3) : "r"(addr));
}

// ---------------- tensor-core persistent LSTM ------------------------------------
// 128 blocks (dir = bx&1, group -> 16 batch rows), 608 threads = 19 warps.
// 1 sync/step; ldmatrix A frags; f16x2 tanh; coherent per-row output writing.
template <typename OutT>
__device__ __forceinline__ void lstm_mma_body(const __half* __restrict__ Gt,
                                              const __half* __restrict__ permAll,
                                              OutT* __restrict__ Hout, int ostride) {
    __shared__ __align__(16) __half h16[2][16][HSTR];
    __shared__ __align__(16) float  outFS[2][16][152];   // used only for fp32 output

    int tid  = threadIdx.x;
    int dir  = blockIdx.x & 1;
    int b0   = (blockIdx.x >> 1) * 16;
    int warp = tid >> 5, lane = tid & 31;
    int l4   = lane >> 2, c2 = (lane & 3) * 2;
    int wbase = warp * 32;
    int goff = dir * G4;
    int hoff = dir * HH;
    const uint4* permLane =
        reinterpret_cast<const uint4*>(permAll + (size_t)dir * PERM_PER_DIR) +
        (warp * 32 + lane) * 20;

    // ldmatrix lane source
    int rowL = ((lane >> 3) & 1) * 8 + (lane & 7);
    int colL = (lane >> 4) * 8;
    unsigned aBase = (unsigned)__cvta_generic_to_shared(&h16[0][rowL][colL]);
    const unsigned ppStride = 16 * HSTR * 2;   // bytes

    // per-lane batch rows
    int LA = g_len[b0 + l4];
    int LB = g_len[b0 + l4 + 8];
    int par = lane & 1;
    int rowSel = par ? (l4 + 8) : l4;
    int Lsel   = par ? LB : LA;
    int jbase  = (wbase >> 2) + ((lane >> 1) & 1);

    size_t rowAg = (size_t)(b0 + l4) * SS;
    size_t rowBg = (size_t)(b0 + l4 + 8) * SS;

    // writer-warp row assignment (warps 0..15 each own one batch row)
    int Lw = (warp < 16) ? g_len[b0 + warp] : 0;
    OutT* wrRow = Hout + (size_t)(b0 + (warp < 16 ? warp : 0)) * SS * ostride + hoff;

    const __half2 sc_if = __floats2half2_rn(0.5f, 0.5f);
    const __half2 sc_go = __floats2half2_rn(1.0f, 0.5f);

    float cst[4] = {0.f, 0.f, 0.f, 0.f};
    float hst[4] = {0.f, 0.f, 0.f, 0.f};

    for (int i = tid; i < 2 * 16 * HSTR; i += blockDim.x)
        (&h16[0][0][0])[i] = __float2half(0.f);

    // prologue: load gates for step 0
    __half2 gaC[4], gbC[4];
    {
        int tA0 = (0 < LA) ? (dir ? (LA - 1) : 0) : 0;
        int tB0 = (0 < LB) ? (dir ? (LB - 1) : 0) : 0;
#pragma unroll
        for (int nt = 0; nt < 4; ++nt) {
            int cA = wbase + nt * 8 + c2;
            gaC[nt] = __floats2half2_rn(0.f, 0.f);
            gbC[nt] = gaC[nt];
            if (cA < G4) {
                gaC[nt] = *reinterpret_cast<const __half2*>(&Gt[(rowAg + tA0) * N2 + goff + cA]);
                gbC[nt] = *reinterpret_cast<const __half2*>(&Gt[(rowBg + tB0) * N2 + goff + cA]);
            }
        }
    }
    __syncthreads();

    for (int s = 0; s < SS; ++s) {
        int pp = s & 1;

        // prefetch gates for step s+1
        __half2 gaN[4], gbN[4];
        {
            int s1 = s + 1;
            int tA1 = (s1 < LA) ? (dir ? (LA - 1 - s1) : s1) : ((s1 < SS) ? s1 : 0);
            int tB1 = (s1 < LB) ? (dir ? (LB - 1 - s1) : s1) : ((s1 < SS) ? s1 : 0);
#pragma unroll
            for (int nt = 0; nt < 4; ++nt) {
                int cA = wbase + nt * 8 + c2;
                gaN[nt] = __floats2half2_rn(0.f, 0.f);
                gbN[nt] = gaN[nt];
                if (cA < G4) {
                    gaN[nt] = *reinterpret_cast<const __half2*>(&Gt[(rowAg + tA1) * N2 + goff + cA]);
                    gbN[nt] = *reinterpret_cast<const __half2*>(&Gt[(rowBg + tB1) * N2 + goff + cA]);
                }
            }
        }

        // MMA: G[16 x 608] = h16 x Whh^T
        float acc[4][4];
#pragma unroll
        for (int nt = 0; nt < 4; ++nt)
#pragma unroll
            for (int r = 0; r < 4; ++r) acc[nt][r] = 0.f;

        unsigned aAddr = aBase + (unsigned)pp * ppStride;
#pragma unroll
        for (int kt = 0; kt < RKT; ++kt) {
            unsigned a0, a1, a2, a3;
            ldsm_x4(a0, a1, a2, a3, aAddr + kt * 32);
            uint4 q0 = permLane[kt * 2 + 0];
            uint4 q1 = permLane[kt * 2 + 1];
            asm volatile("mma.sync.aligned.m16n8k16.row.col.f32.f16.f16.f32 "
                         "{%0,%1,%2,%3},{%4,%5,%6,%7},{%8,%9},{%0,%1,%2,%3};"
                         : "+f"(acc[0][0]), "+f"(acc[0][1]), "+f"(acc[0][2]), "+f"(acc[0][3])
                         : "r"(a0), "r"(a1), "r"(a2), "r"(a3), "r"(q0.x), "r"(q0.y));
            asm volatile("mma.sync.aligned.m16n8k16.row.col.f32.f16.f16.f32 "
                         "{%0,%1,%2,%3},{%4,%5,%6,%7},{%8,%9},{%0,%1,%2,%3};"
                         : "+f"(acc[1][0]), "+f"(acc[1][1]), "+f"(acc[1][2]), "+f"(acc[1][3])
                         : "r"(a0), "r"(a1), "r"(a2), "r"(a3), "r"(q0.z), "r"(q0.w));
            asm volatile("mma.sync.aligned.m16n8k16.row.col.f32.f16.f16.f32 "
                         "{%0,%1,%2,%3},{%4,%5,%6,%7},{%8,%9},{%0,%1,%2,%3};"
                         : "+f"(acc[2][0]), "+f"(acc[2][1]), "+f"(acc[2][2]), "+f"(acc[2][3])
                         : "r"(a0), "r"(a1), "r"(a2), "r"(a3), "r"(q1.x), "r"(q1.y));
            asm volatile("mma.sync.aligned.m16n8k16.row.col.f32.f16.f16.f32 "
                         "{%0,%1,%2,%3},{%4,%5,%6,%7},{%8,%9},{%0,%1,%2,%3};"
                         : "+f"(acc[3][0]), "+f"(acc[3][1]), "+f"(acc[3][2]), "+f"(acc[3][3])
                         : "r"(a0), "r"(a1), "r"(a2), "r"(a3), "r"(q1.z), "r"(q1.w));
        }

        // elementwise: packed shuffle exchange + f16x2 tanh activations
        bool valid = (s < Lsel);
#pragma unroll
        for (int nt = 0; nt < 4; ++nt) {
            float2 fa = __half22float2(gaC[nt]);
            float2 fb = __half22float2(gbC[nt]);
            float v0 = acc[nt][0] + fa.x;
            float v1 = acc[nt][1] + fa.y;
            float v2 = acc[nt][2] + fb.x;
            float v3 = acc[nt][3] + fb.y;
            float sx = par ? v0 : v2;
            float sy = par ? v1 : v3;
            __half2 snd = __floats2half2_rn(sx, sy);
            unsigned rcvu = __shfl_xor_sync(0xffffffff, *reinterpret_cast<unsigned*>(&snd), 1);
            __half2 rh = *reinterpret_cast<__half2*>(&rcvu);
            float px = par ? v2        : v0 * 0.5f;
            float py = par ? v3 * 0.5f : v1 * 0.5f;
            __half2 own2 = __floats2half2_rn(px, py);
            __half2 rsc  = __hmul2(rh, par ? sc_if : sc_go);
            __half2 hif = par ? rsc  : own2;   // (i/2, f/2)
            __half2 hgo = par ? own2 : rsc;    // (g, o/2)
            unsigned t1 = tanh2_fast(*reinterpret_cast<unsigned*>(&hif));
            unsigned t2 = tanh2_fast(*reinterpret_cast<unsigned*>(&hgo));
            float2 f1 = __half22float2(*reinterpret_cast<__half2*>(&t1));
            float2 f2 = __half22float2(*reinterpret_cast<__half2*>(&t2));
            float iv = 0.5f * f1.x + 0.5f;
            float fv = 0.5f * f1.y + 0.5f;
            float gv = f2.x;
            float ov = 0.5f * f2.y + 0.5f;
            float cn = fv * cst[nt] + iv * gv;
            float hn = ov * tanh_fast(cn);
            if (valid) { cst[nt] = cn; hst[nt] = hn; }
            int j = jbase + 2 * nt;
            if (j < HH) {
                h16[pp ^ 1][rowSel][j] = __float2half(hst[nt]);
                if (sizeof(OutT) == 4)
                    outFS[pp][rowSel][j] = valid ? hn : 0.f;
            }
        }
#pragma unroll
        for (int nt = 0; nt < 4; ++nt) { gaC[nt] = gaN[nt]; gbC[nt] = gbN[nt]; }
        __syncthreads();

        // coherent output writing: warps 0..15 each write one batch row
        if (warp < 16) {
            bool v = (s < Lw);
            int t = v ? (dir ? (Lw - 1 - s) : s) : s;
            if (sizeof(OutT) == 2) {
                const unsigned* srcu = reinterpret_cast<const unsigned*>(&h16[pp ^ 1][warp][0]);
                unsigned* dstu = reinterpret_cast<unsigned*>(wrRow + (size_t)t * ostride);
#pragma unroll
                for (int i = lane; i < 75; i += 32) dstu[i] = v ? srcu[i] : 0u;
            } else {
                const float* srcf = &outFS[pp][warp][0];
                float* dstf = reinterpret_cast<float*>(wrRow + (size_t)t * ostride);
#pragma unroll
                for (int i = lane; i < 150; i += 32) dstf[i] = v ? srcf[i] : 0.f;
            }
        }
    }
}

__global__ void __launch_bounds__(608) k_lstm_l0() {
    lstm_mma_body<__half>(g_gates, g_whhp0, g_a16, KP);
}
__global__ void __launch_bounds__(608) k_lstm_l1() {
    lstm_mma_body<float>(g_gates, g_whhp1, g_h2, DD);
}

// ---------------- final FC layers -------------------------------------------------
__global__ void __launch_bounds__(320) k_fc1(const float* __restrict__ bias) {
    __shared__ float v[DD];
    int b = blockIdx.x, tid = threadIdx.x;
    int L = g_len[b];
    const float* src = g_h2 + ((size_t)b * SS + (L - 1)) * DD;
    if (tid < DD) v[tid] = src[tid];
    __syncthreads();
    if (tid < DD) {
        float acc = bias[tid];
        for (int k = 0; k < DD; ++k) acc += v[k] * g_w1t[k * DD + tid];
        g_tmp[b * DD + tid] = tanhf(acc);
    }
}
__global__ void __launch_bounds__(320) k_fc2(const float* __restrict__ bias,
                                             float* __restrict__ out) {
    __shared__ float v[DD];
    int b = blockIdx.x, tid = threadIdx.x;
    if (tid < DD) v[tid] = g_tmp[b * DD + tid];
    __syncthreads();
    if (tid < DD) {
        float acc = bias[tid];
        for (int k = 0; k < DD; ++k) acc += v[k] * g_w2t[k * DD + tid];
        out[b * DD + tid] = acc;
    }
}

// ---------------- host --------------------------------------------------------------
extern "C" void kernel_launch(void* const* d_in, const int* in_sizes, int n_in,
                              void* d_out, int out_size) {
    const int*   x        = (const int*)  d_in[0];
    const int*   mask     = (const int*)  d_in[1];
    const float* emb      = (const float*)d_in[2];
    const float* Wih_l0f  = (const float*)d_in[3];
    const float* Whh_l0f  = (const float*)d_in[4];
    const float* b_l0f    = (const float*)d_in[5];
    const float* Wih_l0b  = (const float*)d_in[6];
    const float* Whh_l0b  = (const float*)d_in[7];
    const float* b_l0b    = (const float*)d_in[8];
    const float* Wih_l1f  = (const float*)d_in[9];
    const float* Whh_l1f  = (const float*)d_in[10];
    const float* b_l1f    = (const float*)d_in[11];
    const float* Wih_l1b  = (const float*)d_in[12];
    const float* Whh_l1b  = (const float*)d_in[13];
    const float* b_l1b    = (const float*)d_in[14];
    const float* W1       = (const float*)d_in[15];
    const float* b1       = (const float*)d_in[16];
    const float* W2       = (const float*)d_in[17];
    const float* b2       = (const float*)d_in[18];
    float* out = (float*)d_out;

    int mask64 = (in_sizes[1] != BB * SS) ? 1 : 0;

    dim3 sgrid(1520, 6);
    k_setup<<<sgrid, 256>>>(mask, mask64,
                            Wih_l0f, Wih_l0b, Wih_l1f, Wih_l1b,
                            Whh_l0f, Whh_l0b, Whh_l1f, Whh_l1b,
                            b_l0f, b_l0b, b_l1f, b_l1b, W1, W2);

    k_embed16<<<(BB * SS * 152 + 255) / 256, 256>>>(x, emb);

    dim3 g16((BB * SS) / 128, N2P / 128);

    k_gemm16_l0<<<g16, 256>>>();
    k_lstm_l0<<<128, 608>>>();

    k_gemm16_l1<<<g16, 256>>>();
    k_lstm_l1<<<128, 608>>>();

    k_fc1<<<BB, 320>>>(b1);
    k_fc2<<<BB, 320>>>(b2, out);
}

// round 12
// speedup vs baseline: 5.1118x; 1.0274x over previous
#include <cuda_runtime.h>
#include <cuda_fp16.h>
#include <math.h>
#include <stddef.h>

#define BB 1024
#define SS 256
#define DD 300
#define HH 150
#define G4 600     // 4*H
#define N2 1200    // both directions
#define N2P 1280   // padded weight rows (guard-free GEMM loads)
#define KP 304     // input-GEMM K padded to 16
#define KT16 (KP / 16)

// recurrence tiling
#define RKT 10
#define RNW 19
#define HSTR 168
#define PERM_PER_DIR (RNW * 32 * 160)

// ---------------- device scratch ------------------------------------------------
__device__ __half g_a16  [(size_t)BB * SS * KP];
__device__ float  g_last [BB * DD];                // layer1 output at t=L-1 only
__device__ __half g_gates[(size_t)BB * SS * N2];
__device__ __half g_w16_0[N2P * KP];
__device__ __half g_w16_1[N2P * KP];
__device__ __half g_whhp0[2 * PERM_PER_DIR];
__device__ __half g_whhp1[2 * PERM_PER_DIR];
__device__ float  g_bias0[N2P];
__device__ float  g_bias1[N2P];
__device__ float  g_w1t  [DD * DD];
__device__ float  g_w2t  [DD * DD];
__device__ float  g_tmp  [BB * DD];
__device__ int    g_len  [BB];

// gate-interleaved weight-row map: within-dir column m -> weight row
__device__ __forceinline__ int ilv_row(int m) { return (m & 3) * HH + (m >> 2); }

// ---------------- fused setup ----------------------------------------------------
__device__ __forceinline__ void perm_pack(const float* Wf, const float* Wb,
                                          __half* dst, int idx) {
    int dir = idx / PERM_PER_DIR;
    int rem = idx - dir * PERM_PER_DIR;
    int wl  = rem / 160;
    int r2  = rem - wl * 160;
    int w   = wl >> 5, l = wl & 31;
    int kt  = r2 >> 4;
    int r3  = r2 & 15;
    int p   = r3 >> 3;
    int r4  = r3 & 7;
    int ridx = r4 >> 1, h = r4 & 1;
    int m = w * 32 + (p * 2 + (ridx >> 1)) * 8 + (l >> 2);
    int k = kt * 16 + (l & 3) * 2 + (ridx & 1) * 8 + h;
    float v = 0.f;
    if (m < G4 && k < HH) {
        int row = ilv_row(m);
        v = dir ? Wb[row * HH + k] : Wf[row * HH + k];
    }
    dst[idx] = __float2half(v);
}

__global__ void k_setup(const int* __restrict__ mask, int mask64,
                        const float* __restrict__ Wih_l0f, const float* __restrict__ Wih_l0b,
                        const float* __restrict__ Wih_l1f, const float* __restrict__ Wih_l1b,
                        const float* __restrict__ Whh_l0f, const float* __restrict__ Whh_l0b,
                        const float* __restrict__ Whh_l1f, const float* __restrict__ Whh_l1b,
                        const float* __restrict__ b_l0f, const float* __restrict__ b_l0b,
                        const float* __restrict__ b_l1f, const float* __restrict__ b_l1b,
                        const float* __restrict__ W1, const float* __restrict__ W2) {
    int idx = blockIdx.x * blockDim.x + threadIdx.x;
    int task = blockIdx.y;
    if (task == 0) {
        if (idx < BB) {
            int c = 0;
            if (mask64) {
                const int* m = mask + (size_t)idx * SS * 2;
                for (int t = 0; t < SS; ++t) c += ((m[2 * t] | m[2 * t + 1]) != 0);
            } else {
                const int* m = mask + (size_t)idx * SS;
                for (int t = 0; t < SS; ++t) c += (m[t] != 0);
            }
            g_len[idx] = c;
        }
        if (idx < N2P) {
            float v0 = 0.f, v1 = 0.f;
            if (idx < N2) {
                int dir = (idx >= G4);
                int m   = idx - dir * G4;
                int row = ilv_row(m);
                v0 = dir ? b_l0b[row] : b_l0f[row];
                v1 = dir ? b_l1b[row] : b_l1f[row];
            }
            g_bias0[idx] = v0;
            g_bias1[idx] = v1;
        }
    } else if (task == 1 || task == 2) {
        if (idx < N2P * KP) {
            int n = idx / KP, k = idx - n * KP;
            const float* Wf = (task == 1) ? Wih_l0f : Wih_l1f;
            const float* Wb = (task == 1) ? Wih_l0b : Wih_l1b;
            float v = 0.f;
            if (n < N2 && k < DD) {
                int dir = (n >= G4);
                int m   = n - dir * G4;
                int row = ilv_row(m);
                v = dir ? Wb[row * DD + k] : Wf[row * DD + k];
            }
            ((task == 1) ? g_w16_0 : g_w16_1)[idx] = __float2half(v);
        }
    } else if (task == 3) {
        if (idx < 2 * PERM_PER_DIR) perm_pack(Whh_l0f, Whh_l0b, g_whhp0, idx);
    } else if (task == 4) {
        if (idx < 2 * PERM_PER_DIR) perm_pack(Whh_l1f, Whh_l1b, g_whhp1, idx);
    } else {
        if (idx < DD * DD) {
            int r = idx / DD, c = idx - r * DD;
            g_w1t[c * DD + r] = W1[idx];
            g_w2t[c * DD + r] = W2[idx];
        }
    }
}

// ---------------- embedding gather -> fp16 A ------------------------------------
__global__ void k_embed16(const int* __restrict__ x, const float* __restrict__ emb) {
    int idx = blockIdx.x * blockDim.x + threadIdx.x;
    int bt = idx / 152;
    int c  = idx - bt * 152;
    int tok = x[bt];
    __half2 v = __floats2half2_rn(0.f, 0.f);
    if (c < 150 && tok != 0) {
        float2 f = reinterpret_cast<const float2*>(emb)[(size_t)tok * 150 + c];
        v = __floats2half2_rn(f.x, f.y);
    }
    reinterpret_cast<__half2*>(g_a16)[idx] = v;
}

// ---------------- input GEMM: cp.async 3-stage, 128x128x16, bias fused ----------
__device__ __forceinline__ void cp16(unsigned dst, const void* src) {
    asm volatile("cp.async.cg.shared.global [%0], [%1], 16;\n" :: "r"(dst), "l"(src));
}
__device__ __forceinline__ void cp_commit() { asm volatile("cp.async.commit_group;\n"); }
__device__ __forceinline__ void cp_wait1()  { asm volatile("cp.async.wait_group 1;\n"); }
__device__ __forceinline__ void cp_wait0()  { asm volatile("cp.async.wait_group 0;\n"); }

__device__ __forceinline__ void gemm16_body(const __half* __restrict__ A,
                                            const __half* __restrict__ Bw,
                                            const float* __restrict__ biasv,
                                            __half* __restrict__ C) {
    __shared__ __half As[3][128][24];
    __shared__ __half Bs[3][128][24];
    int tid  = threadIdx.x;
    int m0   = blockIdx.x * 128;
    int n0   = blockIdx.y * 128;
    int warp = tid >> 5, lane = tid & 31;
    int wm = warp & 3, wn = warp >> 2;
    int l4 = lane >> 2, c2 = (lane & 3) * 2;
    int row = tid >> 1, chk = (tid & 1) * 8;

    const __half* Asrc = A + (size_t)(m0 + row) * KP + chk;
    const __half* Bsrc = Bw + (size_t)(n0 + row) * KP + chk;

    float acc[2][8][4];
#pragma unroll
    for (int i = 0; i < 2; ++i)
#pragma unroll
        for (int j = 0; j < 8; ++j)
#pragma unroll
            for (int q = 0; q < 4; ++q) acc[i][j][q] = 0.f;

#pragma unroll
    for (int p = 0; p < 2; ++p) {
        unsigned da = (unsigned)__cvta_generic_to_shared(&As[p][row][chk]);
        unsigned db = (unsigned)__cvta_generic_to_shared(&Bs[p][row][chk]);
        cp16(da, Asrc + p * 16);
        cp16(db, Bsrc + p * 16);
        cp_commit();
    }

    for (int kt = 0; kt < KT16; ++kt) {
        if (kt == KT16 - 1) cp_wait0(); else cp_wait1();
        __syncthreads();
        int st = kt % 3;
        if (kt + 2 < KT16) {
            int ns = (kt + 2) % 3;
            unsigned da = (unsigned)__cvta_generic_to_shared(&As[ns][row][chk]);
            unsigned db = (unsigned)__cvta_generic_to_shared(&Bs[ns][row][chk]);
            cp16(da, Asrc + (kt + 2) * 16);
            cp16(db, Bsrc + (kt + 2) * 16);
            cp_commit();
        }

        unsigned af[2][4];
#pragma unroll
        for (int mi = 0; mi < 2; ++mi) {
            int rb = wm * 32 + mi * 16;
            af[mi][0] = *reinterpret_cast<const unsigned*>(&As[st][rb + l4][c2]);
            af[mi][1] = *reinterpret_cast<const unsigned*>(&As[st][rb + l4 + 8][c2]);
            af[mi][2] = *reinterpret_cast<const unsigned*>(&As[st][rb + l4][c2 + 8]);
            af[mi][3] = *reinterpret_cast<const unsigned*>(&As[st][rb + l4 + 8][c2 + 8]);
        }
        unsigned bf[8][2];
#pragma unroll
        for (int ni = 0; ni < 8; ++ni) {
            int nr = wn * 64 + ni * 8 + l4;
            bf[ni][0] = *reinterpret_cast<const unsigned*>(&Bs[st][nr][c2]);
            bf[ni][1] = *reinterpret_cast<const unsigned*>(&Bs[st][nr][c2 + 8]);
        }
#pragma unroll
        for (int mi = 0; mi < 2; ++mi)
#pragma unroll
            for (int ni = 0; ni < 8; ++ni)
                asm volatile(
                    "mma.sync.aligned.m16n8k16.row.col.f32.f16.f16.f32 "
                    "{%0,%1,%2,%3},{%4,%5,%6,%7},{%8,%9},{%0,%1,%2,%3};"
                    : "+f"(acc[mi][ni][0]), "+f"(acc[mi][ni][1]),
                      "+f"(acc[mi][ni][2]), "+f"(acc[mi][ni][3])
                    : "r"(af[mi][0]), "r"(af[mi][1]), "r"(af[mi][2]), "r"(af[mi][3]),
                      "r"(bf[ni][0]), "r"(bf[ni][1]));
        __syncthreads();
    }

#pragma unroll
    for (int mi = 0; mi < 2; ++mi)
#pragma unroll
        for (int ni = 0; ni < 8; ++ni) {
            int m = m0 + wm * 32 + mi * 16 + l4;
            int n = n0 + wn * 64 + ni * 8 + c2;
            if (n < N2) {
                float2 bv = *reinterpret_cast<const float2*>(&biasv[n]);
                __half2 h01 = __floats2half2_rn(acc[mi][ni][0] + bv.x, acc[mi][ni][1] + bv.y);
                __half2 h23 = __floats2half2_rn(acc[mi][ni][2] + bv.x, acc[mi][ni][3] + bv.y);
                *reinterpret_cast<__half2*>(C + (size_t)m * N2 + n)       = h01;
                *reinterpret_cast<__half2*>(C + (size_t)(m + 8) * N2 + n) = h23;
            }
        }
}

__global__ void __launch_bounds__(256) k_gemm16_l0() { gemm16_body(g_a16, g_w16_0, g_bias0, g_gates); }
__global__ void __launch_bounds__(256) k_gemm16_l1() { gemm16_body(g_a16, g_w16_1, g_bias1, g_gates); }

// ---------------- fast activations ----------------------------------------------
__device__ __forceinline__ float tanh_fast(float x) {
    float y; asm("tanh.approx.f32 %0, %1;" : "=f"(y) : "f"(x)); return y;
}
__device__ __forceinline__ unsigned tanh2_fast(unsigned x) {
    unsigned y; asm("tanh.approx.f16x2 %0, %1;" : "=r"(y) : "r"(x)); return y;
}
__device__ __forceinline__ void ldsm_x4(unsigned& r0, unsigned& r1,
                                        unsigned& r2, unsigned& r3, unsigned addr) {
    asm volatile("ldmatrix.sync.aligned.m8n8.x4.shared.b16 {%0,%1,%2,%3}, [%4];"
                 : "=r"(r0), "=r"(r1), "=r"(r2), "=r"(r3) : "r"(addr));
}

// ---------------- tensor-core persistent LSTM ------------------------------------
// LAST_ONLY=false (layer0): write full h sequence (fp16) for next layer's GEMM.
// LAST_ONLY=true  (layer1): write only h at t=L-1 into lastOut (fp32).
template <bool LAST_ONLY>
__device__ __forceinline__ void lstm_mma_body(const __half* __restrict__ Gt,
                                              const __half* __restrict__ permAll,
                                              __half* __restrict__ Hout,
                                              float* __restrict__ lastOut) {
    __shared__ __align__(16) __half h16[2][16][HSTR];
    __shared__ __align__(16) float  outFS[2][16][152];   // LAST_ONLY staging

    int tid  = threadIdx.x;
    int dir  = blockIdx.x & 1;
    int b0   = (blockIdx.x >> 1) * 16;
    int warp = tid >> 5, lane = tid & 31;
    int l4   = lane >> 2, c2 = (lane & 3) * 2;
    int wbase = warp * 32;
    int goff = dir * G4;
    int hoff = dir * HH;
    const uint4* permLane =
        reinterpret_cast<const uint4*>(permAll + (size_t)dir * PERM_PER_DIR) +
        (warp * 32 + lane) * 20;

    // ldmatrix lane source
    int rowL = ((lane >> 3) & 1) * 8 + (lane & 7);
    int colL = (lane >> 4) * 8;
    unsigned aBase = (unsigned)__cvta_generic_to_shared(&h16[0][rowL][colL]);
    const unsigned ppStride = 16 * HSTR * 2;   // bytes

    int LA = g_len[b0 + l4];
    int LB = g_len[b0 + l4 + 8];
    int par = lane & 1;
    int b1  = (lane >> 1) & 1;
    int rowSel = par ? (l4 + 8) : l4;
    int Lsel   = par ? LB : LA;
    int jbase  = (warp << 3) + b1;        // j = jbase + 2*nt

    size_t rowAg = (size_t)(b0 + l4) * SS;
    size_t rowBg = (size_t)(b0 + l4 + 8) * SS;

    int Lw = (warp < 16) ? g_len[b0 + warp] : 0;
    __half* wrRow = Hout + (size_t)(b0 + (warp < 16 ? warp : 0)) * SS * KP + hoff;

    const __half2 sc_if = __floats2half2_rn(0.5f, 0.5f);
    const __half2 sc_go = __floats2half2_rn(1.0f, 0.5f);

    float cst[4] = {0.f, 0.f, 0.f, 0.f};
    float hst[4] = {0.f, 0.f, 0.f, 0.f};

    for (int i = tid; i < 2 * 16 * HSTR; i += blockDim.x)
        (&h16[0][0][0])[i] = __float2half(0.f);

    // prologue: load gates for step 0
    __half2 gaC[4], gbC[4];
    {
        int tA0 = (0 < LA) ? (dir ? (LA - 1) : 0) : 0;
        int tB0 = (0 < LB) ? (dir ? (LB - 1) : 0) : 0;
#pragma unroll
        for (int nt = 0; nt < 4; ++nt) {
            int cA = wbase + nt * 8 + c2;
            gaC[nt] = __floats2half2_rn(0.f, 0.f);
            gbC[nt] = gaC[nt];
            if (cA < G4) {
                gaC[nt] = *reinterpret_cast<const __half2*>(&Gt[(rowAg + tA0) * N2 + goff + cA]);
                gbC[nt] = *reinterpret_cast<const __half2*>(&Gt[(rowBg + tB0) * N2 + goff + cA]);
            }
        }
    }
    __syncthreads();

    for (int s = 0; s < SS; ++s) {
        int pp = s & 1;

        // prefetch gates for step s+1
        __half2 gaN[4], gbN[4];
        {
            int s1 = s + 1;
            int tA1 = (s1 < LA) ? (dir ? (LA - 1 - s1) : s1) : ((s1 < SS) ? s1 : 0);
            int tB1 = (s1 < LB) ? (dir ? (LB - 1 - s1) : s1) : ((s1 < SS) ? s1 : 0);
#pragma unroll
            for (int nt = 0; nt < 4; ++nt) {
                int cA = wbase + nt * 8 + c2;
                gaN[nt] = __floats2half2_rn(0.f, 0.f);
                gbN[nt] = gaN[nt];
                if (cA < G4) {
                    gaN[nt] = *reinterpret_cast<const __half2*>(&Gt[(rowAg + tA1) * N2 + goff + cA]);
                    gbN[nt] = *reinterpret_cast<const __half2*>(&Gt[(rowBg + tB1) * N2 + goff + cA]);
                }
            }
        }

        // MMA
        float acc[4][4];
#pragma unroll
        for (int nt = 0; nt < 4; ++nt)
#pragma unroll
            for (int r = 0; r < 4; ++r) acc[nt][r] = 0.f;

        unsigned aAddr = aBase + (unsigned)pp * ppStride;
#pragma unroll
        for (int kt = 0; kt < RKT; ++kt) {
            unsigned a0, a1, a2, a3;
            ldsm_x4(a0, a1, a2, a3, aAddr + kt * 32);
            uint4 q0 = permLane[kt * 2 + 0];
            uint4 q1 = permLane[kt * 2 + 1];
            asm volatile("mma.sync.aligned.m16n8k16.row.col.f32.f16.f16.f32 "
                         "{%0,%1,%2,%3},{%4,%5,%6,%7},{%8,%9},{%0,%1,%2,%3};"
                         : "+f"(acc[0][0]), "+f"(acc[0][1]), "+f"(acc[0][2]), "+f"(acc[0][3])
                         : "r"(a0), "r"(a1), "r"(a2), "r"(a3), "r"(q0.x), "r"(q0.y));
            asm volatile("mma.sync.aligned.m16n8k16.row.col.f32.f16.f16.f32 "
                         "{%0,%1,%2,%3},{%4,%5,%6,%7},{%8,%9},{%0,%1,%2,%3};"
                         : "+f"(acc[1][0]), "+f"(acc[1][1]), "+f"(acc[1][2]), "+f"(acc[1][3])
                         : "r"(a0), "r"(a1), "r"(a2), "r"(a3), "r"(q0.z), "r"(q0.w));
            asm volatile("mma.sync.aligned.m16n8k16.row.col.f32.f16.f16.f32 "
                         "{%0,%1,%2,%3},{%4,%5,%6,%7},{%8,%9},{%0,%1,%2,%3};"
                         : "+f"(acc[2][0]), "+f"(acc[2][1]), "+f"(acc[2][2]), "+f"(acc[2][3])
                         : "r"(a0), "r"(a1), "r"(a2), "r"(a3), "r"(q1.x), "r"(q1.y));
            asm volatile("mma.sync.aligned.m16n8k16.row.col.f32.f16.f16.f32 "
                         "{%0,%1,%2,%3},{%4,%5,%6,%7},{%8,%9},{%0,%1,%2,%3};"
                         : "+f"(acc[3][0]), "+f"(acc[3][1]), "+f"(acc[3][2]), "+f"(acc[3][3])
                         : "r"(a0), "r"(a1), "r"(a2), "r"(a3), "r"(q1.z), "r"(q1.w));
        }

        // elementwise
        bool valid = (s < Lsel);
        bool trig  = LAST_ONLY && (dir ? (s == 0) : (s == Lsel - 1));
#pragma unroll
        for (int nt = 0; nt < 4; ++nt) {
            float2 fa = __half22float2(gaC[nt]);
            float2 fb = __half22float2(gbC[nt]);
            float v0 = acc[nt][0] + fa.x;
            float v1 = acc[nt][1] + fa.y;
            float v2 = acc[nt][2] + fb.x;
            float v3 = acc[nt][3] + fb.y;
            float sx = par ? v0 : v2;
            float sy = par ? v1 : v3;
            __half2 snd = __floats2half2_rn(sx, sy);
            unsigned rcvu = __shfl_xor_sync(0xffffffff, *reinterpret_cast<unsigned*>(&snd), 1);
            __half2 rh = *reinterpret_cast<__half2*>(&rcvu);
            float px = par ? v2        : v0 * 0.5f;
            float py = par ? v3 * 0.5f : v1 * 0.5f;
            __half2 own2 = __floats2half2_rn(px, py);
            __half2 rsc  = __hmul2(rh, par ? sc_if : sc_go);
            __half2 hif = par ? rsc  : own2;
            __half2 hgo = par ? own2 : rsc;
            unsigned t1 = tanh2_fast(*reinterpret_cast<unsigned*>(&hif));
            unsigned t2 = tanh2_fast(*reinterpret_cast<unsigned*>(&hgo));
            float2 f1 = __half22float2(*reinterpret_cast<__half2*>(&t1));
            float2 f2 = __half22float2(*reinterpret_cast<__half2*>(&t2));
            float iv = 0.5f * f1.x + 0.5f;
            float fv = 0.5f * f1.y + 0.5f;
            float gv = f2.x;
            float ov = 0.5f * f2.y + 0.5f;
            float cn = fv * cst[nt] + iv * gv;
            float hn = ov * tanh_fast(cn);
            if (valid) { cst[nt] = cn; hst[nt] = hn; }

            // paired h-state store: lanes l and l^2 hold j and j+1 of same row
            unsigned hbits = (unsigned)__half_as_ushort(__float2half(hst[nt]));
            unsigned partb = __shfl_xor_sync(0xffffffff, hbits, 2);
            if (b1 == 0) {
                int j0 = (warp << 3) + 2 * nt;
                if (j0 < HH) {
                    __half2 hp = __halves2half2(__ushort_as_half((unsigned short)hbits),
                                                __ushort_as_half((unsigned short)partb));
                    *reinterpret_cast<__half2*>(&h16[pp ^ 1][rowSel][j0]) = hp;
                }
            }
            if (LAST_ONLY && trig) {
                int j = jbase + 2 * nt;
                if (j < HH) outFS[pp][rowSel][j] = hn;
            }
        }
#pragma unroll
        for (int nt = 0; nt < 4; ++nt) { gaC[nt] = gaN[nt]; gbC[nt] = gbN[nt]; }
        __syncthreads();

        // writer warps
        if (LAST_ONLY) {
            if (warp < 16) {
                bool wtrig = dir ? (s == 0) : (s == Lw - 1);
                if (wtrig) {
                    float* dst = lastOut + (size_t)(b0 + warp) * DD + hoff;
                    const float* srcf = &outFS[pp][warp][0];
#pragma unroll
                    for (int i = lane; i < 150; i += 32) dst[i] = srcf[i];
                }
            }
        } else {
            if (warp < 16) {
                bool v = (s < Lw);
                int t = v ? (dir ? (Lw - 1 - s) : s) : s;
                const unsigned* srcu = reinterpret_cast<const unsigned*>(&h16[pp ^ 1][warp][0]);
                unsigned* dstu = reinterpret_cast<unsigned*>(wrRow + (size_t)t * KP);
#pragma unroll
                for (int i = lane; i < 75; i += 32) dstu[i] = v ? srcu[i] : 0u;
            }
        }
    }
}

__global__ void __launch_bounds__(608) k_lstm_l0() {
    lstm_mma_body<false>(g_gates, g_whhp0, g_a16, nullptr);
}
__global__ void __launch_bounds__(608) k_lstm_l1() {
    lstm_mma_body<true>(g_gates, g_whhp1, nullptr, g_last);
}

// ---------------- final FC layers -------------------------------------------------
__global__ void __launch_bounds__(320) k_fc1(const float* __restrict__ bias) {
    __shared__ float v[DD];
    int b = blockIdx.x, tid = threadIdx.x;
    const float* src = g_last + (size_t)b * DD;
    if (tid < DD) v[tid] = src[tid];
    __syncthreads();
    if (tid < DD) {
        float acc = bias[tid];
        for (int k = 0; k < DD; ++k) acc += v[k] * g_w1t[k * DD + tid];
        g_tmp[b * DD + tid] = tanhf(acc);
    }
}
__global__ void __launch_bounds__(320) k_fc2(const float* __restrict__ bias,
                                             float* __restrict__ out) {
    __shared__ float v[DD];
    int b = blockIdx.x, tid = threadIdx.x;
    if (tid < DD) v[tid] = g_tmp[b * DD + tid];
    __syncthreads();
    if (tid < DD) {
        float acc = bias[tid];
        for (int k = 0; k < DD; ++k) acc += v[k] * g_w2t[k * DD + tid];
        out[b * DD + tid] = acc;
    }
}

// ---------------- host --------------------------------------------------------------
extern "C" void kernel_launch(void* const* d_in, const int* in_sizes, int n_in,
                              void* d_out, int out_size) {
    const int*   x        = (const int*)  d_in[0];
    const int*   mask     = (const int*)  d_in[1];
    const float* emb      = (const float*)d_in[2];
    const float* Wih_l0f  = (const float*)d_in[3];
    const float* Whh_l0f  = (const float*)d_in[4];
    const float* b_l0f    = (const float*)d_in[5];
    const float* Wih_l0b  = (const float*)d_in[6];
    const float* Whh_l0b  = (const float*)d_in[7];
    const float* b_l0b    = (const float*)d_in[8];
    const float* Wih_l1f  = (const float*)d_in[9];
    const float* Whh_l1f  = (const float*)d_in[10];
    const float* b_l1f    = (const float*)d_in[11];
    const float* Wih_l1b  = (const float*)d_in[12];
    const float* Whh_l1b  = (const float*)d_in[13];
    const float* b_l1b    = (const float*)d_in[14];
    const float* W1       = (const float*)d_in[15];
    const float* b1       = (const float*)d_in[16];
    const float* W2       = (const float*)d_in[17];
    const float* b2       = (const float*)d_in[18];
    float* out = (float*)d_out;

    int mask64 = (in_sizes[1] != BB * SS) ? 1 : 0;

    dim3 sgrid(1520, 6);
    k_setup<<<sgrid, 256>>>(mask, mask64,
                            Wih_l0f, Wih_l0b, Wih_l1f, Wih_l1b,
                            Whh_l0f, Whh_l0b, Whh_l1f, Whh_l1b,
                            b_l0f, b_l0b, b_l1f, b_l1b, W1, W2);

    k_embed16<<<(BB * SS * 152 + 255) / 256, 256>>>(x, emb);

    dim3 g16((BB * SS) / 128, N2P / 128);

    k_gemm16_l0<<<g16, 256>>>();
    k_lstm_l0<<<128, 608>>>();

    k_gemm16_l1<<<g16, 256>>>();
    k_lstm_l1<<<128, 608>>>();

    k_fc1<<<BB, 320>>>(b1);
    k_fc2<<<BB, 320>>>(b2, out);
}

// round 13
// speedup vs baseline: 5.1703x; 1.0114x over previous
#include <cuda_runtime.h>
#include <cuda_fp16.h>
#include <math.h>
#include <stddef.h>

#define BB 1024
#define SS 256
#define DD 300
#define HH 150
#define G4 600     // 4*H
#define DGO 608    // per-dir gate region width (π-closed)
#define N2G 1216   // gates row width (2 dirs)
#define N2P 1280   // padded weight rows (guard-free GEMM loads)
#define KP 304     // input-GEMM K padded to 16
#define KT16 (KP / 16)

// recurrence tiling
#define RKT 10
#define RNW 19
#define HSTR 168
#define PERM_PER_DIR (RNW * 32 * 160)

// ---------------- device scratch ------------------------------------------------
__device__ __half g_a16  [(size_t)BB * SS * KP];
__device__ float  g_last [BB * DD];                // layer1 output at t=L-1 only
__device__ __half g_gates[(size_t)BB * SS * N2G];
__device__ __half g_w16_0[N2P * KP];
__device__ __half g_w16_1[N2P * KP];
__device__ __half g_whhp0[2 * PERM_PER_DIR];
__device__ __half g_whhp1[2 * PERM_PER_DIR];
__device__ float  g_bias0[N2P];
__device__ float  g_bias1[N2P];
__device__ float  g_w1t  [DD * DD];
__device__ float  g_w2t  [DD * DD];
__device__ float  g_tmp  [BB * DD];
__device__ int    g_len  [BB];

// gate-interleaved weight-row map: accumulator column m -> weight row
__device__ __forceinline__ int ilv_row(int m) { return (m & 3) * HH + (m >> 2); }
// in-32-block involution: swap (nt, q) bit-fields; memory col <-> accumulator col
__device__ __forceinline__ int pi32(int m) {
    return (m & ~31) | ((m & 6) << 2) | ((m >> 2) & 6) | (m & 1);
}

// ---------------- fused setup ----------------------------------------------------
__device__ __forceinline__ void perm_pack(const float* Wf, const float* Wb,
                                          __half* dst, int idx) {
    int dir = idx / PERM_PER_DIR;
    int rem = idx - dir * PERM_PER_DIR;
    int wl  = rem / 160;
    int r2  = rem - wl * 160;
    int w   = wl >> 5, l = wl & 31;
    int kt  = r2 >> 4;
    int r3  = r2 & 15;
    int p   = r3 >> 3;
    int r4  = r3 & 7;
    int ridx = r4 >> 1, h = r4 & 1;
    int m = w * 32 + (p * 2 + (ridx >> 1)) * 8 + (l >> 2);
    int k = kt * 16 + (l & 3) * 2 + (ridx & 1) * 8 + h;
    float v = 0.f;
    if (m < G4 && k < HH) {
        int row = ilv_row(m);
        v = dir ? Wb[row * HH + k] : Wf[row * HH + k];
    }
    dst[idx] = __float2half(v);
}

__global__ void k_setup(const int* __restrict__ mask, int mask64,
                        const float* __restrict__ Wih_l0f, const float* __restrict__ Wih_l0b,
                        const float* __restrict__ Wih_l1f, const float* __restrict__ Wih_l1b,
                        const float* __restrict__ Whh_l0f, const float* __restrict__ Whh_l0b,
                        const float* __restrict__ Whh_l1f, const float* __restrict__ Whh_l1b,
                        const float* __restrict__ b_l0f, const float* __restrict__ b_l0b,
                        const float* __restrict__ b_l1f, const float* __restrict__ b_l1b,
                        const float* __restrict__ W1, const float* __restrict__ W2) {
    int idx = blockIdx.x * blockDim.x + threadIdx.x;
    int task = blockIdx.y;
    if (task == 0) {
        if (idx < BB) {
            int c = 0;
            if (mask64) {
                const int* m = mask + (size_t)idx * SS * 2;
                for (int t = 0; t < SS; ++t) c += ((m[2 * t] | m[2 * t + 1]) != 0);
            } else {
                const int* m = mask + (size_t)idx * SS;
                for (int t = 0; t < SS; ++t) c += (m[t] != 0);
            }
            g_len[idx] = c;
        }
        if (idx < N2P) {
            float v0 = 0.f, v1 = 0.f;
            if (idx < N2G) {
                int dir = (idx >= DGO);
                int mm  = idx - dir * DGO;
                int ca  = pi32(mm);
                if (ca < G4) {
                    int row = ilv_row(ca);
                    v0 = dir ? b_l0b[row] : b_l0f[row];
                    v1 = dir ? b_l1b[row] : b_l1f[row];
                }
            }
            g_bias0[idx] = v0;
            g_bias1[idx] = v1;
        }
    } else if (task == 1 || task == 2) {       // pack Wih, π-permuted gate layout
        if (idx < N2P * KP) {
            int n = idx / KP, k = idx - n * KP;
            const float* Wf = (task == 1) ? Wih_l0f : Wih_l1f;
            const float* Wb = (task == 1) ? Wih_l0b : Wih_l1b;
            float v = 0.f;
            if (n < N2G && k < DD) {
                int dir = (n >= DGO);
                int mm  = n - dir * DGO;
                int ca  = pi32(mm);
                if (ca < G4) {
                    int row = ilv_row(ca);
                    v = dir ? Wb[row * DD + k] : Wf[row * DD + k];
                }
            }
            ((task == 1) ? g_w16_0 : g_w16_1)[idx] = __float2half(v);
        }
    } else if (task == 3) {
        if (idx < 2 * PERM_PER_DIR) perm_pack(Whh_l0f, Whh_l0b, g_whhp0, idx);
    } else if (task == 4) {
        if (idx < 2 * PERM_PER_DIR) perm_pack(Whh_l1f, Whh_l1b, g_whhp1, idx);
    } else {
        if (idx < DD * DD) {
            int r = idx / DD, c = idx - r * DD;
            g_w1t[c * DD + r] = W1[idx];
            g_w2t[c * DD + r] = W2[idx];
        }
    }
}

// ---------------- embedding gather -> fp16 A ------------------------------------
__global__ void k_embed16(const int* __restrict__ x, const float* __restrict__ emb) {
    int idx = blockIdx.x * blockDim.x + threadIdx.x;
    int bt = idx / 152;
    int c  = idx - bt * 152;
    int tok = x[bt];
    __half2 v = __floats2half2_rn(0.f, 0.f);
    if (c < 150 && tok != 0) {
        float2 f = reinterpret_cast<const float2*>(emb)[(size_t)tok * 150 + c];
        v = __floats2half2_rn(f.x, f.y);
    }
    reinterpret_cast<__half2*>(g_a16)[idx] = v;
}

// ---------------- input GEMM: cp.async 3-stage, 128x128x16, bias fused ----------
__device__ __forceinline__ void cp16(unsigned dst, const void* src) {
    asm volatile("cp.async.cg.shared.global [%0], [%1], 16;\n" :: "r"(dst), "l"(src));
}
__device__ __forceinline__ void cp_commit() { asm volatile("cp.async.commit_group;\n"); }
__device__ __forceinline__ void cp_wait1()  { asm volatile("cp.async.wait_group 1;\n"); }
__device__ __forceinline__ void cp_wait0()  { asm volatile("cp.async.wait_group 0;\n"); }

__device__ __forceinline__ void gemm16_body(const __half* __restrict__ A,
                                            const __half* __restrict__ Bw,
                                            const float* __restrict__ biasv,
                                            __half* __restrict__ C) {
    __shared__ __half As[3][128][24];
    __shared__ __half Bs[3][128][24];
    int tid  = threadIdx.x;
    int m0   = blockIdx.x * 128;
    int n0   = blockIdx.y * 128;
    int warp = tid >> 5, lane = tid & 31;
    int wm = warp & 3, wn = warp >> 2;
    int l4 = lane >> 2, c2 = (lane & 3) * 2;
    int row = tid >> 1, chk = (tid & 1) * 8;

    const __half* Asrc = A + (size_t)(m0 + row) * KP + chk;
    const __half* Bsrc = Bw + (size_t)(n0 + row) * KP + chk;

    float acc[2][8][4];
#pragma unroll
    for (int i = 0; i < 2; ++i)
#pragma unroll
        for (int j = 0; j < 8; ++j)
#pragma unroll
            for (int q = 0; q < 4; ++q) acc[i][j][q] = 0.f;

#pragma unroll
    for (int p = 0; p < 2; ++p) {
        unsigned da = (unsigned)__cvta_generic_to_shared(&As[p][row][chk]);
        unsigned db = (unsigned)__cvta_generic_to_shared(&Bs[p][row][chk]);
        cp16(da, Asrc + p * 16);
        cp16(db, Bsrc + p * 16);
        cp_commit();
    }

    for (int kt = 0; kt < KT16; ++kt) {
        if (kt == KT16 - 1) cp_wait0(); else cp_wait1();
        __syncthreads();
        int st = kt % 3;
        if (kt + 2 < KT16) {
            int ns = (kt + 2) % 3;
            unsigned da = (unsigned)__cvta_generic_to_shared(&As[ns][row][chk]);
            unsigned db = (unsigned)__cvta_generic_to_shared(&Bs[ns][row][chk]);
            cp16(da, Asrc + (kt + 2) * 16);
            cp16(db, Bsrc + (kt + 2) * 16);
            cp_commit();
        }

        unsigned af[2][4];
#pragma unroll
        for (int mi = 0; mi < 2; ++mi) {
            int rb = wm * 32 + mi * 16;
            af[mi][0] = *reinterpret_cast<const unsigned*>(&As[st][rb + l4][c2]);
            af[mi][1] = *reinterpret_cast<const unsigned*>(&As[st][rb + l4 + 8][c2]);
            af[mi][2] = *reinterpret_cast<const unsigned*>(&As[st][rb + l4][c2 + 8]);
            af[mi][3] = *reinterpret_cast<const unsigned*>(&As[st][rb + l4 + 8][c2 + 8]);
        }
        unsigned bf[8][2];
#pragma unroll
        for (int ni = 0; ni < 8; ++ni) {
            int nr = wn * 64 + ni * 8 + l4;
            bf[ni][0] = *reinterpret_cast<const unsigned*>(&Bs[st][nr][c2]);
            bf[ni][1] = *reinterpret_cast<const unsigned*>(&Bs[st][nr][c2 + 8]);
        }
#pragma unroll
        for (int mi = 0; mi < 2; ++mi)
#pragma unroll
            for (int ni = 0; ni < 8; ++ni)
                asm volatile(
                    "mma.sync.aligned.m16n8k16.row.col.f32.f16.f16.f32 "
                    "{%0,%1,%2,%3},{%4,%5,%6,%7},{%8,%9},{%0,%1,%2,%3};"
                    : "+f"(acc[mi][ni][0]), "+f"(acc[mi][ni][1]),
                      "+f"(acc[mi][ni][2]), "+f"(acc[mi][ni][3])
                    : "r"(af[mi][0]), "r"(af[mi][1]), "r"(af[mi][2]), "r"(af[mi][3]),
                      "r"(bf[ni][0]), "r"(bf[ni][1]));
        __syncthreads();
    }

#pragma unroll
    for (int mi = 0; mi < 2; ++mi)
#pragma unroll
        for (int ni = 0; ni < 8; ++ni) {
            int m = m0 + wm * 32 + mi * 16 + l4;
            int n = n0 + wn * 64 + ni * 8 + c2;
            if (n < N2G) {
                float2 bv = *reinterpret_cast<const float2*>(&biasv[n]);
                __half2 h01 = __floats2half2_rn(acc[mi][ni][0] + bv.x, acc[mi][ni][1] + bv.y);
                __half2 h23 = __floats2half2_rn(acc[mi][ni][2] + bv.x, acc[mi][ni][3] + bv.y);
                *reinterpret_cast<__half2*>(C + (size_t)m * N2G + n)       = h01;
                *reinterpret_cast<__half2*>(C + (size_t)(m + 8) * N2G + n) = h23;
            }
        }
}

__global__ void __launch_bounds__(256) k_gemm16_l0() { gemm16_body(g_a16, g_w16_0, g_bias0, g_gates); }
__global__ void __launch_bounds__(256) k_gemm16_l1() { gemm16_body(g_a16, g_w16_1, g_bias1, g_gates); }

// ---------------- fast activations ----------------------------------------------
__device__ __forceinline__ float tanh_fast(float x) {
    float y; asm("tanh.approx.f32 %0, %1;" : "=f"(y) : "f"(x)); return y;
}
__device__ __forceinline__ unsigned tanh2_fast(unsigned x) {
    unsigned y; asm("tanh.approx.f16x2 %0, %1;" : "=r"(y) : "r"(x)); return y;
}
__device__ __forceinline__ void ldsm_x4(unsigned& r0, unsigned& r1,
                                        unsigned& r2, unsigned& r3, unsigned addr) {
    asm volatile("ldmatrix.sync.aligned.m8n8.x4.shared.b16 {%0,%1,%2,%3}, [%4];"
                 : "=r"(r0), "=r"(r1), "=r"(r2), "=r"(r3) : "r"(addr));
}

// ---------------- tensor-core persistent LSTM ------------------------------------
template <bool LAST_ONLY>
__device__ __forceinline__ void lstm_mma_body(const __half* __restrict__ Gt,
                                              const __half* __restrict__ permAll,
                                              __half* __restrict__ Hout,
                                              float* __restrict__ lastOut) {
    __shared__ __align__(16) __half h16[2][16][HSTR];
    __shared__ __align__(16) float  outFS[2][16][152];   // LAST_ONLY staging

    int tid  = threadIdx.x;
    int dir  = blockIdx.x & 1;
    int b0   = (blockIdx.x >> 1) * 16;
    int warp = tid >> 5, lane = tid & 31;
    int l4   = lane >> 2, q = lane & 3;
    int wbase = warp * 32;
    int goff = dir * DGO;
    int hoff = dir * HH;
    const uint4* permLane =
        reinterpret_cast<const uint4*>(permAll + (size_t)dir * PERM_PER_DIR) +
        (warp * 32 + lane) * 20;

    // ldmatrix lane source
    int rowL = ((lane >> 3) & 1) * 8 + (lane & 7);
    int colL = (lane >> 4) * 8;
    unsigned aBase = (unsigned)__cvta_generic_to_shared(&h16[0][rowL][colL]);
    const unsigned ppStride = 16 * HSTR * 2;   // bytes

    int LA = g_len[b0 + l4];
    int LB = g_len[b0 + l4 + 8];
    int par = lane & 1;
    int b1  = (lane >> 1) & 1;
    int rowSel = par ? (l4 + 8) : l4;
    int Lsel   = par ? LB : LA;
    int jbase  = (warp << 3) + b1;        // j = jbase + 2*nt

    // gate load bases (π layout: one uint4 per row-half covers all 4 nt)
    const __half* gBaseA = Gt + ((size_t)(b0 + l4)     * SS) * N2G + goff + wbase + q * 8;
    const __half* gBaseB = Gt + ((size_t)(b0 + l4 + 8) * SS) * N2G + goff + wbase + q * 8;

    int Lw = (warp < 16) ? g_len[b0 + warp] : 0;
    __half* wrRow = Hout + (size_t)(b0 + (warp < 16 ? warp : 0)) * SS * KP + hoff;

    const __half2 sc_if = __floats2half2_rn(0.5f, 0.5f);
    const __half2 sc_go = __floats2half2_rn(1.0f, 0.5f);

    float cst[4] = {0.f, 0.f, 0.f, 0.f};
    float hst[4] = {0.f, 0.f, 0.f, 0.f};

    for (int i = tid; i < 2 * 16 * HSTR; i += blockDim.x)
        (&h16[0][0][0])[i] = __float2half(0.f);

    // prologue: load gates for step 0
    uint4 gaV, gbV;
    {
        int tA0 = (0 < LA) ? (dir ? (LA - 1) : 0) : 0;
        int tB0 = (0 < LB) ? (dir ? (LB - 1) : 0) : 0;
        gaV = *reinterpret_cast<const uint4*>(gBaseA + (size_t)tA0 * N2G);
        gbV = *reinterpret_cast<const uint4*>(gBaseB + (size_t)tB0 * N2G);
    }
    __syncthreads();

    for (int s = 0; s < SS; ++s) {
        int pp = s & 1;

        // prefetch gates for step s+1
        uint4 gaN, gbN;
        {
            int s1 = s + 1;
            int tA1 = (s1 < LA) ? (dir ? (LA - 1 - s1) : s1) : ((s1 < SS) ? s1 : 0);
            int tB1 = (s1 < LB) ? (dir ? (LB - 1 - s1) : s1) : ((s1 < SS) ? s1 : 0);
            gaN = *reinterpret_cast<const uint4*>(gBaseA + (size_t)tA1 * N2G);
            gbN = *reinterpret_cast<const uint4*>(gBaseB + (size_t)tB1 * N2G);
        }

        // MMA
        float acc[4][4];
#pragma unroll
        for (int nt = 0; nt < 4; ++nt)
#pragma unroll
            for (int r = 0; r < 4; ++r) acc[nt][r] = 0.f;

        unsigned aAddr = aBase + (unsigned)pp * ppStride;
#pragma unroll
        for (int kt = 0; kt < RKT; ++kt) {
            unsigned a0, a1, a2, a3;
            ldsm_x4(a0, a1, a2, a3, aAddr + kt * 32);
            uint4 q0 = permLane[kt * 2 + 0];
            uint4 q1 = permLane[kt * 2 + 1];
            asm volatile("mma.sync.aligned.m16n8k16.row.col.f32.f16.f16.f32 "
                         "{%0,%1,%2,%3},{%4,%5,%6,%7},{%8,%9},{%0,%1,%2,%3};"
                         : "+f"(acc[0][0]), "+f"(acc[0][1]), "+f"(acc[0][2]), "+f"(acc[0][3])
                         : "r"(a0), "r"(a1), "r"(a2), "r"(a3), "r"(q0.x), "r"(q0.y));
            asm volatile("mma.sync.aligned.m16n8k16.row.col.f32.f16.f16.f32 "
                         "{%0,%1,%2,%3},{%4,%5,%6,%7},{%8,%9},{%0,%1,%2,%3};"
                         : "+f"(acc[1][0]), "+f"(acc[1][1]), "+f"(acc[1][2]), "+f"(acc[1][3])
                         : "r"(a0), "r"(a1), "r"(a2), "r"(a3), "r"(q0.z), "r"(q0.w));
            asm volatile("mma.sync.aligned.m16n8k16.row.col.f32.f16.f16.f32 "
                         "{%0,%1,%2,%3},{%4,%5,%6,%7},{%8,%9},{%0,%1,%2,%3};"
                         : "+f"(acc[2][0]), "+f"(acc[2][1]), "+f"(acc[2][2]), "+f"(acc[2][3])
                         : "r"(a0), "r"(a1), "r"(a2), "r"(a3), "r"(q1.x), "r"(q1.y));
            asm volatile("mma.sync.aligned.m16n8k16.row.col.f32.f16.f16.f32 "
                         "{%0,%1,%2,%3},{%4,%5,%6,%7},{%8,%9},{%0,%1,%2,%3};"
                         : "+f"(acc[3][0]), "+f"(acc[3][1]), "+f"(acc[3][2]), "+f"(acc[3][3])
                         : "r"(a0), "r"(a1), "r"(a2), "r"(a3), "r"(q1.z), "r"(q1.w));
        }

        // elementwise
        const __half2* gaH = reinterpret_cast<const __half2*>(&gaV);
        const __half2* gbH = reinterpret_cast<const __half2*>(&gbV);
        bool valid = (s < Lsel);
        bool trig  = LAST_ONLY && (dir ? (s == 0) : (s == Lsel - 1));
#pragma unroll
        for (int nt = 0; nt < 4; ++nt) {
            float2 fa = __half22float2(gaH[nt]);
            float2 fb = __half22float2(gbH[nt]);
            float v0 = acc[nt][0] + fa.x;
            float v1 = acc[nt][1] + fa.y;
            float v2 = acc[nt][2] + fb.x;
            float v3 = acc[nt][3] + fb.y;
            float sx = par ? v0 : v2;
            float sy = par ? v1 : v3;
            __half2 snd = __floats2half2_rn(sx, sy);
            unsigned rcvu = __shfl_xor_sync(0xffffffff, *reinterpret_cast<unsigned*>(&snd), 1);
            __half2 rh = *reinterpret_cast<__half2*>(&rcvu);
            float px = par ? v2        : v0 * 0.5f;
            float py = par ? v3 * 0.5f : v1 * 0.5f;
            __half2 own2 = __floats2half2_rn(px, py);
            __half2 rsc  = __hmul2(rh, par ? sc_if : sc_go);
            __half2 hif = par ? rsc  : own2;
            __half2 hgo = par ? own2 : rsc;
            unsigned t1 = tanh2_fast(*reinterpret_cast<unsigned*>(&hif));
            unsigned t2 = tanh2_fast(*reinterpret_cast<unsigned*>(&hgo));
            float2 f1 = __half22float2(*reinterpret_cast<__half2*>(&t1));
            float2 f2 = __half22float2(*reinterpret_cast<__half2*>(&t2));
            float iv = 0.5f * f1.x + 0.5f;
            float fv = 0.5f * f1.y + 0.5f;
            float gv = f2.x;
            float ov = 0.5f * f2.y + 0.5f;
            float cn = fv * cst[nt] + iv * gv;
            float hn = ov * tanh_fast(cn);
            if (valid) { cst[nt] = cn; hst[nt] = hn; }

            // paired h-state store
            unsigned hbits = (unsigned)__half_as_ushort(__float2half(hst[nt]));
            unsigned partb = __shfl_xor_sync(0xffffffff, hbits, 2);
            if (b1 == 0) {
                int j0 = (warp << 3) + 2 * nt;
                if (j0 < HH) {
                    __half2 hp = __halves2half2(__ushort_as_half((unsigned short)hbits),
                                                __ushort_as_half((unsigned short)partb));
                    *reinterpret_cast<__half2*>(&h16[pp ^ 1][rowSel][j0]) = hp;
                }
            }
            if (LAST_ONLY && trig) {
                int j = jbase + 2 * nt;
                if (j < HH) outFS[pp][rowSel][j] = hn;
            }
        }
        gaV = gaN; gbV = gbN;
        __syncthreads();

        // writer warps
        if (LAST_ONLY) {
            if (warp < 16) {
                bool wtrig = dir ? (s == 0) : (s == Lw - 1);
                if (wtrig) {
                    float* dst = lastOut + (size_t)(b0 + warp) * DD + hoff;
                    const float* srcf = &outFS[pp][warp][0];
#pragma unroll
                    for (int i = lane; i < 150; i += 32) dst[i] = srcf[i];
                }
            }
        } else {
            if (warp < 16) {
                bool v = (s < Lw);
                int t = v ? (dir ? (Lw - 1 - s) : s) : s;
                const unsigned* srcu = reinterpret_cast<const unsigned*>(&h16[pp ^ 1][warp][0]);
                unsigned* dstu = reinterpret_cast<unsigned*>(wrRow + (size_t)t * KP);
#pragma unroll
                for (int i = lane; i < 75; i += 32) dstu[i] = v ? srcu[i] : 0u;
            }
        }
    }
}

__global__ void __launch_bounds__(608) k_lstm_l0() {
    lstm_mma_body<false>(g_gates, g_whhp0, g_a16, nullptr);
}
__global__ void __launch_bounds__(608) k_lstm_l1() {
    lstm_mma_body<true>(g_gates, g_whhp1, nullptr, g_last);
}

// ---------------- final FC layers -------------------------------------------------
__global__ void __launch_bounds__(320) k_fc1(const float* __restrict__ bias) {
    __shared__ float v[DD];
    int b = blockIdx.x, tid = threadIdx.x;
    const float* src = g_last + (size_t)b * DD;
    if (tid < DD) v[tid] = src[tid];
    __syncthreads();
    if (tid < DD) {
        float acc = bias[tid];
        for (int k = 0; k < DD; ++k) acc += v[k] * g_w1t[k * DD + tid];
        g_tmp[b * DD + tid] = tanhf(acc);
    }
}
__global__ void __launch_bounds__(320) k_fc2(const float* __restrict__ bias,
                                             float* __restrict__ out) {
    __shared__ float v[DD];
    int b = blockIdx.x, tid = threadIdx.x;
    if (tid < DD) v[tid] = g_tmp[b * DD + tid];
    __syncthreads();
    if (tid < DD) {
        float acc = bias[tid];
        for (int k = 0; k < DD; ++k) acc += v[k] * g_w2t[k * DD + tid];
        out[b * DD + tid] = acc;
    }
}

// ---------------- host --------------------------------------------------------------
extern "C" void kernel_launch(void* const* d_in, const int* in_sizes, int n_in,
                              void* d_out, int out_size) {
    const int*   x        = (const int*)  d_in[0];
    const int*   mask     = (const int*)  d_in[1];
    const float* emb      = (const float*)d_in[2];
    const float* Wih_l0f  = (const float*)d_in[3];
    const float* Whh_l0f  = (const float*)d_in[4];
    const float* b_l0f    = (const float*)d_in[5];
    const float* Wih_l0b  = (const float*)d_in[6];
    const float* Whh_l0b  = (const float*)d_in[7];
    const float* b_l0b    = (const float*)d_in[8];
    const float* Wih_l1f  = (const float*)d_in[9];
    const float* Whh_l1f  = (const float*)d_in[10];
    const float* b_l1f    = (const float*)d_in[11];
    const float* Wih_l1b  = (const float*)d_in[12];
    const float* Whh_l1b  = (const float*)d_in[13];
    const float* b_l1b    = (const float*)d_in[14];
    const float* W1       = (const float*)d_in[15];
    const float* b1       = (const float*)d_in[16];
    const float* W2       = (const float*)d_in[17];
    const float* b2       = (const float*)d_in[18];
    float* out = (float*)d_out;

    int mask64 = (in_sizes[1] != BB * SS) ? 1 : 0;

    dim3 sgrid(1520, 6);
    k_setup<<<sgrid, 256>>>(mask, mask64,
                            Wih_l0f, Wih_l0b, Wih_l1f, Wih_l1b,
                            Whh_l0f, Whh_l0b, Whh_l1f, Whh_l1b,
                            b_l0f, b_l0b, b_l1f, b_l1b, W1, W2);

    k_embed16<<<(BB * SS * 152 + 255) / 256, 256>>>(x, emb);

    dim3 g16((BB * SS) / 128, N2P / 128);

    k_gemm16_l0<<<g16, 256>>>();
    k_lstm_l0<<<128, 608>>>();

    k_gemm16_l1<<<g16, 256>>>();
    k_lstm_l1<<<128, 608>>>();

    k_fc1<<<BB, 320>>>(b1);
    k_fc2<<<BB, 320>>>(b2, out);
}

// round 14
// speedup vs baseline: 5.4574x; 1.0555x over previous
#include <cuda_runtime.h>
#include <cuda_fp16.h>
#include <math.h>
#include <stddef.h>

#define BB 1024
#define SS 256
#define DD 300
#define HH 150
#define G4 600     // 4*H
#define DGO 608    // per-dir gate region width (π-closed)
#define N2G 1216   // gates row width (2 dirs)
#define N2P 1280   // padded weight rows (guard-free GEMM loads)
#define KP 304     // input-GEMM K padded to 16
#define KT16 (KP / 16)

// recurrence tiling
#define RKT 10
#define RNW 19
#define HSTR 168
#define PERM_PER_DIR (RNW * 32 * 160)

// ---------------- device scratch ------------------------------------------------
__device__ __half g_a16  [(size_t)BB * SS * KP];
__device__ float  g_last [BB * DD];                // layer1 output at t=L-1 only
__device__ __half g_gates[(size_t)BB * SS * N2G];
__device__ __half g_w16_0[N2P * KP];
__device__ __half g_w16_1[N2P * KP];
__device__ __half g_whhp0[2 * PERM_PER_DIR];
__device__ __half g_whhp1[2 * PERM_PER_DIR];
__device__ float  g_bias0[N2P];
__device__ float  g_bias1[N2P];
__device__ float  g_w1t  [DD * DD];
__device__ float  g_w2t  [DD * DD];
__device__ float  g_tmp  [BB * DD];
__device__ int    g_len  [BB];

// gate-interleaved weight-row map: accumulator column m -> weight row
__device__ __forceinline__ int ilv_row(int m) { return (m & 3) * HH + (m >> 2); }
// in-32-block involution: swap (nt, q) bit-fields; memory col <-> accumulator col
__device__ __forceinline__ int pi32(int m) {
    return (m & ~31) | ((m & 6) << 2) | ((m >> 2) & 6) | (m & 1);
}

// ---------------- fused setup ----------------------------------------------------
__device__ __forceinline__ void perm_pack(const float* Wf, const float* Wb,
                                          __half* dst, int idx) {
    int dir = idx / PERM_PER_DIR;
    int rem = idx - dir * PERM_PER_DIR;
    int wl  = rem / 160;
    int r2  = rem - wl * 160;
    int w   = wl >> 5, l = wl & 31;
    int kt  = r2 >> 4;
    int r3  = r2 & 15;
    int p   = r3 >> 3;
    int r4  = r3 & 7;
    int ridx = r4 >> 1, h = r4 & 1;
    int m = w * 32 + (p * 2 + (ridx >> 1)) * 8 + (l >> 2);
    int k = kt * 16 + (l & 3) * 2 + (ridx & 1) * 8 + h;
    float v = 0.f;
    if (m < G4 && k < HH) {
        int row = ilv_row(m);
        v = dir ? Wb[row * HH + k] : Wf[row * HH + k];
    }
    dst[idx] = __float2half(v);
}

__global__ void k_setup(const int* __restrict__ mask, int mask64,
                        const float* __restrict__ Wih_l0f, const float* __restrict__ Wih_l0b,
                        const float* __restrict__ Wih_l1f, const float* __restrict__ Wih_l1b,
                        const float* __restrict__ Whh_l0f, const float* __restrict__ Whh_l0b,
                        const float* __restrict__ Whh_l1f, const float* __restrict__ Whh_l1b,
                        const float* __restrict__ b_l0f, const float* __restrict__ b_l0b,
                        const float* __restrict__ b_l1f, const float* __restrict__ b_l1b,
                        const float* __restrict__ W1, const float* __restrict__ W2) {
    int idx = blockIdx.x * blockDim.x + threadIdx.x;
    int task = blockIdx.y;
    if (task == 0) {
        if (idx < BB) {
            int c = 0;
            if (mask64) {
                const int* m = mask + (size_t)idx * SS * 2;
                for (int t = 0; t < SS; ++t) c += ((m[2 * t] | m[2 * t + 1]) != 0);
            } else {
                const int* m = mask + (size_t)idx * SS;
                for (int t = 0; t < SS; ++t) c += (m[t] != 0);
            }
            g_len[idx] = c;
        }
        if (idx < N2P) {
            float v0 = 0.f, v1 = 0.f;
            if (idx < N2G) {
                int dir = (idx >= DGO);
                int mm  = idx - dir * DGO;
                int ca  = pi32(mm);
                if (ca < G4) {
                    int row = ilv_row(ca);
                    v0 = dir ? b_l0b[row] : b_l0f[row];
                    v1 = dir ? b_l1b[row] : b_l1f[row];
                }
            }
            g_bias0[idx] = v0;
            g_bias1[idx] = v1;
        }
    } else if (task == 1 || task == 2) {       // pack Wih, π-permuted gate layout
        if (idx < N2P * KP) {
            int n = idx / KP, k = idx - n * KP;
            const float* Wf = (task == 1) ? Wih_l0f : Wih_l1f;
            const float* Wb = (task == 1) ? Wih_l0b : Wih_l1b;
            float v = 0.f;
            if (n < N2G && k < DD) {
                int dir = (n >= DGO);
                int mm  = n - dir * DGO;
                int ca  = pi32(mm);
                if (ca < G4) {
                    int row = ilv_row(ca);
                    v = dir ? Wb[row * DD + k] : Wf[row * DD + k];
                }
            }
            ((task == 1) ? g_w16_0 : g_w16_1)[idx] = __float2half(v);
        }
    } else if (task == 3) {
        if (idx < 2 * PERM_PER_DIR) perm_pack(Whh_l0f, Whh_l0b, g_whhp0, idx);
    } else if (task == 4) {
        if (idx < 2 * PERM_PER_DIR) perm_pack(Whh_l1f, Whh_l1b, g_whhp1, idx);
    } else {
        if (idx < DD * DD) {
            int r = idx / DD, c = idx - r * DD;
            g_w1t[c * DD + r] = W1[idx];
            g_w2t[c * DD + r] = W2[idx];
        }
    }
}

// ---------------- embedding gather -> fp16 A ------------------------------------
__global__ void k_embed16(const int* __restrict__ x, const float* __restrict__ emb) {
    int idx = blockIdx.x * blockDim.x + threadIdx.x;
    int bt = idx / 152;
    int c  = idx - bt * 152;
    int tok = x[bt];
    __half2 v = __floats2half2_rn(0.f, 0.f);
    if (c < 150 && tok != 0) {
        float2 f = reinterpret_cast<const float2*>(emb)[(size_t)tok * 150 + c];
        v = __floats2half2_rn(f.x, f.y);
    }
    reinterpret_cast<__half2*>(g_a16)[idx] = v;
}

// ---------------- helpers --------------------------------------------------------
__device__ __forceinline__ void cp16(unsigned dst, const void* src) {
    asm volatile("cp.async.cg.shared.global [%0], [%1], 16;\n" :: "r"(dst), "l"(src));
}
__device__ __forceinline__ void cp_commit() { asm volatile("cp.async.commit_group;\n"); }
__device__ __forceinline__ void cp_wait1()  { asm volatile("cp.async.wait_group 1;\n"); }
__device__ __forceinline__ void cp_wait0()  { asm volatile("cp.async.wait_group 0;\n"); }
__device__ __forceinline__ void ldsm_x4(unsigned& r0, unsigned& r1,
                                        unsigned& r2, unsigned& r3, unsigned addr) {
    asm volatile("ldmatrix.sync.aligned.m8n8.x4.shared.b16 {%0,%1,%2,%3}, [%4];"
                 : "=r"(r0), "=r"(r1), "=r"(r2), "=r"(r3) : "r"(addr));
}

// ---------------- input GEMM: cp.async 3-stage, 128x128x16, ldmatrix frags ------
__device__ __forceinline__ void gemm16_body(const __half* __restrict__ A,
                                            const __half* __restrict__ Bw,
                                            const float* __restrict__ biasv,
                                            __half* __restrict__ C) {
    __shared__ __half As[3][128][24];
    __shared__ __half Bs[3][128][24];
    int tid  = threadIdx.x;
    int m0   = blockIdx.x * 128;
    int n0   = blockIdx.y * 128;
    int warp = tid >> 5, lane = tid & 31;
    int wm = warp & 3, wn = warp >> 2;
    int l4 = lane >> 2, c2 = (lane & 3) * 2;
    int row = tid >> 1, chk = (tid & 1) * 8;

    const __half* Asrc = A + (size_t)(m0 + row) * KP + chk;
    const __half* Bsrc = Bw + (size_t)(n0 + row) * KP + chk;

    // ldmatrix lane addressing
    int aRow = wm * 32 + ((lane >> 3) & 1) * 8 + (lane & 7);   // + mi*16
    int aCol = (lane >> 4) * 8;
    int bRow = wn * 64 + ((lane >> 4) & 1) * 8 + (lane & 7);   // + ni2*16
    int bCol = ((lane >> 3) & 1) * 8;

    float acc[2][8][4];
#pragma unroll
    for (int i = 0; i < 2; ++i)
#pragma unroll
        for (int j = 0; j < 8; ++j)
#pragma unroll
            for (int q = 0; q < 4; ++q) acc[i][j][q] = 0.f;

#pragma unroll
    for (int p = 0; p < 2; ++p) {
        unsigned da = (unsigned)__cvta_generic_to_shared(&As[p][row][chk]);
        unsigned db = (unsigned)__cvta_generic_to_shared(&Bs[p][row][chk]);
        cp16(da, Asrc + p * 16);
        cp16(db, Bsrc + p * 16);
        cp_commit();
    }

    for (int kt = 0; kt < KT16; ++kt) {
        if (kt == KT16 - 1) cp_wait0(); else cp_wait1();
        __syncthreads();
        int st = kt % 3;
        if (kt + 2 < KT16) {
            int ns = (kt + 2) % 3;
            unsigned da = (unsigned)__cvta_generic_to_shared(&As[ns][row][chk]);
            unsigned db = (unsigned)__cvta_generic_to_shared(&Bs[ns][row][chk]);
            cp16(da, Asrc + (kt + 2) * 16);
            cp16(db, Bsrc + (kt + 2) * 16);
            cp_commit();
        }

        unsigned af[2][4];
#pragma unroll
        for (int mi = 0; mi < 2; ++mi) {
            unsigned addr = (unsigned)__cvta_generic_to_shared(&As[st][aRow + mi * 16][aCol]);
            ldsm_x4(af[mi][0], af[mi][1], af[mi][2], af[mi][3], addr);
        }
        unsigned bf[8][2];
#pragma unroll
        for (int nj = 0; nj < 4; ++nj) {
            unsigned addr = (unsigned)__cvta_generic_to_shared(&Bs[st][bRow + nj * 16][bCol]);
            ldsm_x4(bf[2 * nj][0], bf[2 * nj][1], bf[2 * nj + 1][0], bf[2 * nj + 1][1], addr);
        }
#pragma unroll
        for (int mi = 0; mi < 2; ++mi)
#pragma unroll
            for (int ni = 0; ni < 8; ++ni)
                asm volatile(
                    "mma.sync.aligned.m16n8k16.row.col.f32.f16.f16.f32 "
                    "{%0,%1,%2,%3},{%4,%5,%6,%7},{%8,%9},{%0,%1,%2,%3};"
                    : "+f"(acc[mi][ni][0]), "+f"(acc[mi][ni][1]),
                      "+f"(acc[mi][ni][2]), "+f"(acc[mi][ni][3])
                    : "r"(af[mi][0]), "r"(af[mi][1]), "r"(af[mi][2]), "r"(af[mi][3]),
                      "r"(bf[ni][0]), "r"(bf[ni][1]));
        // single barrier per iteration: the sync at the top of iteration kt+1
        // guarantees all reads of stage (kt)%3 complete before its reuse at kt+3.
    }

#pragma unroll
    for (int mi = 0; mi < 2; ++mi)
#pragma unroll
        for (int ni = 0; ni < 8; ++ni) {
            int m = m0 + wm * 32 + mi * 16 + l4;
            int n = n0 + wn * 64 + ni * 8 + c2;
            if (n < N2G) {
                float2 bv = *reinterpret_cast<const float2*>(&biasv[n]);
                __half2 h01 = __floats2half2_rn(acc[mi][ni][0] + bv.x, acc[mi][ni][1] + bv.y);
                __half2 h23 = __floats2half2_rn(acc[mi][ni][2] + bv.x, acc[mi][ni][3] + bv.y);
                *reinterpret_cast<__half2*>(C + (size_t)m * N2G + n)       = h01;
                *reinterpret_cast<__half2*>(C + (size_t)(m + 8) * N2G + n) = h23;
            }
        }
}

__global__ void __launch_bounds__(256) k_gemm16_l0() { gemm16_body(g_a16, g_w16_0, g_bias0, g_gates); }
__global__ void __launch_bounds__(256) k_gemm16_l1() { gemm16_body(g_a16, g_w16_1, g_bias1, g_gates); }

// ---------------- fast activations ----------------------------------------------
__device__ __forceinline__ float tanh_fast(float x) {
    float y; asm("tanh.approx.f32 %0, %1;" : "=f"(y) : "f"(x)); return y;
}
__device__ __forceinline__ unsigned tanh2_fast(unsigned x) {
    unsigned y; asm("tanh.approx.f16x2 %0, %1;" : "=r"(y) : "r"(x)); return y;
}

// ---------------- tensor-core persistent LSTM ------------------------------------
template <bool LAST_ONLY>
__device__ __forceinline__ void lstm_mma_body(const __half* __restrict__ Gt,
                                              const __half* __restrict__ permAll,
                                              __half* __restrict__ Hout,
                                              float* __restrict__ lastOut) {
    __shared__ __align__(16) __half h16[2][16][HSTR];
    __shared__ __align__(16) float  outFS[2][16][152];   // LAST_ONLY staging

    int tid  = threadIdx.x;
    int dir  = blockIdx.x & 1;
    int b0   = (blockIdx.x >> 1) * 16;
    int warp = tid >> 5, lane = tid & 31;
    int l4   = lane >> 2, q = lane & 3;
    int wbase = warp * 32;
    int goff = dir * DGO;
    int hoff = dir * HH;
    const uint4* permLane =
        reinterpret_cast<const uint4*>(permAll + (size_t)dir * PERM_PER_DIR) +
        (warp * 32 + lane) * 20;

    // ldmatrix lane source
    int rowL = ((lane >> 3) & 1) * 8 + (lane & 7);
    int colL = (lane >> 4) * 8;
    unsigned aBase = (unsigned)__cvta_generic_to_shared(&h16[0][rowL][colL]);
    const unsigned ppStride = 16 * HSTR * 2;   // bytes

    int LA = g_len[b0 + l4];
    int LB = g_len[b0 + l4 + 8];
    int par = lane & 1;
    int b1  = (lane >> 1) & 1;
    int rowSel = par ? (l4 + 8) : l4;
    int Lsel   = par ? LB : LA;
    int jbase  = (warp << 3) + b1;        // j = jbase + 2*nt

    // gate load bases (π layout: one uint4 per row-half covers all 4 nt)
    const __half* gBaseA = Gt + ((size_t)(b0 + l4)     * SS) * N2G + goff + wbase + q * 8;
    const __half* gBaseB = Gt + ((size_t)(b0 + l4 + 8) * SS) * N2G + goff + wbase + q * 8;

    int Lw = (warp < 16) ? g_len[b0 + warp] : 0;
    __half* wrRow = Hout + (size_t)(b0 + (warp < 16 ? warp : 0)) * SS * KP + hoff;

    const __half2 sc_if = __floats2half2_rn(0.5f, 0.5f);
    const __half2 sc_go = __floats2half2_rn(1.0f, 0.5f);

    float cst[4] = {0.f, 0.f, 0.f, 0.f};
    float hst[4] = {0.f, 0.f, 0.f, 0.f};

    for (int i = tid; i < 2 * 16 * HSTR; i += blockDim.x)
        (&h16[0][0][0])[i] = __float2half(0.f);

    // prologue: load gates for step 0
    uint4 gaV, gbV;
    {
        int tA0 = (0 < LA) ? (dir ? (LA - 1) : 0) : 0;
        int tB0 = (0 < LB) ? (dir ? (LB - 1) : 0) : 0;
        gaV = *reinterpret_cast<const uint4*>(gBaseA + (size_t)tA0 * N2G);
        gbV = *reinterpret_cast<const uint4*>(gBaseB + (size_t)tB0 * N2G);
    }
    __syncthreads();

    for (int s = 0; s < SS; ++s) {
        int pp = s & 1;

        // prefetch gates for step s+1
        uint4 gaN, gbN;
        {
            int s1 = s + 1;
            int tA1 = (s1 < LA) ? (dir ? (LA - 1 - s1) : s1) : ((s1 < SS) ? s1 : 0);
            int tB1 = (s1 < LB) ? (dir ? (LB - 1 - s1) : s1) : ((s1 < SS) ? s1 : 0);
            gaN = *reinterpret_cast<const uint4*>(gBaseA + (size_t)tA1 * N2G);
            gbN = *reinterpret_cast<const uint4*>(gBaseB + (size_t)tB1 * N2G);
        }

        // MMA
        float acc[4][4];
#pragma unroll
        for (int nt = 0; nt < 4; ++nt)
#pragma unroll
            for (int r = 0; r < 4; ++r) acc[nt][r] = 0.f;

        unsigned aAddr = aBase + (unsigned)pp * ppStride;
#pragma unroll
        for (int kt = 0; kt < RKT; ++kt) {
            unsigned a0, a1, a2, a3;
            ldsm_x4(a0, a1, a2, a3, aAddr + kt * 32);
            uint4 q0 = permLane[kt * 2 + 0];
            uint4 q1 = permLane[kt * 2 + 1];
            asm volatile("mma.sync.aligned.m16n8k16.row.col.f32.f16.f16.f32 "
                         "{%0,%1,%2,%3},{%4,%5,%6,%7},{%8,%9},{%0,%1,%2,%3};"
                         : "+f"(acc[0][0]), "+f"(acc[0][1]), "+f"(acc[0][2]), "+f"(acc[0][3])
                         : "r"(a0), "r"(a1), "r"(a2), "r"(a3), "r"(q0.x), "r"(q0.y));
            asm volatile("mma.sync.aligned.m16n8k16.row.col.f32.f16.f16.f32 "
                         "{%0,%1,%2,%3},{%4,%5,%6,%7},{%8,%9},{%0,%1,%2,%3};"
                         : "+f"(acc[1][0]), "+f"(acc[1][1]), "+f"(acc[1][2]), "+f"(acc[1][3])
                         : "r"(a0), "r"(a1), "r"(a2), "r"(a3), "r"(q0.z), "r"(q0.w));
            asm volatile("mma.sync.aligned.m16n8k16.row.col.f32.f16.f16.f32 "
                         "{%0,%1,%2,%3},{%4,%5,%6,%7},{%8,%9},{%0,%1,%2,%3};"
                         : "+f"(acc[2][0]), "+f"(acc[2][1]), "+f"(acc[2][2]), "+f"(acc[2][3])
                         : "r"(a0), "r"(a1), "r"(a2), "r"(a3), "r"(q1.x), "r"(q1.y));
            asm volatile("mma.sync.aligned.m16n8k16.row.col.f32.f16.f16.f32 "
                         "{%0,%1,%2,%3},{%4,%5,%6,%7},{%8,%9},{%0,%1,%2,%3};"
                         : "+f"(acc[3][0]), "+f"(acc[3][1]), "+f"(acc[3][2]), "+f"(acc[3][3])
                         : "r"(a0), "r"(a1), "r"(a2), "r"(a3), "r"(q1.z), "r"(q1.w));
        }

        // elementwise
        const __half2* gaH = reinterpret_cast<const __half2*>(&gaV);
        const __half2* gbH = reinterpret_cast<const __half2*>(&gbV);
        bool valid = (s < Lsel);
        bool trig  = LAST_ONLY && (dir ? (s == 0) : (s == Lsel - 1));
#pragma unroll
        for (int nt = 0; nt < 4; ++nt) {
            float2 fa = __half22float2(gaH[nt]);
            float2 fb = __half22float2(gbH[nt]);
            float v0 = acc[nt][0] + fa.x;
            float v1 = acc[nt][1] + fa.y;
            float v2 = acc[nt][2] + fb.x;
            float v3 = acc[nt][3] + fb.y;
            float sx = par ? v0 : v2;
            float sy = par ? v1 : v3;
            __half2 snd = __floats2half2_rn(sx, sy);
            unsigned rcvu = __shfl_xor_sync(0xffffffff, *reinterpret_cast<unsigned*>(&snd), 1);
            __half2 rh = *reinterpret_cast<__half2*>(&rcvu);
            float px = par ? v2        : v0 * 0.5f;
            float py = par ? v3 * 0.5f : v1 * 0.5f;
            __half2 own2 = __floats2half2_rn(px, py);
            __half2 rsc  = __hmul2(rh, par ? sc_if : sc_go);
            __half2 hif = par ? rsc  : own2;
            __half2 hgo = par ? own2 : rsc;
            unsigned t1 = tanh2_fast(*reinterpret_cast<unsigned*>(&hif));
            unsigned t2 = tanh2_fast(*reinterpret_cast<unsigned*>(&hgo));
            float2 f1 = __half22float2(*reinterpret_cast<__half2*>(&t1));
            float2 f2 = __half22float2(*reinterpret_cast<__half2*>(&t2));
            float iv = 0.5f * f1.x + 0.5f;
            float fv = 0.5f * f1.y + 0.5f;
            float gv = f2.x;
            float ov = 0.5f * f2.y + 0.5f;
            float cn = fv * cst[nt] + iv * gv;
            float hn = ov * tanh_fast(cn);
            if (valid) { cst[nt] = cn; hst[nt] = hn; }

            // paired h-state store
            unsigned hbits = (unsigned)__half_as_ushort(__float2half(hst[nt]));
            unsigned partb = __shfl_xor_sync(0xffffffff, hbits, 2);
            if (b1 == 0) {
                int j0 = (warp << 3) + 2 * nt;
                if (j0 < HH) {
                    __half2 hp = __halves2half2(__ushort_as_half((unsigned short)hbits),
                                                __ushort_as_half((unsigned short)partb));
                    *reinterpret_cast<__half2*>(&h16[pp ^ 1][rowSel][j0]) = hp;
                }
            }
            if (LAST_ONLY && trig) {
                int j = jbase + 2 * nt;
                if (j < HH) outFS[pp][rowSel][j] = hn;
            }
        }
        gaV = gaN; gbV = gbN;
        __syncthreads();

        // writer warps
        if (LAST_ONLY) {
            if (warp < 16) {
                bool wtrig = dir ? (s == 0) : (s == Lw - 1);
                if (wtrig) {
                    float* dst = lastOut + (size_t)(b0 + warp) * DD + hoff;
                    const float* srcf = &outFS[pp][warp][0];
#pragma unroll
                    for (int i = lane; i < 150; i += 32) dst[i] = srcf[i];
                }
            }
        } else {
            if (warp < 16) {
                bool v = (s < Lw);
                int t = v ? (dir ? (Lw - 1 - s) : s) : s;
                const unsigned* srcu = reinterpret_cast<const unsigned*>(&h16[pp ^ 1][warp][0]);
                unsigned* dstu = reinterpret_cast<unsigned*>(wrRow + (size_t)t * KP);
#pragma unroll
                for (int i = lane; i < 75; i += 32) dstu[i] = v ? srcu[i] : 0u;
            }
        }
    }
}

__global__ void __launch_bounds__(608) k_lstm_l0() {
    lstm_mma_body<false>(g_gates, g_whhp0, g_a16, nullptr);
}
__global__ void __launch_bounds__(608) k_lstm_l1() {
    lstm_mma_body<true>(g_gates, g_whhp1, nullptr, g_last);
}

// ---------------- final FC layers -------------------------------------------------
__global__ void __launch_bounds__(320) k_fc1(const float* __restrict__ bias) {
    __shared__ float v[DD];
    int b = blockIdx.x, tid = threadIdx.x;
    const float* src = g_last + (size_t)b * DD;
    if (tid < DD) v[tid] = src[tid];
    __syncthreads();
    if (tid < DD) {
        float acc = bias[tid];
        for (int k = 0; k < DD; ++k) acc += v[k] * g_w1t[k * DD + tid];
        g_tmp[b * DD + tid] = tanhf(acc);
    }
}
__global__ void __launch_bounds__(320) k_fc2(const float* __restrict__ bias,
                                             float* __restrict__ out) {
    __shared__ float v[DD];
    int b = blockIdx.x, tid = threadIdx.x;
    if (tid < DD) v[tid] = g_tmp[b * DD + tid];
    __syncthreads();
    if (tid < DD) {
        float acc = bias[tid];
        for (int k = 0; k < DD; ++k) acc += v[k] * g_w2t[k * DD + tid];
        out[b * DD + tid] = acc;
    }
}

// ---------------- host --------------------------------------------------------------
extern "C" void kernel_launch(void* const* d_in, const int* in_sizes, int n_in,
                              void* d_out, int out_size) {
    const int*   x        = (const int*)  d_in[0];
    const int*   mask     = (const int*)  d_in[1];
    const float* emb      = (const float*)d_in[2];
    const float* Wih_l0f  = (const float*)d_in[3];
    const float* Whh_l0f  = (const float*)d_in[4];
    const float* b_l0f    = (const float*)d_in[5];
    const float* Wih_l0b  = (const float*)d_in[6];
    const float* Whh_l0b  = (const float*)d_in[7];
    const float* b_l0b    = (const float*)d_in[8];
    const float* Wih_l1f  = (const float*)d_in[9];
    const float* Whh_l1f  = (const float*)d_in[10];
    const float* b_l1f    = (const float*)d_in[11];
    const float* Wih_l1b  = (const float*)d_in[12];
    const float* Whh_l1b  = (const float*)d_in[13];
    const float* b_l1b    = (const float*)d_in[14];
    const float* W1       = (const float*)d_in[15];
    const float* b1       = (const float*)d_in[16];
    const float* W2       = (const float*)d_in[17];
    const float* b2       = (const float*)d_in[18];
    float* out = (float*)d_out;

    int mask64 = (in_sizes[1] != BB * SS) ? 1 : 0;

    dim3 sgrid(1520, 6);
    k_setup<<<sgrid, 256>>>(mask, mask64,
                            Wih_l0f, Wih_l0b, Wih_l1f, Wih_l1b,
                            Whh_l0f, Whh_l0b, Whh_l1f, Whh_l1b,
                            b_l0f, b_l0b, b_l1f, b_l1b, W1, W2);

    k_embed16<<<(BB * SS * 152 + 255) / 256, 256>>>(x, emb);

    dim3 g16((BB * SS) / 128, N2P / 128);

    k_gemm16_l0<<<g16, 256>>>();
    k_lstm_l0<<<128, 608>>>();

    k_gemm16_l1<<<g16, 256>>>();
    k_lstm_l1<<<128, 608>>>();

    k_fc1<<<BB, 320>>>(b1);
    k_fc2<<<BB, 320>>>(b2, out);
}

// round 15
// speedup vs baseline: 6.4359x; 1.1793x over previous
#include <cuda_runtime.h>
#include <cuda_fp16.h>
#include <math.h>
#include <stddef.h>

#define BB 1024
#define SS 256
#define DD 300
#define HH 150
#define G4 600     // 4*H
#define DGO 608    // per-dir gate region width (π-closed)
#define N2G 1216   // gates row width (2 dirs)
#define N2P 1280   // padded weight rows
#define KP 304     // input-GEMM K padded to 16
#define KT16 (KP / 16)

// recurrence tiling
#define RKT 10
#define RNW 19
#define HSTR 168
#define PERM_PER_DIR (RNW * 32 * 160)

// ---------------- device scratch ------------------------------------------------
__device__ __half g_a16  [(size_t)BB * SS * KP];      // compacted rows
__device__ float  g_last [BB * DD];
__device__ __half g_gates[(size_t)BB * SS * N2G];     // compacted rows
__device__ __half g_w16_0[N2P * KP];
__device__ __half g_w16_1[N2P * KP];
__device__ __half g_whhp0[2 * PERM_PER_DIR];
__device__ __half g_whhp1[2 * PERM_PER_DIR];
__device__ float  g_bias0[N2P];
__device__ float  g_bias1[N2P];
__device__ float  g_w1t  [DD * DD];
__device__ float  g_w2t  [DD * DD];
__device__ float  g_tmp  [BB * DD];
__device__ int    g_len  [BB];
__device__ int    g_perm [BB];        // sorted (ascending length) batch order
__device__ int    g_rowstart[BB];     // batch row -> first compacted row
__device__ int    g_rowmap[BB * SS];  // compacted row -> (b<<8)|t
__device__ int    g_mc[2];            // [0]=Mc, [1]=Mc padded to 128

__device__ __forceinline__ int ilv_row(int m) { return (m & 3) * HH + (m >> 2); }
__device__ __forceinline__ int pi32(int m) {
    return (m & ~31) | ((m & 6) << 2) | ((m >> 2) & 6) | (m & 1);
}

// ---------------- fused setup ----------------------------------------------------
__device__ __forceinline__ void perm_pack(const float* Wf, const float* Wb,
                                          __half* dst, int idx) {
    int dir = idx / PERM_PER_DIR;
    int rem = idx - dir * PERM_PER_DIR;
    int wl  = rem / 160;
    int r2  = rem - wl * 160;
    int w   = wl >> 5, l = wl & 31;
    int kt  = r2 >> 4;
    int r3  = r2 & 15;
    int p   = r3 >> 3;
    int r4  = r3 & 7;
    int ridx = r4 >> 1, h = r4 & 1;
    int m = w * 32 + (p * 2 + (ridx >> 1)) * 8 + (l >> 2);
    int k = kt * 16 + (l & 3) * 2 + (ridx & 1) * 8 + h;
    float v = 0.f;
    if (m < G4 && k < HH) {
        int row = ilv_row(m);
        v = dir ? Wb[row * HH + k] : Wf[row * HH + k];
    }
    dst[idx] = __float2half(v);
}

__global__ void k_setup(const int* __restrict__ mask, int mask64,
                        const float* __restrict__ Wih_l0f, const float* __restrict__ Wih_l0b,
                        const float* __restrict__ Wih_l1f, const float* __restrict__ Wih_l1b,
                        const float* __restrict__ Whh_l0f, const float* __restrict__ Whh_l0b,
                        const float* __restrict__ Whh_l1f, const float* __restrict__ Whh_l1b,
                        const float* __restrict__ b_l0f, const float* __restrict__ b_l0b,
                        const float* __restrict__ b_l1f, const float* __restrict__ b_l1b,
                        const float* __restrict__ W1, const float* __restrict__ W2) {
    int idx = blockIdx.x * blockDim.x + threadIdx.x;
    int task = blockIdx.y;
    if (task == 0) {
        if (idx < BB) {
            int c = 0;
            if (mask64) {
                const int* m = mask + (size_t)idx * SS * 2;
                for (int t = 0; t < SS; ++t) c += ((m[2 * t] | m[2 * t + 1]) != 0);
            } else {
                const int* m = mask + (size_t)idx * SS;
                for (int t = 0; t < SS; ++t) c += (m[t] != 0);
            }
            g_len[idx] = c;
        }
        if (idx < N2P) {
            float v0 = 0.f, v1 = 0.f;
            if (idx < N2G) {
                int dir = (idx >= DGO);
                int mm  = idx - dir * DGO;
                int ca  = pi32(mm);
                if (ca < G4) {
                    int row = ilv_row(ca);
                    v0 = dir ? b_l0b[row] : b_l0f[row];
                    v1 = dir ? b_l1b[row] : b_l1f[row];
                }
            }
            g_bias0[idx] = v0;
            g_bias1[idx] = v1;
        }
    } else if (task == 1 || task == 2) {
        if (idx < N2P * KP) {
            int n = idx / KP, k = idx - n * KP;
            const float* Wf = (task == 1) ? Wih_l0f : Wih_l1f;
            const float* Wb = (task == 1) ? Wih_l0b : Wih_l1b;
            float v = 0.f;
            if (n < N2G && k < DD) {
                int dir = (n >= DGO);
                int mm  = n - dir * DGO;
                int ca  = pi32(mm);
                if (ca < G4) {
                    int row = ilv_row(ca);
                    v = dir ? Wb[row * DD + k] : Wf[row * DD + k];
                }
            }
            ((task == 1) ? g_w16_0 : g_w16_1)[idx] = __float2half(v);
        }
    } else if (task == 3) {
        if (idx < 2 * PERM_PER_DIR) perm_pack(Whh_l0f, Whh_l0b, g_whhp0, idx);
    } else if (task == 4) {
        if (idx < 2 * PERM_PER_DIR) perm_pack(Whh_l1f, Whh_l1b, g_whhp1, idx);
    } else {
        if (idx < DD * DD) {
            int r = idx / DD, c = idx - r * DD;
            g_w1t[c * DD + r] = W1[idx];
            g_w2t[c * DD + r] = W2[idx];
        }
    }
}

// ---------------- length sort + row compaction maps -------------------------------
__global__ void k_sort() {
    int tid = threadIdx.x;
    if (tid == 0) {
        int off[257];
        for (int i = 0; i <= 256; ++i) off[i] = 0;
        for (int b = 0; b < BB; ++b) off[g_len[b]]++;
        int run = 0;
        for (int l = 0; l <= 256; ++l) { int h = off[l]; off[l] = run; run += h; }
        for (int b = 0; b < BB; ++b) {
            int l = g_len[b];
            g_perm[off[l]++] = b;
        }
        int rs = 0;
        for (int p = 0; p < BB; ++p) {
            int b = g_perm[p];
            g_rowstart[b] = rs;
            rs += g_len[b];
        }
        g_mc[0] = rs;
        g_mc[1] = (rs + 127) & ~127;
    }
    __syncthreads();
    for (int p = tid; p < BB; p += blockDim.x) {
        int b = g_perm[p];
        int s0 = g_rowstart[b];
        int L = g_len[b];
        for (int t = 0; t < L; ++t) g_rowmap[s0 + t] = (b << 8) | t;
    }
}

// ---------------- embedding gather -> compacted fp16 A ----------------------------
__global__ void k_embed16(const int* __restrict__ x, const float* __restrict__ emb) {
    int idx = blockIdx.x * blockDim.x + threadIdx.x;
    int r = idx / 152;
    if (r >= g_mc[0]) return;
    int c = idx - r * 152;
    int bt = g_rowmap[r];
    int b = bt >> 8, t = bt & 255;
    int tok = x[b * SS + t];
    __half2 v = __floats2half2_rn(0.f, 0.f);
    if (c < 150 && tok != 0) {
        float2 f = reinterpret_cast<const float2*>(emb)[(size_t)tok * 150 + c];
        v = __floats2half2_rn(f.x, f.y);
    }
    reinterpret_cast<__half2*>(g_a16)[(size_t)r * 152 + c] = v;
}

// ---------------- helpers ----------------------------------------------------------
__device__ __forceinline__ void cp16(unsigned dst, const void* src) {
    asm volatile("cp.async.cg.shared.global [%0], [%1], 16;\n" :: "r"(dst), "l"(src));
}
__device__ __forceinline__ void cp_commit() { asm volatile("cp.async.commit_group;\n"); }
__device__ __forceinline__ void cp_wait1()  { asm volatile("cp.async.wait_group 1;\n"); }
__device__ __forceinline__ void cp_wait0()  { asm volatile("cp.async.wait_group 0;\n"); }
__device__ __forceinline__ void ldsm_x4(unsigned& r0, unsigned& r1,
                                        unsigned& r2, unsigned& r3, unsigned addr) {
    asm volatile("ldmatrix.sync.aligned.m8n8.x4.shared.b16 {%0,%1,%2,%3}, [%4];"
                 : "=r"(r0), "=r"(r1), "=r"(r2), "=r"(r3) : "r"(addr));
}

// ---------------- input GEMM (compacted M, early-exit past Mc_pad) -----------------
__device__ __forceinline__ void gemm16_body(const __half* __restrict__ A,
                                            const __half* __restrict__ Bw,
                                            const float* __restrict__ biasv,
                                            __half* __restrict__ C) {
    int m0 = blockIdx.x * 128;
    if (m0 >= g_mc[1]) return;

    __shared__ __half As[3][128][24];
    __shared__ __half Bs[3][128][24];
    int tid  = threadIdx.x;
    int n0   = blockIdx.y * 128;
    int warp = tid >> 5, lane = tid & 31;
    int wm = warp & 3, wn = warp >> 2;
    int l4 = lane >> 2, c2 = (lane & 3) * 2;
    int row = tid >> 1, chk = (tid & 1) * 8;

    const __half* Asrc = A + (size_t)(m0 + row) * KP + chk;
    const __half* Bsrc = Bw + (size_t)(n0 + row) * KP + chk;

    int aRow = wm * 32 + ((lane >> 3) & 1) * 8 + (lane & 7);
    int aCol = (lane >> 4) * 8;
    int bRow = wn * 64 + ((lane >> 4) & 1) * 8 + (lane & 7);
    int bCol = ((lane >> 3) & 1) * 8;

    float acc[2][8][4];
#pragma unroll
    for (int i = 0; i < 2; ++i)
#pragma unroll
        for (int j = 0; j < 8; ++j)
#pragma unroll
            for (int q = 0; q < 4; ++q) acc[i][j][q] = 0.f;

#pragma unroll
    for (int p = 0; p < 2; ++p) {
        unsigned da = (unsigned)__cvta_generic_to_shared(&As[p][row][chk]);
        unsigned db = (unsigned)__cvta_generic_to_shared(&Bs[p][row][chk]);
        cp16(da, Asrc + p * 16);
        cp16(db, Bsrc + p * 16);
        cp_commit();
    }

    for (int kt = 0; kt < KT16; ++kt) {
        if (kt == KT16 - 1) cp_wait0(); else cp_wait1();
        __syncthreads();
        int st = kt % 3;
        if (kt + 2 < KT16) {
            int ns = (kt + 2) % 3;
            unsigned da = (unsigned)__cvta_generic_to_shared(&As[ns][row][chk]);
            unsigned db = (unsigned)__cvta_generic_to_shared(&Bs[ns][row][chk]);
            cp16(da, Asrc + (kt + 2) * 16);
            cp16(db, Bsrc + (kt + 2) * 16);
            cp_commit();
        }

        unsigned af[2][4];
#pragma unroll
        for (int mi = 0; mi < 2; ++mi) {
            unsigned addr = (unsigned)__cvta_generic_to_shared(&As[st][aRow + mi * 16][aCol]);
            ldsm_x4(af[mi][0], af[mi][1], af[mi][2], af[mi][3], addr);
        }
        unsigned bf[8][2];
#pragma unroll
        for (int nj = 0; nj < 4; ++nj) {
            unsigned addr = (unsigned)__cvta_generic_to_shared(&Bs[st][bRow + nj * 16][bCol]);
            ldsm_x4(bf[2 * nj][0], bf[2 * nj][1], bf[2 * nj + 1][0], bf[2 * nj + 1][1], addr);
        }
#pragma unroll
        for (int mi = 0; mi < 2; ++mi)
#pragma unroll
            for (int ni = 0; ni < 8; ++ni)
                asm volatile(
                    "mma.sync.aligned.m16n8k16.row.col.f32.f16.f16.f32 "
                    "{%0,%1,%2,%3},{%4,%5,%6,%7},{%8,%9},{%0,%1,%2,%3};"
                    : "+f"(acc[mi][ni][0]), "+f"(acc[mi][ni][1]),
                      "+f"(acc[mi][ni][2]), "+f"(acc[mi][ni][3])
                    : "r"(af[mi][0]), "r"(af[mi][1]), "r"(af[mi][2]), "r"(af[mi][3]),
                      "r"(bf[ni][0]), "r"(bf[ni][1]));
    }

#pragma unroll
    for (int mi = 0; mi < 2; ++mi)
#pragma unroll
        for (int ni = 0; ni < 8; ++ni) {
            int m = m0 + wm * 32 + mi * 16 + l4;
            int n = n0 + wn * 64 + ni * 8 + c2;
            if (n < N2G) {
                float2 bv = *reinterpret_cast<const float2*>(&biasv[n]);
                __half2 h01 = __floats2half2_rn(acc[mi][ni][0] + bv.x, acc[mi][ni][1] + bv.y);
                __half2 h23 = __floats2half2_rn(acc[mi][ni][2] + bv.x, acc[mi][ni][3] + bv.y);
                *reinterpret_cast<__half2*>(C + (size_t)m * N2G + n)       = h01;
                *reinterpret_cast<__half2*>(C + (size_t)(m + 8) * N2G + n) = h23;
            }
        }
}

__global__ void __launch_bounds__(256) k_gemm16_l0() { gemm16_body(g_a16, g_w16_0, g_bias0, g_gates); }
__global__ void __launch_bounds__(256) k_gemm16_l1() { gemm16_body(g_a16, g_w16_1, g_bias1, g_gates); }

// ---------------- fast activations ----------------------------------------------
__device__ __forceinline__ float tanh_fast(float x) {
    float y; asm("tanh.approx.f32 %0, %1;" : "=f"(y) : "f"(x)); return y;
}
__device__ __forceinline__ unsigned tanh2_fast(unsigned x) {
    unsigned y; asm("tanh.approx.f16x2 %0, %1;" : "=r"(y) : "r"(x)); return y;
}

// ---------------- tensor-core persistent LSTM (sorted groups, early exit) ---------
template <bool LAST_ONLY>
__device__ __forceinline__ void lstm_mma_body(const __half* __restrict__ Gt,
                                              const __half* __restrict__ permAll,
                                              __half* __restrict__ Hout,
                                              float* __restrict__ lastOut) {
    __shared__ __align__(16) __half h16[2][16][HSTR];
    __shared__ __align__(16) float  outFS[2][16][152];

    int tid  = threadIdx.x;
    int dir  = blockIdx.x & 1;
    int b0   = (blockIdx.x >> 1) * 16;     // sorted-position group base
    int warp = tid >> 5, lane = tid & 31;
    int l4   = lane >> 2, q = lane & 3;
    int wbase = warp * 32;
    int goff = dir * DGO;
    int hoff = dir * HH;
    const uint4* permLane =
        reinterpret_cast<const uint4*>(permAll + (size_t)dir * PERM_PER_DIR) +
        (warp * 32 + lane) * 20;

    int rowL = ((lane >> 3) & 1) * 8 + (lane & 7);
    int colL = (lane >> 4) * 8;
    unsigned aBase = (unsigned)__cvta_generic_to_shared(&h16[0][rowL][colL]);
    const unsigned ppStride = 16 * HSTR * 2;

    int pA = g_perm[b0 + l4];
    int pB = g_perm[b0 + l4 + 8];
    int LA = g_len[pA];
    int LB = g_len[pB];
    int Lmax = g_len[g_perm[b0 + 15]];     // ascending sort: last is max
    int par = lane & 1;
    int b1  = (lane >> 1) & 1;
    int rowSel = par ? (l4 + 8) : l4;
    int Lsel   = par ? LB : LA;
    int jbase  = (warp << 3) + b1;

    const __half* gBaseA = Gt + (size_t)g_rowstart[pA] * N2G + goff + wbase + q * 8;
    const __half* gBaseB = Gt + (size_t)g_rowstart[pB] * N2G + goff + wbase + q * 8;

    int bw = (warp < 16) ? g_perm[b0 + warp] : 0;
    int Lw = (warp < 16) ? g_len[bw] : 0;
    __half* wrBase = Hout ? (Hout + (size_t)g_rowstart[bw] * KP + hoff) : (__half*)0;

    const __half2 sc_if = __floats2half2_rn(0.5f, 0.5f);
    const __half2 sc_go = __floats2half2_rn(1.0f, 0.5f);

    float cst[4] = {0.f, 0.f, 0.f, 0.f};
    float hst[4] = {0.f, 0.f, 0.f, 0.f};

    for (int i = tid; i < 2 * 16 * HSTR; i += blockDim.x)
        (&h16[0][0][0])[i] = __float2half(0.f);

    uint4 gaV, gbV;
    {
        int tA0 = dir ? (LA - 1) : 0;
        int tB0 = dir ? (LB - 1) : 0;
        gaV = *reinterpret_cast<const uint4*>(gBaseA + (size_t)tA0 * N2G);
        gbV = *reinterpret_cast<const uint4*>(gBaseB + (size_t)tB0 * N2G);
    }
    __syncthreads();

    for (int s = 0; s < Lmax; ++s) {
        int pp = s & 1;

        // prefetch gates for step s+1 (invalid rows -> t=0, safe & unused)
        uint4 gaN, gbN;
        {
            int s1 = s + 1;
            int tA1 = (s1 < LA) ? (dir ? (LA - 1 - s1) : s1) : 0;
            int tB1 = (s1 < LB) ? (dir ? (LB - 1 - s1) : s1) : 0;
            gaN = *reinterpret_cast<const uint4*>(gBaseA + (size_t)tA1 * N2G);
            gbN = *reinterpret_cast<const uint4*>(gBaseB + (size_t)tB1 * N2G);
        }

        // MMA
        float acc[4][4];
#pragma unroll
        for (int nt = 0; nt < 4; ++nt)
#pragma unroll
            for (int r = 0; r < 4; ++r) acc[nt][r] = 0.f;

        unsigned aAddr = aBase + (unsigned)pp * ppStride;
#pragma unroll
        for (int kt = 0; kt < RKT; ++kt) {
            unsigned a0, a1, a2, a3;
            ldsm_x4(a0, a1, a2, a3, aAddr + kt * 32);
            uint4 q0 = permLane[kt * 2 + 0];
            uint4 q1 = permLane[kt * 2 + 1];
            asm volatile("mma.sync.aligned.m16n8k16.row.col.f32.f16.f16.f32 "
                         "{%0,%1,%2,%3},{%4,%5,%6,%7},{%8,%9},{%0,%1,%2,%3};"
                         : "+f"(acc[0][0]), "+f"(acc[0][1]), "+f"(acc[0][2]), "+f"(acc[0][3])
                         : "r"(a0), "r"(a1), "r"(a2), "r"(a3), "r"(q0.x), "r"(q0.y));
            asm volatile("mma.sync.aligned.m16n8k16.row.col.f32.f16.f16.f32 "
                         "{%0,%1,%2,%3},{%4,%5,%6,%7},{%8,%9},{%0,%1,%2,%3};"
                         : "+f"(acc[1][0]), "+f"(acc[1][1]), "+f"(acc[1][2]), "+f"(acc[1][3])
                         : "r"(a0), "r"(a1), "r"(a2), "r"(a3), "r"(q0.z), "r"(q0.w));
            asm volatile("mma.sync.aligned.m16n8k16.row.col.f32.f16.f16.f32 "
                         "{%0,%1,%2,%3},{%4,%5,%6,%7},{%8,%9},{%0,%1,%2,%3};"
                         : "+f"(acc[2][0]), "+f"(acc[2][1]), "+f"(acc[2][2]), "+f"(acc[2][3])
                         : "r"(a0), "r"(a1), "r"(a2), "r"(a3), "r"(q1.x), "r"(q1.y));
            asm volatile("mma.sync.aligned.m16n8k16.row.col.f32.f16.f16.f32 "
                         "{%0,%1,%2,%3},{%4,%5,%6,%7},{%8,%9},{%0,%1,%2,%3};"
                         : "+f"(acc[3][0]), "+f"(acc[3][1]), "+f"(acc[3][2]), "+f"(acc[3][3])
                         : "r"(a0), "r"(a1), "r"(a2), "r"(a3), "r"(q1.z), "r"(q1.w));
        }

        // elementwise
        const __half2* gaH = reinterpret_cast<const __half2*>(&gaV);
        const __half2* gbH = reinterpret_cast<const __half2*>(&gbV);
        bool valid = (s < Lsel);
        bool trig  = LAST_ONLY && (dir ? (s == 0) : (s == Lsel - 1));
#pragma unroll
        for (int nt = 0; nt < 4; ++nt) {
            float2 fa = __half22float2(gaH[nt]);
            float2 fb = __half22float2(gbH[nt]);
            float v0 = acc[nt][0] + fa.x;
            float v1 = acc[nt][1] + fa.y;
            float v2 = acc[nt][2] + fb.x;
            float v3 = acc[nt][3] + fb.y;
            float sx = par ? v0 : v2;
            float sy = par ? v1 : v3;
            __half2 snd = __floats2half2_rn(sx, sy);
            unsigned rcvu = __shfl_xor_sync(0xffffffff, *reinterpret_cast<unsigned*>(&snd), 1);
            __half2 rh = *reinterpret_cast<__half2*>(&rcvu);
            float px = par ? v2        : v0 * 0.5f;
            float py = par ? v3 * 0.5f : v1 * 0.5f;
            __half2 own2 = __floats2half2_rn(px, py);
            __half2 rsc  = __hmul2(rh, par ? sc_if : sc_go);
            __half2 hif = par ? rsc  : own2;
            __half2 hgo = par ? own2 : rsc;
            unsigned t1 = tanh2_fast(*reinterpret_cast<unsigned*>(&hif));
            unsigned t2 = tanh2_fast(*reinterpret_cast<unsigned*>(&hgo));
            float2 f1 = __half22float2(*reinterpret_cast<__half2*>(&t1));
            float2 f2 = __half22float2(*reinterpret_cast<__half2*>(&t2));
            float iv = 0.5f * f1.x + 0.5f;
            float fv = 0.5f * f1.y + 0.5f;
            float gv = f2.x;
            float ov = 0.5f * f2.y + 0.5f;
            float cn = fv * cst[nt] + iv * gv;
            float hn = ov * tanh_fast(cn);
            if (valid) { cst[nt] = cn; hst[nt] = hn; }

            unsigned hbits = (unsigned)__half_as_ushort(__float2half(hst[nt]));
            unsigned partb = __shfl_xor_sync(0xffffffff, hbits, 2);
            if (b1 == 0) {
                int j0 = (warp << 3) + 2 * nt;
                if (j0 < HH) {
                    __half2 hp = __halves2half2(__ushort_as_half((unsigned short)hbits),
                                                __ushort_as_half((unsigned short)partb));
                    *reinterpret_cast<__half2*>(&h16[pp ^ 1][rowSel][j0]) = hp;
                }
            }
            if (LAST_ONLY && trig) {
                int j = jbase + 2 * nt;
                if (j < HH) outFS[pp][rowSel][j] = hn;
            }
        }
        gaV = gaN; gbV = gbN;
        __syncthreads();

        // writer warps
        if (LAST_ONLY) {
            if (warp < 16) {
                bool wtrig = dir ? (s == 0) : (s == Lw - 1);
                if (wtrig) {
                    float* dst = lastOut + (size_t)bw * DD + hoff;
                    const float* srcf = &outFS[pp][warp][0];
#pragma unroll
                    for (int i = lane; i < 150; i += 32) dst[i] = srcf[i];
                }
            }
        } else {
            if (warp < 16 && s < Lw) {
                int t = dir ? (Lw - 1 - s) : s;
                const unsigned* srcu = reinterpret_cast<const unsigned*>(&h16[pp ^ 1][warp][0]);
                unsigned* dstu = reinterpret_cast<unsigned*>(wrBase + (size_t)t * KP);
#pragma unroll
                for (int i = lane; i < 75; i += 32) dstu[i] = srcu[i];
            }
        }
    }
}

__global__ void __launch_bounds__(608) k_lstm_l0() {
    lstm_mma_body<false>(g_gates, g_whhp0, g_a16, nullptr);
}
__global__ void __launch_bounds__(608) k_lstm_l1() {
    lstm_mma_body<true>(g_gates, g_whhp1, nullptr, g_last);
}

// ---------------- final FC layers -------------------------------------------------
__global__ void __launch_bounds__(320) k_fc1(const float* __restrict__ bias) {
    __shared__ float v[DD];
    int b = blockIdx.x, tid = threadIdx.x;
    const float* src = g_last + (size_t)b * DD;
    if (tid < DD) v[tid] = src[tid];
    __syncthreads();
    if (tid < DD) {
        float acc = bias[tid];
        for (int k = 0; k < DD; ++k) acc += v[k] * g_w1t[k * DD + tid];
        g_tmp[b * DD + tid] = tanhf(acc);
    }
}
__global__ void __launch_bounds__(320) k_fc2(const float* __restrict__ bias,
                                             float* __restrict__ out) {
    __shared__ float v[DD];
    int b = blockIdx.x, tid = threadIdx.x;
    if (tid < DD) v[tid] = g_tmp[b * DD + tid];
    __syncthreads();
    if (tid < DD) {
        float acc = bias[tid];
        for (int k = 0; k < DD; ++k) acc += v[k] * g_w2t[k * DD + tid];
        out[b * DD + tid] = acc;
    }
}

// ---------------- host --------------------------------------------------------------
extern "C" void kernel_launch(void* const* d_in, const int* in_sizes, int n_in,
                              void* d_out, int out_size) {
    const int*   x        = (const int*)  d_in[0];
    const int*   mask     = (const int*)  d_in[1];
    const float* emb      = (const float*)d_in[2];
    const float* Wih_l0f  = (const float*)d_in[3];
    const float* Whh_l0f  = (const float*)d_in[4];
    const float* b_l0f    = (const float*)d_in[5];
    const float* Wih_l0b  = (const float*)d_in[6];
    const float* Whh_l0b  = (const float*)d_in[7];
    const float* b_l0b    = (const float*)d_in[8];
    const float* Wih_l1f  = (const float*)d_in[9];
    const float* Whh_l1f  = (const float*)d_in[10];
    const float* b_l1f    = (const float*)d_in[11];
    const float* Wih_l1b  = (const float*)d_in[12];
    const float* Whh_l1b  = (const float*)d_in[13];
    const float* b_l1b    = (const float*)d_in[14];
    const float* W1       = (const float*)d_in[15];
    const float* b1       = (const float*)d_in[16];
    const float* W2       = (const float*)d_in[17];
    const float* b2       = (const float*)d_in[18];
    float* out = (float*)d_out;

    int mask64 = (in_sizes[1] != BB * SS) ? 1 : 0;

    dim3 sgrid(1520, 6);
    k_setup<<<sgrid, 256>>>(mask, mask64,
                            Wih_l0f, Wih_l0b, Wih_l1f, Wih_l1b,
                            Whh_l0f, Whh_l0b, Whh_l1f, Whh_l1b,
                            b_l0f, b_l0b, b_l1f, b_l1b, W1, W2);

    k_sort<<<1, 256>>>();

    k_embed16<<<(BB * SS * 152 + 255) / 256, 256>>>(x, emb);

    dim3 g16((BB * SS) / 128, N2P / 128);   // worst-case grid; blocks past Mc_pad exit

    k_gemm16_l0<<<g16, 256>>>();
    k_lstm_l0<<<128, 608>>>();

    k_gemm16_l1<<<g16, 256>>>();
    k_lstm_l1<<<128, 608>>>();

    k_fc1<<<BB, 320>>>(b1);
    k_fc2<<<BB, 320>>>(b2, out);
}